// round 1
// baseline (speedup 1.0000x reference)
#include <cuda_runtime.h>
#include <math.h>

// Problem dims
#define Bb 4
#define Tt 2048
#define Dd 1024
#define NHh 16
#define HDh 64
#define FFd 4096
#define MM (Bb*Tt)          // 8192 rows

// -------- scratch (device globals; no allocs allowed) --------
__device__ float g_xln[(size_t)MM*Dd];
__device__ float g_q  [(size_t)MM*Dd];
__device__ float g_k  [(size_t)MM*Dd];
__device__ float g_v  [(size_t)MM*Dd];
__device__ float g_scores[(size_t)Bb*NHh*Tt*Tt];   // 1 GiB
__device__ float g_ctx[(size_t)MM*Dd];
__device__ float g_xres[(size_t)MM*Dd];
__device__ float g_yln[(size_t)MM*Dd];
__device__ float g_h1 [(size_t)MM*FFd];

// -------- block reductions (256 threads) --------
__device__ __forceinline__ float block_reduce_sum(float v, float* sh) {
    int t = threadIdx.x;
    #pragma unroll
    for (int o = 16; o > 0; o >>= 1) v += __shfl_down_sync(0xffffffffu, v, o);
    if ((t & 31) == 0) sh[t >> 5] = v;
    __syncthreads();
    if (t < 32) {
        float w = (t < 8) ? sh[t] : 0.0f;
        #pragma unroll
        for (int o = 4; o > 0; o >>= 1) w += __shfl_down_sync(0xffffffffu, w, o);
        if (t == 0) sh[0] = w;
    }
    __syncthreads();
    float r = sh[0];
    __syncthreads();
    return r;
}

__device__ __forceinline__ float block_reduce_max(float v, float* sh) {
    int t = threadIdx.x;
    #pragma unroll
    for (int o = 16; o > 0; o >>= 1) v = fmaxf(v, __shfl_down_sync(0xffffffffu, v, o));
    if ((t & 31) == 0) sh[t >> 5] = v;
    __syncthreads();
    if (t < 32) {
        float w = (t < 8) ? sh[t] : -3.0e38f;
        #pragma unroll
        for (int o = 4; o > 0; o >>= 1) w = fmaxf(w, __shfl_down_sync(0xffffffffu, w, o));
        if (t == 0) sh[0] = w;
    }
    __syncthreads();
    float r = sh[0];
    __syncthreads();
    return r;
}

// -------- LayerNorm: one block (256 thr) per row of 1024 --------
__global__ void ln_kernel(const float* __restrict__ x, const float* __restrict__ gamma,
                          const float* __restrict__ beta, float* __restrict__ out)
{
    __shared__ float sh[32];
    size_t row = blockIdx.x;
    const float4* xr = (const float4*)(x + row * Dd);
    float4*       orow = (float4*)(out + row * Dd);
    int t = threadIdx.x;             // 256 threads * 4 = 1024
    float4 xv = xr[t];
    float s  = xv.x + xv.y + xv.z + xv.w;
    float s2 = xv.x*xv.x + xv.y*xv.y + xv.z*xv.z + xv.w*xv.w;
    float S  = block_reduce_sum(s,  sh);
    float S2 = block_reduce_sum(s2, sh);
    float mean = S * (1.0f / Dd);
    float var  = S2 * (1.0f / Dd) - mean * mean;
    float rs   = rsqrtf(var + 1e-6f);
    float4 gv = ((const float4*)gamma)[t];
    float4 bv = ((const float4*)beta)[t];
    float4 ov;
    ov.x = (xv.x - mean) * rs * gv.x + bv.x;
    ov.y = (xv.y - mean) * rs * gv.y + bv.y;
    ov.z = (xv.z - mean) * rs * gv.z + bv.z;
    ov.w = (xv.w - mean) * rs * gv.w + bv.w;
    orow[t] = ov;
}

// -------- softcap + softmax: one block (256 thr) per row of 2048 --------
__global__ void softcap_softmax(float* __restrict__ sc)
{
    __shared__ float sh[32];
    __shared__ float buf[Tt];        // 8 KB row cache
    size_t row = blockIdx.x;
    float4* r = (float4*)(sc + row * (size_t)Tt);
    int t = threadIdx.x;
    float lmax = -3.0e38f;
    #pragma unroll
    for (int j = 0; j < 2; j++) {
        float4 v = r[t + j*256];
        v.x = 50.0f * tanhf(v.x * 0.02f);
        v.y = 50.0f * tanhf(v.y * 0.02f);
        v.z = 50.0f * tanhf(v.z * 0.02f);
        v.w = 50.0f * tanhf(v.w * 0.02f);
        ((float4*)buf)[t + j*256] = v;
        lmax = fmaxf(lmax, fmaxf(fmaxf(v.x, v.y), fmaxf(v.z, v.w)));
    }
    __syncthreads();
    float m = block_reduce_max(lmax, sh);
    float ls = 0.0f;
    #pragma unroll
    for (int j = 0; j < 2; j++) {
        float4 v = ((float4*)buf)[t + j*256];
        v.x = expf(v.x - m); v.y = expf(v.y - m);
        v.z = expf(v.z - m); v.w = expf(v.w - m);
        ((float4*)buf)[t + j*256] = v;
        ls += v.x + v.y + v.z + v.w;
    }
    __syncthreads();
    float S = block_reduce_sum(ls, sh);
    float inv = 1.0f / S;
    #pragma unroll
    for (int j = 0; j < 2; j++) {
        float4 v = ((float4*)buf)[t + j*256];
        v.x *= inv; v.y *= inv; v.z *= inv; v.w *= inv;
        r[t + j*256] = v;
    }
}

// -------- generic NN GEMM: C = act(alpha*(A@B + bias)) (+res) --------
// A [M,K] row-major contiguous, B [K,N] row-major contiguous. M%128==0, N%128==0, K%16==0.
template<int ACT, bool HAS_BIAS, bool HAS_RES>
__global__ __launch_bounds__(256) void gemm_nn(
    const float* __restrict__ A, const float* __restrict__ Bm,
    const float* __restrict__ bias, const float* __restrict__ res,
    float* __restrict__ C, int M, int N, int K, float alpha)
{
    __shared__ float sA[16][128];
    __shared__ float sB[16][128];
    int tid = threadIdx.x;
    int tx = tid & 15, ty = tid >> 4;
    int row0 = blockIdx.y * 128;
    int col0 = blockIdx.x * 128;
    const float* Ab = A + (size_t)row0 * K;
    const float* Bp = Bm + col0;
    float acc[8][8] = {};
    for (int k0 = 0; k0 < K; k0 += 16) {
        #pragma unroll
        for (int i = 0; i < 2; i++) {
            int idx = tid + i*256;
            int rr = idx >> 2, c4 = idx & 3;
            float4 a = *(const float4*)(Ab + (size_t)rr * K + k0 + c4*4);
            sA[c4*4+0][rr] = a.x; sA[c4*4+1][rr] = a.y;
            sA[c4*4+2][rr] = a.z; sA[c4*4+3][rr] = a.w;
        }
        #pragma unroll
        for (int i = 0; i < 2; i++) {
            int idx = tid + i*256;
            int rr = idx >> 5, c4 = idx & 31;
            float4 b = *(const float4*)(Bp + (size_t)(k0 + rr) * N + c4*4);
            *(float4*)&sB[rr][c4*4] = b;
        }
        __syncthreads();
        #pragma unroll
        for (int kk = 0; kk < 16; kk++) {
            float ra[8], rb[8];
            *(float4*)&ra[0] = *(float4*)&sA[kk][ty*8];
            *(float4*)&ra[4] = *(float4*)&sA[kk][ty*8+4];
            *(float4*)&rb[0] = *(float4*)&sB[kk][tx*8];
            *(float4*)&rb[4] = *(float4*)&sB[kk][tx*8+4];
            #pragma unroll
            for (int i = 0; i < 8; i++)
                #pragma unroll
                for (int j = 0; j < 8; j++)
                    acc[i][j] += ra[i] * rb[j];
        }
        __syncthreads();
    }
    #pragma unroll
    for (int i = 0; i < 8; i++) {
        size_t row = (size_t)(row0 + ty*8 + i);
        float* crow = C + row * N + col0 + tx*8;
        const float* rrow = res + row * N + col0 + tx*8;  // only read if HAS_RES
        float vv[8];
        #pragma unroll
        for (int j = 0; j < 8; j++) {
            float v = acc[i][j];
            if (HAS_BIAS) v += bias[col0 + tx*8 + j];
            v *= alpha;
            if (ACT == 1) v = 0.5f * v * (1.0f + erff(v * 0.70710678118654752f));
            vv[j] = v;
        }
        if (HAS_RES) {
            float4 r0 = *(const float4*)rrow;
            float4 r1 = *(const float4*)(rrow + 4);
            vv[0]+=r0.x; vv[1]+=r0.y; vv[2]+=r0.z; vv[3]+=r0.w;
            vv[4]+=r1.x; vv[5]+=r1.y; vv[6]+=r1.z; vv[7]+=r1.w;
        }
        *(float4*)crow       = make_float4(vv[0], vv[1], vv[2], vv[3]);
        *(float4*)(crow + 4) = make_float4(vv[4], vv[5], vv[6], vv[7]);
    }
}

// -------- batched NT GEMM: scores[z][t][s] = sum_h q[b,t,n,h]*k[b,s,n,h] --------
__global__ __launch_bounds__(256) void gemm_scores(
    const float* __restrict__ q, const float* __restrict__ k, float* __restrict__ sc)
{
    int z = blockIdx.z;
    int b = z / NHh, n = z % NHh;
    const float* A  = q + (size_t)b * Tt * Dd + n * HDh;   // lda = Dd
    const float* Bk = k + (size_t)b * Tt * Dd + n * HDh;   // ldb = Dd (transposed use)
    float* C = sc + (size_t)z * Tt * Tt;
    __shared__ float sA[16][128];
    __shared__ float sB[16][128];
    int tid = threadIdx.x, tx = tid & 15, ty = tid >> 4;
    int row0 = blockIdx.y * 128, col0 = blockIdx.x * 128;
    float acc[8][8] = {};
    for (int k0 = 0; k0 < HDh; k0 += 16) {
        #pragma unroll
        for (int i = 0; i < 2; i++) {
            int idx = tid + i*256;
            int rr = idx >> 2, c4 = idx & 3;
            float4 a = *(const float4*)(A + (size_t)(row0 + rr) * Dd + k0 + c4*4);
            sA[c4*4+0][rr] = a.x; sA[c4*4+1][rr] = a.y;
            sA[c4*4+2][rr] = a.z; sA[c4*4+3][rr] = a.w;
            float4 bb = *(const float4*)(Bk + (size_t)(col0 + rr) * Dd + k0 + c4*4);
            sB[c4*4+0][rr] = bb.x; sB[c4*4+1][rr] = bb.y;
            sB[c4*4+2][rr] = bb.z; sB[c4*4+3][rr] = bb.w;
        }
        __syncthreads();
        #pragma unroll
        for (int kk = 0; kk < 16; kk++) {
            float ra[8], rb[8];
            *(float4*)&ra[0] = *(float4*)&sA[kk][ty*8];
            *(float4*)&ra[4] = *(float4*)&sA[kk][ty*8+4];
            *(float4*)&rb[0] = *(float4*)&sB[kk][tx*8];
            *(float4*)&rb[4] = *(float4*)&sB[kk][tx*8+4];
            #pragma unroll
            for (int i = 0; i < 8; i++)
                #pragma unroll
                for (int j = 0; j < 8; j++)
                    acc[i][j] += ra[i] * rb[j];
        }
        __syncthreads();
    }
    #pragma unroll
    for (int i = 0; i < 8; i++) {
        float* crow = C + (size_t)(row0 + ty*8 + i) * Tt + col0 + tx*8;
        *(float4*)crow       = make_float4(acc[i][0], acc[i][1], acc[i][2], acc[i][3]);
        *(float4*)(crow + 4) = make_float4(acc[i][4], acc[i][5], acc[i][6], acc[i][7]);
    }
}

// -------- batched NN GEMM: ctx[b,t,n,h] = sum_s W[z][t][s]*v[b,s,n,h] --------
__global__ __launch_bounds__(256) void gemm_ctx(
    const float* __restrict__ w, const float* __restrict__ v, float* __restrict__ ctx)
{
    int z = blockIdx.z;
    int b = z / NHh, n = z % NHh;
    const float* A  = w + (size_t)z * Tt * Tt;               // lda = Tt
    const float* Bv = v + (size_t)b * Tt * Dd + n * HDh;     // ldb = Dd
    float* C = ctx + (size_t)b * Tt * Dd + n * HDh;          // ldc = Dd
    __shared__ float sA[16][128];
    __shared__ float sB[16][64];
    int tid = threadIdx.x, tx = tid & 15, ty = tid >> 4;
    int row0 = blockIdx.y * 128;
    float acc[8][4] = {};
    for (int k0 = 0; k0 < Tt; k0 += 16) {
        #pragma unroll
        for (int i = 0; i < 2; i++) {
            int idx = tid + i*256;
            int rr = idx >> 2, c4 = idx & 3;
            float4 a = *(const float4*)(A + (size_t)(row0 + rr) * Tt + k0 + c4*4);
            sA[c4*4+0][rr] = a.x; sA[c4*4+1][rr] = a.y;
            sA[c4*4+2][rr] = a.z; sA[c4*4+3][rr] = a.w;
        }
        {
            int rr = tid >> 4, c4 = tid & 15;
            float4 bb = *(const float4*)(Bv + (size_t)(k0 + rr) * Dd + c4*4);
            *(float4*)&sB[rr][c4*4] = bb;
        }
        __syncthreads();
        #pragma unroll
        for (int kk = 0; kk < 16; kk++) {
            float ra[8], rb[4];
            *(float4*)&ra[0] = *(float4*)&sA[kk][ty*8];
            *(float4*)&ra[4] = *(float4*)&sA[kk][ty*8+4];
            *(float4*)&rb[0] = *(float4*)&sB[kk][tx*4];
            #pragma unroll
            for (int i = 0; i < 8; i++)
                #pragma unroll
                for (int j = 0; j < 4; j++)
                    acc[i][j] += ra[i] * rb[j];
        }
        __syncthreads();
    }
    #pragma unroll
    for (int i = 0; i < 8; i++) {
        float* crow = C + (size_t)(row0 + ty*8 + i) * Dd + tx*4;
        *(float4*)crow = make_float4(acc[i][0], acc[i][1], acc[i][2], acc[i][3]);
    }
}

// -------- launch --------
extern "C" void kernel_launch(void* const* d_in, const int* in_sizes, int n_in,
                              void* d_out, int out_size)
{
    const float* inputs = (const float*)d_in[0];
    const float* ln1_g  = (const float*)d_in[1];
    const float* ln1_b  = (const float*)d_in[2];
    const float* wq     = (const float*)d_in[3];
    const float* bq     = (const float*)d_in[4];
    const float* wk     = (const float*)d_in[5];
    const float* bk     = (const float*)d_in[6];
    const float* wv     = (const float*)d_in[7];
    const float* bv     = (const float*)d_in[8];
    const float* wo     = (const float*)d_in[9];
    const float* bo     = (const float*)d_in[10];
    const float* ln2_g  = (const float*)d_in[11];
    const float* ln2_b  = (const float*)d_in[12];
    const float* w1     = (const float*)d_in[13];
    const float* b1     = (const float*)d_in[14];
    const float* w2     = (const float*)d_in[15];
    const float* b2     = (const float*)d_in[16];
    float* out = (float*)d_out;

    float *xln, *q, *k, *v, *sc, *ctx, *xres, *yln, *h1;
    cudaGetSymbolAddress((void**)&xln,  g_xln);
    cudaGetSymbolAddress((void**)&q,    g_q);
    cudaGetSymbolAddress((void**)&k,    g_k);
    cudaGetSymbolAddress((void**)&v,    g_v);
    cudaGetSymbolAddress((void**)&sc,   g_scores);
    cudaGetSymbolAddress((void**)&ctx,  g_ctx);
    cudaGetSymbolAddress((void**)&xres, g_xres);
    cudaGetSymbolAddress((void**)&yln,  g_yln);
    cudaGetSymbolAddress((void**)&h1,   g_h1);

    // 1) LN1
    ln_kernel<<<MM, 256>>>(inputs, ln1_g, ln1_b, xln);

    // 2) QKV projections (q scaled by 1/sqrt(H)=0.125)
    dim3 gD(Dd/128, MM/128);
    gemm_nn<0, true, false><<<gD, 256>>>(xln, wq, bq, nullptr, q, MM, Dd, Dd, 0.125f);
    gemm_nn<0, true, false><<<gD, 256>>>(xln, wk, bk, nullptr, k, MM, Dd, Dd, 1.0f);
    gemm_nn<0, true, false><<<gD, 256>>>(xln, wv, bv, nullptr, v, MM, Dd, Dd, 1.0f);

    // 3) scores = Q K^T per (b,n)
    dim3 gS(Tt/128, Tt/128, Bb*NHh);
    gemm_scores<<<gS, 256>>>(q, k, sc);

    // 4) softcap + softmax over rows
    softcap_softmax<<<Bb*NHh*Tt, 256>>>(sc);

    // 5) context = W V per (b,n)
    dim3 gC(1, Tt/128, Bb*NHh);
    gemm_ctx<<<gC, 256>>>(sc, v, ctx);

    // 6) out-proj + residual with inputs -> x_res
    gemm_nn<0, true, true><<<gD, 256>>>(ctx, wo, bo, inputs, xres, MM, Dd, Dd, 1.0f);

    // 7) LN2
    ln_kernel<<<MM, 256>>>(xres, ln2_g, ln2_b, yln);

    // 8) MLP up + exact GELU
    dim3 gF(FFd/128, MM/128);
    gemm_nn<1, true, false><<<gF, 256>>>(yln, w1, b1, nullptr, h1, MM, FFd, Dd, 1.0f);

    // 9) MLP down + bias + residual with x_res -> out
    gemm_nn<0, true, true><<<gD, 256>>>(h1, w2, b2, xres, out, MM, Dd, FFd, 1.0f);
}

// round 3
// speedup vs baseline: 2.4095x; 2.4095x over previous
#include <cuda_runtime.h>
#include <math.h>
#include <stdint.h>

// Problem dims
#define Bb 4
#define Tt 2048
#define Dd 1024
#define NHh 16
#define HDh 64
#define FFd 4096
#define MM (Bb*Tt)          // 8192 rows

// -------- scratch (device globals; no allocs allowed) --------
__device__ float g_xln[(size_t)MM*Dd];
__device__ float g_q  [(size_t)MM*Dd];
__device__ float g_k  [(size_t)MM*Dd];
__device__ float g_v  [(size_t)MM*Dd];
__device__ float g_scores[(size_t)Bb*NHh*Tt*Tt];   // 1 GiB
__device__ float g_ctx[(size_t)MM*Dd];
__device__ float g_xres[(size_t)MM*Dd];
__device__ float g_yln[(size_t)MM*Dd];
__device__ float g_h1 [(size_t)MM*FFd];

// -------- helpers --------
__device__ __forceinline__ uint32_t f2tf(float f) {
    uint32_t u;
    asm("cvt.rna.tf32.f32 %0, %1;" : "=r"(u) : "f"(f));
    return u;
}

#define MMA_TF32(c, a, b) \
    asm volatile("mma.sync.aligned.m16n8k8.row.col.f32.tf32.tf32.f32 " \
                 "{%0,%1,%2,%3},{%4,%5,%6,%7},{%8,%9},{%0,%1,%2,%3};" \
                 : "+f"((c)[0]), "+f"((c)[1]), "+f"((c)[2]), "+f"((c)[3]) \
                 : "r"((a)[0]), "r"((a)[1]), "r"((a)[2]), "r"((a)[3]), \
                   "r"((b)[0]), "r"((b)[1]))

__device__ __forceinline__ float block_reduce_sum(float v, float* sh) {
    int t = threadIdx.x;
    #pragma unroll
    for (int o = 16; o > 0; o >>= 1) v += __shfl_down_sync(0xffffffffu, v, o);
    if ((t & 31) == 0) sh[t >> 5] = v;
    __syncthreads();
    if (t < 32) {
        float w = (t < 8) ? sh[t] : 0.0f;
        #pragma unroll
        for (int o = 4; o > 0; o >>= 1) w += __shfl_down_sync(0xffffffffu, w, o);
        if (t == 0) sh[0] = w;
    }
    __syncthreads();
    float r = sh[0];
    __syncthreads();
    return r;
}

__device__ __forceinline__ float block_reduce_max(float v, float* sh) {
    int t = threadIdx.x;
    #pragma unroll
    for (int o = 16; o > 0; o >>= 1) v = fmaxf(v, __shfl_down_sync(0xffffffffu, v, o));
    if ((t & 31) == 0) sh[t >> 5] = v;
    __syncthreads();
    if (t < 32) {
        float w = (t < 8) ? sh[t] : -3.0e38f;
        #pragma unroll
        for (int o = 4; o > 0; o >>= 1) w = fmaxf(w, __shfl_down_sync(0xffffffffu, w, o));
        if (t == 0) sh[0] = w;
    }
    __syncthreads();
    float r = sh[0];
    __syncthreads();
    return r;
}

// -------- LayerNorm: one block (256 thr) per row of 1024 --------
__global__ void ln_kernel(const float* __restrict__ x, const float* __restrict__ gamma,
                          const float* __restrict__ beta, float* __restrict__ out)
{
    __shared__ float sh[32];
    size_t row = blockIdx.x;
    const float4* xr = (const float4*)(x + row * Dd);
    float4*       orow = (float4*)(out + row * Dd);
    int t = threadIdx.x;
    float4 xv = xr[t];
    float s  = xv.x + xv.y + xv.z + xv.w;
    float s2 = xv.x*xv.x + xv.y*xv.y + xv.z*xv.z + xv.w*xv.w;
    float S  = block_reduce_sum(s,  sh);
    float S2 = block_reduce_sum(s2, sh);
    float mean = S * (1.0f / Dd);
    float var  = S2 * (1.0f / Dd) - mean * mean;
    float rs   = rsqrtf(var + 1e-6f);
    float4 gv = ((const float4*)gamma)[t];
    float4 bv = ((const float4*)beta)[t];
    float4 ov;
    ov.x = (xv.x - mean) * rs * gv.x + bv.x;
    ov.y = (xv.y - mean) * rs * gv.y + bv.y;
    ov.z = (xv.z - mean) * rs * gv.z + bv.z;
    ov.w = (xv.w - mean) * rs * gv.w + bv.w;
    orow[t] = ov;
}

// -------- softcap + softmax: one block (256 thr) per row of 2048 --------
__global__ void softcap_softmax(float* __restrict__ sc)
{
    __shared__ float sh[32];
    __shared__ float buf[Tt];
    size_t row = blockIdx.x;
    float4* r = (float4*)(sc + row * (size_t)Tt);
    int t = threadIdx.x;
    float lmax = -3.0e38f;
    #pragma unroll
    for (int j = 0; j < 2; j++) {
        float4 v = r[t + j*256];
        v.x = 50.0f * tanhf(v.x * 0.02f);
        v.y = 50.0f * tanhf(v.y * 0.02f);
        v.z = 50.0f * tanhf(v.z * 0.02f);
        v.w = 50.0f * tanhf(v.w * 0.02f);
        ((float4*)buf)[t + j*256] = v;
        lmax = fmaxf(lmax, fmaxf(fmaxf(v.x, v.y), fmaxf(v.z, v.w)));
    }
    __syncthreads();
    float m = block_reduce_max(lmax, sh);
    float ls = 0.0f;
    #pragma unroll
    for (int j = 0; j < 2; j++) {
        float4 v = ((float4*)buf)[t + j*256];
        v.x = expf(v.x - m); v.y = expf(v.y - m);
        v.z = expf(v.z - m); v.w = expf(v.w - m);
        ((float4*)buf)[t + j*256] = v;
        ls += v.x + v.y + v.z + v.w;
    }
    __syncthreads();
    float S = block_reduce_sum(ls, sh);
    float inv = 1.0f / S;
    #pragma unroll
    for (int j = 0; j < 2; j++) {
        float4 v = ((float4*)buf)[t + j*256];
        v.x *= inv; v.y *= inv; v.z *= inv; v.w *= inv;
        r[t + j*256] = v;
    }
}

// ============================================================================
// TF32 tensor-core GEMM: C = act(alpha*(A@B + bias)) (+res)
// A [M,K] row-major, B [K,N] row-major. BM=128 BN=128 BK=32, 256 threads.
// Warp tile 64x32: warps 2(m) x 4(n); per warp 4 m-tiles (m16) x 4 n-tiles (n8).
// smem: sA[m][k] stride 36 (frag bank = (4m+k)%32, conflict-free)
//       sB[k][n] stride 136 (frag bank = (8k+n)%32, conflict-free)
// ============================================================================
template<int ACT, bool HAS_BIAS, bool HAS_RES>
__global__ __launch_bounds__(256) void gemm_nn_mma(
    const float* __restrict__ A, const float* __restrict__ Bm,
    const float* __restrict__ bias, const float* __restrict__ res,
    float* __restrict__ C, int M, int N, int K, float alpha)
{
    __shared__ uint32_t sA[128][36];
    __shared__ uint32_t sB[32][136];
    int tid = threadIdx.x;
    int lane = tid & 31, wid = tid >> 5;
    int g = lane >> 2, tig = lane & 3;
    int wm0 = (wid >> 2) * 64;
    int wn0 = (wid & 3) * 32;
    int row0 = blockIdx.y * 128;
    int col0 = blockIdx.x * 128;

    float acc[4][4][4] = {};

    for (int k0 = 0; k0 < K; k0 += 32) {
        // load A tile 128x32 (coalesced: 8 lanes cover one row's 32 k)
        #pragma unroll
        for (int i = 0; i < 4; i++) {
            int f = tid + i*256;
            int rr = f >> 3, kq = f & 7;
            float4 a = *(const float4*)(A + (size_t)(row0 + rr) * K + k0 + kq*4);
            uint4 u; u.x = f2tf(a.x); u.y = f2tf(a.y); u.z = f2tf(a.z); u.w = f2tf(a.w);
            *(uint4*)&sA[rr][kq*4] = u;
        }
        // load B tile 32x128
        #pragma unroll
        for (int i = 0; i < 4; i++) {
            int f = tid + i*256;
            int kr = f >> 5, nq = f & 31;
            float4 b = *(const float4*)(Bm + (size_t)(k0 + kr) * N + col0 + nq*4);
            uint4 u; u.x = f2tf(b.x); u.y = f2tf(b.y); u.z = f2tf(b.z); u.w = f2tf(b.w);
            *(uint4*)&sB[kr][nq*4] = u;
        }
        __syncthreads();
        #pragma unroll
        for (int kk = 0; kk < 32; kk += 8) {
            uint32_t af[4][4], bf[4][2];
            #pragma unroll
            for (int i = 0; i < 4; i++) {
                int m = wm0 + i*16 + g;
                af[i][0] = sA[m    ][kk + tig];
                af[i][1] = sA[m + 8][kk + tig];
                af[i][2] = sA[m    ][kk + tig + 4];
                af[i][3] = sA[m + 8][kk + tig + 4];
            }
            #pragma unroll
            for (int j = 0; j < 4; j++) {
                int n = wn0 + j*8 + g;
                bf[j][0] = sB[kk + tig    ][n];
                bf[j][1] = sB[kk + tig + 4][n];
            }
            #pragma unroll
            for (int i = 0; i < 4; i++)
                #pragma unroll
                for (int j = 0; j < 4; j++)
                    MMA_TF32(acc[i][j], af[i], bf[j]);
        }
        __syncthreads();
    }

    // epilogue
    #pragma unroll
    for (int i = 0; i < 4; i++) {
        #pragma unroll
        for (int j = 0; j < 4; j++) {
            int col = col0 + wn0 + j*8 + tig*2;
            #pragma unroll
            for (int h = 0; h < 2; h++) {   // h=0: rows g, h=1: rows g+8
                int row = row0 + wm0 + i*16 + g + h*8;
                float v0 = acc[i][j][h*2 + 0];
                float v1 = acc[i][j][h*2 + 1];
                if (HAS_BIAS) { v0 += bias[col]; v1 += bias[col + 1]; }
                v0 *= alpha; v1 *= alpha;
                if (ACT == 1) {
                    v0 = 0.5f * v0 * (1.0f + erff(v0 * 0.70710678118654752f));
                    v1 = 0.5f * v1 * (1.0f + erff(v1 * 0.70710678118654752f));
                }
                if (HAS_RES) {
                    float2 rr = *(const float2*)(res + (size_t)row * N + col);
                    v0 += rr.x; v1 += rr.y;
                }
                *(float2*)(C + (size_t)row * N + col) = make_float2(v0, v1);
            }
        }
    }
}

// ============================================================================
// scores[z][t][s] = sum_h q[b,t,n,h]*k[b,s,n,h]  (NT, K=64, TF32 mma)
// Both operands stored row-major [rows][36] in smem.
// ============================================================================
__global__ __launch_bounds__(256) void gemm_scores_mma(
    const float* __restrict__ q, const float* __restrict__ k, float* __restrict__ sc)
{
    __shared__ uint32_t sA[128][36];
    __shared__ uint32_t sBn[128][36];
    int z = blockIdx.z;
    int b = z / NHh, n = z % NHh;
    const float* Aq = q + (size_t)b * Tt * Dd + n * HDh;
    const float* Bk = k + (size_t)b * Tt * Dd + n * HDh;
    float* C = sc + (size_t)z * Tt * Tt;

    int tid = threadIdx.x;
    int lane = tid & 31, wid = tid >> 5;
    int g = lane >> 2, tig = lane & 3;
    int wm0 = (wid >> 2) * 64;
    int wn0 = (wid & 3) * 32;
    int row0 = blockIdx.y * 128;
    int col0 = blockIdx.x * 128;

    float acc[4][4][4] = {};

    for (int k0 = 0; k0 < HDh; k0 += 32) {
        #pragma unroll
        for (int i = 0; i < 4; i++) {
            int f = tid + i*256;
            int rr = f >> 3, kq = f & 7;
            float4 a = *(const float4*)(Aq + (size_t)(row0 + rr) * Dd + k0 + kq*4);
            uint4 u; u.x = f2tf(a.x); u.y = f2tf(a.y); u.z = f2tf(a.z); u.w = f2tf(a.w);
            *(uint4*)&sA[rr][kq*4] = u;
            float4 bb = *(const float4*)(Bk + (size_t)(col0 + rr) * Dd + k0 + kq*4);
            uint4 ub; ub.x = f2tf(bb.x); ub.y = f2tf(bb.y); ub.z = f2tf(bb.z); ub.w = f2tf(bb.w);
            *(uint4*)&sBn[rr][kq*4] = ub;
        }
        __syncthreads();
        #pragma unroll
        for (int kk = 0; kk < 32; kk += 8) {
            uint32_t af[4][4], bf[4][2];
            #pragma unroll
            for (int i = 0; i < 4; i++) {
                int m = wm0 + i*16 + g;
                af[i][0] = sA[m    ][kk + tig];
                af[i][1] = sA[m + 8][kk + tig];
                af[i][2] = sA[m    ][kk + tig + 4];
                af[i][3] = sA[m + 8][kk + tig + 4];
            }
            #pragma unroll
            for (int j = 0; j < 4; j++) {
                int nn = wn0 + j*8 + g;
                bf[j][0] = sBn[nn][kk + tig];
                bf[j][1] = sBn[nn][kk + tig + 4];
            }
            #pragma unroll
            for (int i = 0; i < 4; i++)
                #pragma unroll
                for (int j = 0; j < 4; j++)
                    MMA_TF32(acc[i][j], af[i], bf[j]);
        }
        __syncthreads();
    }

    #pragma unroll
    for (int i = 0; i < 4; i++)
        #pragma unroll
        for (int j = 0; j < 4; j++) {
            int col = col0 + wn0 + j*8 + tig*2;
            #pragma unroll
            for (int h = 0; h < 2; h++) {
                int row = row0 + wm0 + i*16 + g + h*8;
                *(float2*)(C + (size_t)row * Tt + col) =
                    make_float2(acc[i][j][h*2], acc[i][j][h*2 + 1]);
            }
        }
}

// ============================================================================
// ctx[b,t,n,h] = sum_s W[z][t][s]*v[b,s,n,h]  (NN, N=64, TF32 mma)
// BM=128 BN=64 BK=32, 256 threads, warp tile 32x32 (warps 4m x 2n).
// ============================================================================
__global__ __launch_bounds__(256) void gemm_ctx_mma(
    const float* __restrict__ w, const float* __restrict__ v, float* __restrict__ ctx)
{
    __shared__ uint32_t sA[128][36];
    __shared__ uint32_t sB[32][72];
    int z = blockIdx.z;
    int b = z / NHh, n = z % NHh;
    const float* Aw = w + (size_t)z * Tt * Tt;
    const float* Bv = v + (size_t)b * Tt * Dd + n * HDh;
    float* C = ctx + (size_t)b * Tt * Dd + n * HDh;

    int tid = threadIdx.x;
    int lane = tid & 31, wid = tid >> 5;
    int g = lane >> 2, tig = lane & 3;
    int wm0 = (wid >> 1) * 32;
    int wn0 = (wid & 1) * 32;
    int row0 = blockIdx.y * 128;

    float acc[2][4][4] = {};

    for (int k0 = 0; k0 < Tt; k0 += 32) {
        #pragma unroll
        for (int i = 0; i < 4; i++) {
            int f = tid + i*256;
            int rr = f >> 3, kq = f & 7;
            float4 a = *(const float4*)(Aw + (size_t)(row0 + rr) * Tt + k0 + kq*4);
            uint4 u; u.x = f2tf(a.x); u.y = f2tf(a.y); u.z = f2tf(a.z); u.w = f2tf(a.w);
            *(uint4*)&sA[rr][kq*4] = u;
        }
        #pragma unroll
        for (int i = 0; i < 2; i++) {
            int f = tid + i*256;
            int kr = f >> 4, nq = f & 15;
            float4 bb = *(const float4*)(Bv + (size_t)(k0 + kr) * Dd + nq*4);
            uint4 u; u.x = f2tf(bb.x); u.y = f2tf(bb.y); u.z = f2tf(bb.z); u.w = f2tf(bb.w);
            *(uint4*)&sB[kr][nq*4] = u;
        }
        __syncthreads();
        #pragma unroll
        for (int kk = 0; kk < 32; kk += 8) {
            uint32_t af[2][4], bf[4][2];
            #pragma unroll
            for (int i = 0; i < 2; i++) {
                int m = wm0 + i*16 + g;
                af[i][0] = sA[m    ][kk + tig];
                af[i][1] = sA[m + 8][kk + tig];
                af[i][2] = sA[m    ][kk + tig + 4];
                af[i][3] = sA[m + 8][kk + tig + 4];
            }
            #pragma unroll
            for (int j = 0; j < 4; j++) {
                int nn = wn0 + j*8 + g;
                bf[j][0] = sB[kk + tig    ][nn];
                bf[j][1] = sB[kk + tig + 4][nn];
            }
            #pragma unroll
            for (int i = 0; i < 2; i++)
                #pragma unroll
                for (int j = 0; j < 4; j++)
                    MMA_TF32(acc[i][j], af[i], bf[j]);
        }
        __syncthreads();
    }

    #pragma unroll
    for (int i = 0; i < 2; i++)
        #pragma unroll
        for (int j = 0; j < 4; j++) {
            int col = wn0 + j*8 + tig*2;
            #pragma unroll
            for (int h = 0; h < 2; h++) {
                int row = row0 + wm0 + i*16 + g + h*8;
                *(float2*)(C + (size_t)row * Dd + col) =
                    make_float2(acc[i][j][h*2], acc[i][j][h*2 + 1]);
            }
        }
}

// -------- launch --------
extern "C" void kernel_launch(void* const* d_in, const int* in_sizes, int n_in,
                              void* d_out, int out_size)
{
    const float* inputs = (const float*)d_in[0];
    const float* ln1_g  = (const float*)d_in[1];
    const float* ln1_b  = (const float*)d_in[2];
    const float* wq     = (const float*)d_in[3];
    const float* bq     = (const float*)d_in[4];
    const float* wk     = (const float*)d_in[5];
    const float* bk     = (const float*)d_in[6];
    const float* wv     = (const float*)d_in[7];
    const float* bv     = (const float*)d_in[8];
    const float* wo     = (const float*)d_in[9];
    const float* bo     = (const float*)d_in[10];
    const float* ln2_g  = (const float*)d_in[11];
    const float* ln2_b  = (const float*)d_in[12];
    const float* w1     = (const float*)d_in[13];
    const float* b1     = (const float*)d_in[14];
    const float* w2     = (const float*)d_in[15];
    const float* b2     = (const float*)d_in[16];
    float* out = (float*)d_out;

    float *xln, *q, *k, *v, *sc, *ctx, *xres, *yln, *h1;
    cudaGetSymbolAddress((void**)&xln,  g_xln);
    cudaGetSymbolAddress((void**)&q,    g_q);
    cudaGetSymbolAddress((void**)&k,    g_k);
    cudaGetSymbolAddress((void**)&v,    g_v);
    cudaGetSymbolAddress((void**)&sc,   g_scores);
    cudaGetSymbolAddress((void**)&ctx,  g_ctx);
    cudaGetSymbolAddress((void**)&xres, g_xres);
    cudaGetSymbolAddress((void**)&yln,  g_yln);
    cudaGetSymbolAddress((void**)&h1,   g_h1);

    // 1) LN1
    ln_kernel<<<MM, 256>>>(inputs, ln1_g, ln1_b, xln);

    // 2) QKV projections (q scaled by 1/sqrt(H)=0.125)
    dim3 gD(Dd/128, MM/128);
    gemm_nn_mma<0, true, false><<<gD, 256>>>(xln, wq, bq, nullptr, q, MM, Dd, Dd, 0.125f);
    gemm_nn_mma<0, true, false><<<gD, 256>>>(xln, wk, bk, nullptr, k, MM, Dd, Dd, 1.0f);
    gemm_nn_mma<0, true, false><<<gD, 256>>>(xln, wv, bv, nullptr, v, MM, Dd, Dd, 1.0f);

    // 3) scores = Q K^T per (b,n)
    dim3 gS(Tt/128, Tt/128, Bb*NHh);
    gemm_scores_mma<<<gS, 256>>>(q, k, sc);

    // 4) softcap + softmax over rows
    softcap_softmax<<<Bb*NHh*Tt, 256>>>(sc);

    // 5) context = W V per (b,n)
    dim3 gC(1, Tt/128, Bb*NHh);
    gemm_ctx_mma<<<gC, 256>>>(sc, v, ctx);

    // 6) out-proj + residual with inputs -> x_res
    gemm_nn_mma<0, true, true><<<gD, 256>>>(ctx, wo, bo, inputs, xres, MM, Dd, Dd, 1.0f);

    // 7) LN2
    ln_kernel<<<MM, 256>>>(xres, ln2_g, ln2_b, yln);

    // 8) MLP up + exact GELU
    dim3 gF(FFd/128, MM/128);
    gemm_nn_mma<1, true, false><<<gF, 256>>>(yln, w1, b1, nullptr, h1, MM, FFd, Dd, 1.0f);

    // 9) MLP down + bias + residual with x_res -> out
    gemm_nn_mma<0, true, true><<<gD, 256>>>(h1, w2, b2, xres, out, MM, Dd, FFd, 1.0f);
}

// round 5
// speedup vs baseline: 3.4835x; 1.4457x over previous
#include <cuda_runtime.h>
#include <math.h>
#include <stdint.h>

// Problem dims
#define Bb 4
#define Tt 2048
#define Dd 1024
#define NHh 16
#define HDh 64
#define FFd 4096
#define MM (Bb*Tt)          // 8192 rows

// -------- scratch (device globals; no allocs allowed) --------
__device__ float g_xln[(size_t)MM*Dd];
__device__ float g_q  [(size_t)MM*Dd];
__device__ float g_k  [(size_t)MM*Dd];
__device__ float g_v  [(size_t)MM*Dd];
__device__ float g_ctx[(size_t)MM*Dd];
__device__ float g_xres[(size_t)MM*Dd];
__device__ float g_yln[(size_t)MM*Dd];
__device__ float g_h1 [(size_t)MM*FFd];
// tf32-rounded weights
__device__ float g_wq_t[(size_t)Dd*Dd];
__device__ float g_wk_t[(size_t)Dd*Dd];
__device__ float g_wv_t[(size_t)Dd*Dd];
__device__ float g_wo_t[(size_t)Dd*Dd];
__device__ float g_w1_t[(size_t)Dd*FFd];
__device__ float g_w2_t[(size_t)FFd*Dd];

// -------- helpers --------
__device__ __forceinline__ uint32_t f2tf(float f) {
    uint32_t u;
    asm("cvt.rna.tf32.f32 %0, %1;" : "=r"(u) : "f"(f));
    return u;
}

#define MMA_TF32(c, a, b) \
    asm volatile("mma.sync.aligned.m16n8k8.row.col.f32.tf32.tf32.f32 " \
                 "{%0,%1,%2,%3},{%4,%5,%6,%7},{%8,%9},{%0,%1,%2,%3};" \
                 : "+f"((c)[0]), "+f"((c)[1]), "+f"((c)[2]), "+f"((c)[3]) \
                 : "r"((a)[0]), "r"((a)[1]), "r"((a)[2]), "r"((a)[3]), \
                   "r"((b)[0]), "r"((b)[1]))

#define CP16(dst_u32, src_ptr) \
    asm volatile("cp.async.cg.shared.global [%0], [%1], 16;" :: "r"(dst_u32), "l"(src_ptr))
#define CP_COMMIT() asm volatile("cp.async.commit_group;")
#define CP_WAIT0()  asm volatile("cp.async.wait_group 0;")
#define CP_WAIT1()  asm volatile("cp.async.wait_group 1;")

__device__ __forceinline__ uint32_t s2u(const void* p) {
    return (uint32_t)__cvta_generic_to_shared(p);
}

__device__ __forceinline__ float block_reduce_sum(float v, float* sh) {
    int t = threadIdx.x;
    #pragma unroll
    for (int o = 16; o > 0; o >>= 1) v += __shfl_down_sync(0xffffffffu, v, o);
    if ((t & 31) == 0) sh[t >> 5] = v;
    __syncthreads();
    if (t < 32) {
        float w = (t < 8) ? sh[t] : 0.0f;
        #pragma unroll
        for (int o = 4; o > 0; o >>= 1) w += __shfl_down_sync(0xffffffffu, w, o);
        if (t == 0) sh[0] = w;
    }
    __syncthreads();
    float r = sh[0];
    __syncthreads();
    return r;
}

// -------- tf32 rounding elementwise (weights) --------
__global__ void round_tf32_kernel(const float* __restrict__ in, float* __restrict__ out, int n4)
{
    int i = blockIdx.x * 256 + threadIdx.x;
    if (i < n4) {
        float4 v = ((const float4*)in)[i];
        uint4 u;
        u.x = f2tf(v.x); u.y = f2tf(v.y); u.z = f2tf(v.z); u.w = f2tf(v.w);
        ((uint4*)out)[i] = u;
    }
}

// -------- LayerNorm: one block (256 thr) per row of 1024; output tf32-rounded --------
__global__ void ln_kernel(const float* __restrict__ x, const float* __restrict__ gamma,
                          const float* __restrict__ beta, float* __restrict__ out)
{
    __shared__ float sh[32];
    size_t row = blockIdx.x;
    const float4* xr = (const float4*)(x + row * Dd);
    int t = threadIdx.x;
    float4 xv = xr[t];
    float s  = xv.x + xv.y + xv.z + xv.w;
    float s2 = xv.x*xv.x + xv.y*xv.y + xv.z*xv.z + xv.w*xv.w;
    float S  = block_reduce_sum(s,  sh);
    float S2 = block_reduce_sum(s2, sh);
    float mean = S * (1.0f / Dd);
    float var  = S2 * (1.0f / Dd) - mean * mean;
    float rs   = rsqrtf(var + 1e-6f);
    float4 gv = ((const float4*)gamma)[t];
    float4 bv = ((const float4*)beta)[t];
    uint4 ov;
    ov.x = f2tf((xv.x - mean) * rs * gv.x + bv.x);
    ov.y = f2tf((xv.y - mean) * rs * gv.y + bv.y);
    ov.z = f2tf((xv.z - mean) * rs * gv.z + bv.z);
    ov.w = f2tf((xv.w - mean) * rs * gv.w + bv.w);
    ((uint4*)(out + row * Dd))[t] = ov;
}

// ============================================================================
// cp.async double-buffered TF32 GEMM: C = act(alpha*(A@B + bias)) (+res)
// A [M,K] and B [K,N] must be tf32-pre-rounded. BM=128 BN=128 BK=32, 256 thr.
// 2-stage smem pipeline; warps 2m x 4n (warp tile 64x32).
// ============================================================================
#define G2_SMEM ((2*128*36 + 2*32*136)*4)
template<int ACT, bool HAS_BIAS, bool HAS_RES, bool ROUND>
__global__ __launch_bounds__(256, 2) void gemm2(
    const float* __restrict__ A, const float* __restrict__ Bm,
    const float* __restrict__ bias, const float* __restrict__ res,
    float* __restrict__ C, int M, int N, int K, float alpha)
{
    extern __shared__ uint32_t smem_[];
    uint32_t* sA = smem_;               // [2][128*36]
    uint32_t* sB = smem_ + 2*128*36;    // [2][32*136]
    int tid = threadIdx.x;
    int lane = tid & 31, wid = tid >> 5;
    int g = lane >> 2, tig = lane & 3;
    int wm0 = (wid >> 2) * 64;
    int wn0 = (wid & 3) * 32;
    int row0 = blockIdx.y * 128;
    int col0 = blockIdx.x * 128;
    const float* Ab = A + (size_t)row0 * K;
    const float* Bp = Bm + col0;

    int arow = tid >> 3, acol4 = (tid & 7) * 4;
    int brow = tid >> 5, bcol4 = (tid & 31) * 4;

    float acc[4][4][4] = {};

    int nk = K >> 5;
    // copy one stage
    #define COPY_STAGE(buf, k0) do { \
        uint32_t* dA = sA + (buf)*128*36; \
        uint32_t* dB = sB + (buf)*32*136; \
        _Pragma("unroll") \
        for (int i_ = 0; i_ < 4; i_++) { \
            int rr = arow + i_*32; \
            CP16(s2u(dA + rr*36 + acol4), Ab + (size_t)rr * K + (k0) + acol4); \
        } \
        _Pragma("unroll") \
        for (int i_ = 0; i_ < 4; i_++) { \
            int rr = brow + i_*8; \
            CP16(s2u(dB + rr*136 + bcol4), Bp + (size_t)((k0) + rr) * N + bcol4); \
        } \
    } while (0)

    COPY_STAGE(0, 0);
    CP_COMMIT();
    for (int it = 0; it < nk; it++) {
        if (it + 1 < nk) {
            COPY_STAGE((it+1)&1, (it+1)<<5);
            CP_COMMIT();
            CP_WAIT1();
        } else {
            CP_WAIT0();
        }
        __syncthreads();
        uint32_t* cA = sA + (it&1)*128*36;
        uint32_t* cB = sB + (it&1)*32*136;
        #pragma unroll
        for (int kk = 0; kk < 32; kk += 8) {
            uint32_t af[4][4], bf[4][2];
            #pragma unroll
            for (int i = 0; i < 4; i++) {
                int m = wm0 + i*16 + g;
                af[i][0] = cA[m*36 + kk + tig];
                af[i][1] = cA[(m+8)*36 + kk + tig];
                af[i][2] = cA[m*36 + kk + tig + 4];
                af[i][3] = cA[(m+8)*36 + kk + tig + 4];
            }
            #pragma unroll
            for (int j = 0; j < 4; j++) {
                int nn = wn0 + j*8 + g;
                bf[j][0] = cB[(kk + tig)*136 + nn];
                bf[j][1] = cB[(kk + tig + 4)*136 + nn];
            }
            #pragma unroll
            for (int i = 0; i < 4; i++)
                #pragma unroll
                for (int j = 0; j < 4; j++)
                    MMA_TF32(acc[i][j], af[i], bf[j]);
        }
        __syncthreads();
    }
    #undef COPY_STAGE

    // epilogue
    #pragma unroll
    for (int i = 0; i < 4; i++) {
        #pragma unroll
        for (int j = 0; j < 4; j++) {
            int col = col0 + wn0 + j*8 + tig*2;
            #pragma unroll
            for (int h = 0; h < 2; h++) {
                int row = row0 + wm0 + i*16 + g + h*8;
                float v0 = acc[i][j][h*2 + 0];
                float v1 = acc[i][j][h*2 + 1];
                if (HAS_BIAS) { v0 += bias[col]; v1 += bias[col + 1]; }
                v0 *= alpha; v1 *= alpha;
                if (ACT == 1) {
                    v0 = 0.5f * v0 * (1.0f + erff(v0 * 0.70710678118654752f));
                    v1 = 0.5f * v1 * (1.0f + erff(v1 * 0.70710678118654752f));
                }
                if (HAS_RES) {
                    float2 rr = *(const float2*)(res + (size_t)row * N + col);
                    v0 += rr.x; v1 += rr.y;
                }
                if (ROUND) { v0 = __uint_as_float(f2tf(v0)); v1 = __uint_as_float(f2tf(v1)); }
                *(float2*)(C + (size_t)row * N + col) = make_float2(v0, v1);
            }
        }
    }
}

// ============================================================================
// Fused flash attention with soft-cap (fixed softmax reference m=50):
//   p = exp(50*tanh(s/50) - 50) = exp(-100/(e^{s/25}+1))
// Q pre-scaled by 0.125 and tf32-rounded; K,V tf32-rounded.
// BM=128 queries/CTA, BS=64 keys/tile. 256 thr, warps 2m x 4n.
// Row-sum l: per-warp partials (16 cols each) combined across the 4 n-warps
// through smem sL[4][128] at the end.
// ============================================================================
#define FA_SMEM ((128*68 + 64*68 + 64*72 + 128*68 + 4*128)*4)
__global__ __launch_bounds__(256, 2) void flash_attn(
    const float* __restrict__ q, const float* __restrict__ k,
    const float* __restrict__ v, float* __restrict__ ctx)
{
    extern __shared__ uint32_t smem_[];
    uint32_t* sQ = smem_;                 // [128][68]
    uint32_t* sK = smem_ + 128*68;        // [64][68]
    uint32_t* sV = sK + 64*68;            // [64][72]
    uint32_t* sP = sV + 64*72;            // [128][68]
    float*    sL = (float*)(sP + 128*68); // [4][128]
    int tid = threadIdx.x;
    int lane = tid & 31, wid = tid >> 5;
    int g = lane >> 2, tig = lane & 3;
    int wm0 = (wid >> 2) * 64;            // 2 warps on m
    int wn0 = (wid & 3) * 16;             // 4 warps on n (16 cols each)
    int row0 = blockIdx.x * 128;
    int z = blockIdx.y;
    int b = z >> 4, n = z & 15;
    const float* Qb = q + ((size_t)b*Tt + row0) * Dd + n*HDh;
    const float* Kb = k + (size_t)b*Tt*Dd + n*HDh;
    const float* Vb = v + (size_t)b*Tt*Dd + n*HDh;

    // load Q tile (128 x 64)
    {
        int rr = tid >> 4, cq = (tid & 15) * 4;
        #pragma unroll
        for (int i = 0; i < 8; i++) {
            int r2 = rr + i*16;
            CP16(s2u(sQ + r2*68 + cq), Qb + (size_t)r2 * Dd + cq);
        }
    }
    CP_COMMIT();

    float l[8] = {0,0,0,0,0,0,0,0};
    float accO[4][2][4] = {};

    for (int s0 = 0; s0 < Tt; s0 += 64) {
        // load K,V tiles (64 x 64 each)
        {
            int rr = tid >> 4, cq = (tid & 15) * 4;
            #pragma unroll
            for (int i = 0; i < 4; i++) {
                int r2 = rr + i*16;
                CP16(s2u(sK + r2*68 + cq), Kb + (size_t)(s0 + r2) * Dd + cq);
                CP16(s2u(sV + r2*72 + cq), Vb + (size_t)(s0 + r2) * Dd + cq);
            }
        }
        CP_COMMIT();
        CP_WAIT0();
        __syncthreads();

        // S = Q @ K^T  (128 x 64)
        float accS[4][2][4] = {};
        #pragma unroll
        for (int kk = 0; kk < 64; kk += 8) {
            uint32_t af[4][4], bf[2][2];
            #pragma unroll
            for (int i = 0; i < 4; i++) {
                int m = wm0 + i*16 + g;
                af[i][0] = sQ[m*68 + kk + tig];
                af[i][1] = sQ[(m+8)*68 + kk + tig];
                af[i][2] = sQ[m*68 + kk + tig + 4];
                af[i][3] = sQ[(m+8)*68 + kk + tig + 4];
            }
            #pragma unroll
            for (int j = 0; j < 2; j++) {
                int nn = wn0 + j*8 + g;
                bf[j][0] = sK[nn*68 + kk + tig];
                bf[j][1] = sK[nn*68 + kk + tig + 4];
            }
            #pragma unroll
            for (int i = 0; i < 4; i++)
                #pragma unroll
                for (int j = 0; j < 2; j++)
                    MMA_TF32(accS[i][j], af[i], bf[j]);
        }

        // softcap + exp (fixed ref 50) + partial row-sum + store P (tf32)
        #pragma unroll
        for (int i = 0; i < 4; i++) {
            #pragma unroll
            for (int h = 0; h < 2; h++) {
                int m = wm0 + i*16 + g + h*8;
                float ps = 0.0f;
                #pragma unroll
                for (int j = 0; j < 2; j++) {
                    float s0v = accS[i][j][h*2 + 0];
                    float s1v = accS[i][j][h*2 + 1];
                    float u0 = __expf(s0v * 0.04f);
                    float u1 = __expf(s1v * 0.04f);
                    float p0 = __expf(__fdividef(-100.0f, u0 + 1.0f));
                    float p1 = __expf(__fdividef(-100.0f, u1 + 1.0f));
                    ps += p0 + p1;
                    uint2 pv; pv.x = f2tf(p0); pv.y = f2tf(p1);
                    *(uint2*)(sP + m*68 + wn0 + j*8 + tig*2) = pv;
                }
                ps += __shfl_xor_sync(0xffffffffu, ps, 1);
                ps += __shfl_xor_sync(0xffffffffu, ps, 2);
                l[i*2 + h] += ps;     // this warp's 16-column share
            }
        }
        __syncthreads();

        // O += P @ V  (128 x 64, k = 64)
        #pragma unroll
        for (int kk = 0; kk < 64; kk += 8) {
            uint32_t af[4][4], bf[2][2];
            #pragma unroll
            for (int i = 0; i < 4; i++) {
                int m = wm0 + i*16 + g;
                af[i][0] = sP[m*68 + kk + tig];
                af[i][1] = sP[(m+8)*68 + kk + tig];
                af[i][2] = sP[m*68 + kk + tig + 4];
                af[i][3] = sP[(m+8)*68 + kk + tig + 4];
            }
            #pragma unroll
            for (int j = 0; j < 2; j++) {
                int nn = wn0 + j*8 + g;
                bf[j][0] = sV[(kk + tig)*72 + nn];
                bf[j][1] = sV[(kk + tig + 4)*72 + nn];
            }
            #pragma unroll
            for (int i = 0; i < 4; i++)
                #pragma unroll
                for (int j = 0; j < 2; j++)
                    MMA_TF32(accO[i][j], af[i], bf[j]);
        }
        __syncthreads();
    }

    // combine per-warp l partials across the 4 n-warps
    #pragma unroll
    for (int i = 0; i < 4; i++)
        #pragma unroll
        for (int h = 0; h < 2; h++)
            if (tig == 0)
                sL[(wid & 3)*128 + wm0 + i*16 + h*8 + g] = l[i*2 + h];
    __syncthreads();

    // normalize by total l and store ctx (tf32-rounded; feeds out-proj GEMM)
    float* Cb = ctx + ((size_t)b*Tt + row0) * Dd + n*HDh;
    #pragma unroll
    for (int i = 0; i < 4; i++) {
        #pragma unroll
        for (int h = 0; h < 2; h++) {
            int m = wm0 + i*16 + g + h*8;
            float ltot = sL[m] + sL[128 + m] + sL[256 + m] + sL[384 + m];
            float linv = __fdividef(1.0f, ltot);
            #pragma unroll
            for (int j = 0; j < 2; j++) {
                int col = wn0 + j*8 + tig*2;
                float v0 = accO[i][j][h*2 + 0] * linv;
                float v1 = accO[i][j][h*2 + 1] * linv;
                float2 o2 = make_float2(__uint_as_float(f2tf(v0)),
                                        __uint_as_float(f2tf(v1)));
                *(float2*)(Cb + (size_t)m * Dd + col) = o2;
            }
        }
    }
}

// -------- launch --------
extern "C" void kernel_launch(void* const* d_in, const int* in_sizes, int n_in,
                              void* d_out, int out_size)
{
    const float* inputs = (const float*)d_in[0];
    const float* ln1_g  = (const float*)d_in[1];
    const float* ln1_b  = (const float*)d_in[2];
    const float* wq     = (const float*)d_in[3];
    const float* bq     = (const float*)d_in[4];
    const float* wk     = (const float*)d_in[5];
    const float* bk     = (const float*)d_in[6];
    const float* wv     = (const float*)d_in[7];
    const float* bv     = (const float*)d_in[8];
    const float* wo     = (const float*)d_in[9];
    const float* bo     = (const float*)d_in[10];
    const float* ln2_g  = (const float*)d_in[11];
    const float* ln2_b  = (const float*)d_in[12];
    const float* w1     = (const float*)d_in[13];
    const float* b1     = (const float*)d_in[14];
    const float* w2     = (const float*)d_in[15];
    const float* b2     = (const float*)d_in[16];
    float* out = (float*)d_out;

    float *xln, *q, *k, *v, *ctx, *xres, *yln, *h1;
    float *wq_t, *wk_t, *wv_t, *wo_t, *w1_t, *w2_t;
    cudaGetSymbolAddress((void**)&xln,  g_xln);
    cudaGetSymbolAddress((void**)&q,    g_q);
    cudaGetSymbolAddress((void**)&k,    g_k);
    cudaGetSymbolAddress((void**)&v,    g_v);
    cudaGetSymbolAddress((void**)&ctx,  g_ctx);
    cudaGetSymbolAddress((void**)&xres, g_xres);
    cudaGetSymbolAddress((void**)&yln,  g_yln);
    cudaGetSymbolAddress((void**)&h1,   g_h1);
    cudaGetSymbolAddress((void**)&wq_t, g_wq_t);
    cudaGetSymbolAddress((void**)&wk_t, g_wk_t);
    cudaGetSymbolAddress((void**)&wv_t, g_wv_t);
    cudaGetSymbolAddress((void**)&wo_t, g_wo_t);
    cudaGetSymbolAddress((void**)&w1_t, g_w1_t);
    cudaGetSymbolAddress((void**)&w2_t, g_w2_t);

    // opt-in dynamic smem
    cudaFuncSetAttribute((const void*)gemm2<0,true,false,true>,  cudaFuncAttributeMaxDynamicSharedMemorySize, G2_SMEM);
    cudaFuncSetAttribute((const void*)gemm2<0,true,true,false>,  cudaFuncAttributeMaxDynamicSharedMemorySize, G2_SMEM);
    cudaFuncSetAttribute((const void*)gemm2<1,true,false,true>,  cudaFuncAttributeMaxDynamicSharedMemorySize, G2_SMEM);
    cudaFuncSetAttribute((const void*)flash_attn, cudaFuncAttributeMaxDynamicSharedMemorySize, FA_SMEM);

    // 0) round weights to tf32
    round_tf32_kernel<<<(Dd*Dd/4 + 255)/256, 256>>>(wq, wq_t, Dd*Dd/4);
    round_tf32_kernel<<<(Dd*Dd/4 + 255)/256, 256>>>(wk, wk_t, Dd*Dd/4);
    round_tf32_kernel<<<(Dd*Dd/4 + 255)/256, 256>>>(wv, wv_t, Dd*Dd/4);
    round_tf32_kernel<<<(Dd*Dd/4 + 255)/256, 256>>>(wo, wo_t, Dd*Dd/4);
    round_tf32_kernel<<<(Dd*FFd/4 + 255)/256, 256>>>(w1, w1_t, Dd*FFd/4);
    round_tf32_kernel<<<(FFd*Dd/4 + 255)/256, 256>>>(w2, w2_t, FFd*Dd/4);

    // 1) LN1 (tf32-rounded out)
    ln_kernel<<<MM, 256>>>(inputs, ln1_g, ln1_b, xln);

    // 2) QKV projections (q scaled by 0.125; outputs tf32-rounded for flash mma)
    dim3 gD(Dd/128, MM/128);
    gemm2<0,true,false,true><<<gD, 256, G2_SMEM>>>(xln, wq_t, bq, nullptr, q, MM, Dd, Dd, 0.125f);
    gemm2<0,true,false,true><<<gD, 256, G2_SMEM>>>(xln, wk_t, bk, nullptr, k, MM, Dd, Dd, 1.0f);
    gemm2<0,true,false,true><<<gD, 256, G2_SMEM>>>(xln, wv_t, bv, nullptr, v, MM, Dd, Dd, 1.0f);

    // 3) fused attention -> ctx
    dim3 gA(Tt/128, Bb*NHh);
    flash_attn<<<gA, 256, FA_SMEM>>>(q, k, v, ctx);

    // 4) out-proj + residual(inputs) -> xres (fp32, no rounding)
    gemm2<0,true,true,false><<<gD, 256, G2_SMEM>>>(ctx, wo_t, bo, inputs, xres, MM, Dd, Dd, 1.0f);

    // 5) LN2
    ln_kernel<<<MM, 256>>>(xres, ln2_g, ln2_b, yln);

    // 6) MLP up + exact GELU -> h1 (tf32-rounded)
    dim3 gF(FFd/128, MM/128);
    gemm2<1,true,false,true><<<gF, 256, G2_SMEM>>>(yln, w1_t, b1, nullptr, h1, MM, FFd, Dd, 1.0f);

    // 7) MLP down + bias + residual(xres) -> out
    gemm2<0,true,true,false><<<gD, 256, G2_SMEM>>>(h1, w2_t, b2, xres, out, MM, Dd, FFd, 1.0f);
}

// round 7
// speedup vs baseline: 5.8120x; 1.6684x over previous
#include <cuda_runtime.h>
#include <cuda_fp16.h>
#include <math.h>
#include <stdint.h>

// Problem dims
#define Bb 4
#define Tt 2048
#define Dd 1024
#define NHh 16
#define HDh 64
#define FFd 4096
#define MM (Bb*Tt)          // 8192 rows

// -------- scratch (device globals; no allocs allowed) --------
__device__ __half g_xln[(size_t)MM*Dd];
__device__ __half g_q  [(size_t)MM*Dd];
__device__ __half g_k  [(size_t)MM*Dd];
__device__ __half g_v  [(size_t)MM*Dd];
__device__ __half g_ctx[(size_t)MM*Dd];
__device__ float  g_xres[(size_t)MM*Dd];
__device__ __half g_yln[(size_t)MM*Dd];
__device__ __half g_h1 [(size_t)MM*FFd];
// packed fp16 weights: u32 [K/2][N], u32 = half2(w[2r][n], w[2r+1][n])
__device__ uint32_t g_wq_p[(size_t)Dd/2*Dd];
__device__ uint32_t g_wk_p[(size_t)Dd/2*Dd];
__device__ uint32_t g_wv_p[(size_t)Dd/2*Dd];
__device__ uint32_t g_wo_p[(size_t)Dd/2*Dd];
__device__ uint32_t g_w1_p[(size_t)Dd/2*FFd];
__device__ uint32_t g_w2_p[(size_t)FFd/2*Dd];

// -------- helpers --------
#define MMA_F16(c, a, b) \
    asm volatile("mma.sync.aligned.m16n8k16.row.col.f32.f16.f16.f32 " \
                 "{%0,%1,%2,%3},{%4,%5,%6,%7},{%8,%9},{%0,%1,%2,%3};" \
                 : "+f"((c)[0]), "+f"((c)[1]), "+f"((c)[2]), "+f"((c)[3]) \
                 : "r"((a)[0]), "r"((a)[1]), "r"((a)[2]), "r"((a)[3]), \
                   "r"((b)[0]), "r"((b)[1]))

#define CP16(dst_u32, src_ptr) \
    asm volatile("cp.async.cg.shared.global [%0], [%1], 16;" :: "r"(dst_u32), "l"(src_ptr))
#define CP_COMMIT() asm volatile("cp.async.commit_group;")
#define CP_WAIT0()  asm volatile("cp.async.wait_group 0;")
#define CP_WAIT1()  asm volatile("cp.async.wait_group 1;")

__device__ __forceinline__ uint32_t s2u(const void* p) {
    return (uint32_t)__cvta_generic_to_shared(p);
}

__device__ __forceinline__ uint32_t h2u(__half2 h) {
    return *(uint32_t*)&h;
}

__device__ __forceinline__ float block_reduce_sum(float v, float* sh) {
    int t = threadIdx.x;
    #pragma unroll
    for (int o = 16; o > 0; o >>= 1) v += __shfl_down_sync(0xffffffffu, v, o);
    if ((t & 31) == 0) sh[t >> 5] = v;
    __syncthreads();
    if (t < 32) {
        float w = (t < 8) ? sh[t] : 0.0f;
        #pragma unroll
        for (int o = 4; o > 0; o >>= 1) w += __shfl_down_sync(0xffffffffu, w, o);
        if (t == 0) sh[0] = w;
    }
    __syncthreads();
    float r = sh[0];
    __syncthreads();
    return r;
}

// -------- weight pack: fp32 [K][N] -> u32 [K/2][N] (half2 along k) --------
__global__ void pack_w_kernel(const float* __restrict__ in, uint32_t* __restrict__ out,
                              int N, int total)   // total = K/2*N
{
    int idx = blockIdx.x * 256 + threadIdx.x;
    if (idx < total) {
        int r = idx / N, n = idx - r * N;
        float a = in[(size_t)(2*r) * N + n];
        float b = in[(size_t)(2*r+1) * N + n];
        out[idx] = h2u(__floats2half2_rn(a, b));
    }
}

// -------- LayerNorm: one block (256 thr) per row of 1024; fp16 out --------
__global__ void ln_kernel(const float* __restrict__ x, const float* __restrict__ gamma,
                          const float* __restrict__ beta, __half* __restrict__ out)
{
    __shared__ float sh[32];
    size_t row = blockIdx.x;
    const float4* xr = (const float4*)(x + row * Dd);
    int t = threadIdx.x;
    float4 xv = xr[t];
    float s  = xv.x + xv.y + xv.z + xv.w;
    float s2 = xv.x*xv.x + xv.y*xv.y + xv.z*xv.z + xv.w*xv.w;
    float S  = block_reduce_sum(s,  sh);
    float S2 = block_reduce_sum(s2, sh);
    float mean = S * (1.0f / Dd);
    float var  = S2 * (1.0f / Dd) - mean * mean;
    float rs   = rsqrtf(var + 1e-6f);
    float4 gv = ((const float4*)gamma)[t];
    float4 bv = ((const float4*)beta)[t];
    __half2 h0 = __floats2half2_rn((xv.x - mean) * rs * gv.x + bv.x,
                                   (xv.y - mean) * rs * gv.y + bv.y);
    __half2 h1 = __floats2half2_rn((xv.z - mean) * rs * gv.z + bv.z,
                                   (xv.w - mean) * rs * gv.w + bv.w);
    uint2 pkd; pkd.x = h2u(h0); pkd.y = h2u(h1);
    *(uint2*)(out + row * Dd + t*4) = pkd;
}

// ============================================================================
// cp.async double-buffered FP16 GEMM: C = act(alpha*(A@B + bias)) (+res)
// A [M,K] fp16 row-major; B packed u32 [K/2][N]. BM=128 BN=128 BK=32, 256 thr.
// 2-stage pipeline; warps 2m x 4n (warp tile 64x32); mma m16n8k16.
// smem: sA u32 [128][20] (u32 = k-pair), sB u32 [16][136].
// ============================================================================
#define G2_SMEM ((2*128*20 + 2*16*136)*4)
template<int ACT, bool HAS_BIAS, bool HAS_RES, bool OUT_HALF>
__global__ __launch_bounds__(256, 2) void gemm2(
    const __half* __restrict__ A, const uint32_t* __restrict__ Bm,
    const float* __restrict__ bias, const float* __restrict__ res,
    void* __restrict__ Cv, int M, int N, int K, float alpha)
{
    extern __shared__ uint32_t smem_[];
    uint32_t* sA = smem_;               // [2][128*20]
    uint32_t* sB = smem_ + 2*128*20;    // [2][16*136]
    int tid = threadIdx.x;
    int lane = tid & 31, wid = tid >> 5;
    int g = lane >> 2, tig = lane & 3;
    int wm0 = (wid >> 2) * 64;
    int wn0 = (wid & 3) * 32;
    int row0 = blockIdx.y * 128;
    int col0 = blockIdx.x * 128;
    const __half* Ab = A + (size_t)row0 * K;
    const uint32_t* Bp = Bm + col0;

    float acc[4][4][4] = {};

    int nk = K >> 5;
    // copy one stage: A 128 rows x 32 halfs (4 x 16B chunks/row); B 16 kpair rows x 128 u32
    #define COPY_STAGE(buf, k0) do { \
        uint32_t* dA = sA + (buf)*128*20; \
        uint32_t* dB = sB + (buf)*16*136; \
        _Pragma("unroll") \
        for (int i_ = 0; i_ < 2; i_++) { \
            int f = tid + i_*256; \
            int rr = f >> 2, cq = f & 3; \
            CP16(s2u(dA + rr*20 + cq*4), Ab + (size_t)rr * K + (k0) + cq*8); \
        } \
        _Pragma("unroll") \
        for (int i_ = 0; i_ < 2; i_++) { \
            int f = tid + i_*256; \
            int rr = f >> 5, cq = f & 31; \
            CP16(s2u(dB + rr*136 + cq*4), Bp + (size_t)(((k0)>>1) + rr) * N + cq*4); \
        } \
    } while (0)

    COPY_STAGE(0, 0);
    CP_COMMIT();
    for (int it = 0; it < nk; it++) {
        if (it + 1 < nk) {
            COPY_STAGE((it+1)&1, (it+1)<<5);
            CP_COMMIT();
            CP_WAIT1();
        } else {
            CP_WAIT0();
        }
        __syncthreads();
        uint32_t* cA = sA + (it&1)*128*20;
        uint32_t* cB = sB + (it&1)*16*136;
        #pragma unroll
        for (int kk = 0; kk < 32; kk += 16) {
            int kc = kk >> 1;
            uint32_t af[4][4], bf[4][2];
            #pragma unroll
            for (int i = 0; i < 4; i++) {
                int m = wm0 + i*16 + g;
                af[i][0] = cA[m*20 + kc + tig];
                af[i][1] = cA[(m+8)*20 + kc + tig];
                af[i][2] = cA[m*20 + kc + tig + 4];
                af[i][3] = cA[(m+8)*20 + kc + tig + 4];
            }
            #pragma unroll
            for (int j = 0; j < 4; j++) {
                int nn = wn0 + j*8 + g;
                bf[j][0] = cB[(kc + tig)*136 + nn];
                bf[j][1] = cB[(kc + tig + 4)*136 + nn];
            }
            #pragma unroll
            for (int i = 0; i < 4; i++)
                #pragma unroll
                for (int j = 0; j < 4; j++)
                    MMA_F16(acc[i][j], af[i], bf[j]);
        }
        __syncthreads();
    }
    #undef COPY_STAGE

    // epilogue
    #pragma unroll
    for (int i = 0; i < 4; i++) {
        #pragma unroll
        for (int j = 0; j < 4; j++) {
            int col = col0 + wn0 + j*8 + tig*2;
            #pragma unroll
            for (int h = 0; h < 2; h++) {
                int row = row0 + wm0 + i*16 + g + h*8;
                float v0 = acc[i][j][h*2 + 0];
                float v1 = acc[i][j][h*2 + 1];
                if (HAS_BIAS) { v0 += bias[col]; v1 += bias[col + 1]; }
                v0 *= alpha; v1 *= alpha;
                if (ACT == 1) {
                    v0 = 0.5f * v0 * (1.0f + erff(v0 * 0.70710678118654752f));
                    v1 = 0.5f * v1 * (1.0f + erff(v1 * 0.70710678118654752f));
                }
                if (HAS_RES) {
                    float2 rr = *(const float2*)(res + (size_t)row * N + col);
                    v0 += rr.x; v1 += rr.y;
                }
                if (OUT_HALF) {
                    __half2 h2v = __floats2half2_rn(v0, v1);
                    *(uint32_t*)((__half*)Cv + (size_t)row * N + col) = h2u(h2v);
                } else {
                    *(float2*)((float*)Cv + (size_t)row * N + col) = make_float2(v0, v1);
                }
            }
        }
    }
}

// ============================================================================
// Fused flash attention, fp16 operands, soft-cap with fixed reference 2:
//   p = exp(min(50*tanh(s/50), 10) - 2); reference cancels in l-normalization.
// Q pre-scaled by 0.125. BM=128, BS=64. 256 thr, warps 2m x 4n.
// smem u32: sQ [128][36], sK [64][36], sV packed [32][72], sP packed [128][36].
// ============================================================================
#define FA_SMEM ((128*36 + 64*36 + 32*72 + 128*36 + 4*128)*4)
__global__ __launch_bounds__(256, 2) void flash_attn(
    const __half* __restrict__ q, const __half* __restrict__ k,
    const __half* __restrict__ v, __half* __restrict__ ctx)
{
    extern __shared__ uint32_t smem_[];
    uint32_t* sQ = smem_;                 // [128][36]
    uint32_t* sK = smem_ + 128*36;        // [64][36]
    uint32_t* sV = sK + 64*36;            // [32][72] packed s-pairs
    uint32_t* sP = sV + 32*72;            // [128][36] packed s-pairs
    float*    sL = (float*)(sP + 128*36); // [4][128]
    int tid = threadIdx.x;
    int lane = tid & 31, wid = tid >> 5;
    int g = lane >> 2, tig = lane & 3;
    int wm0 = (wid >> 2) * 64;            // 2 warps on m
    int wn0 = (wid & 3) * 16;             // 4 warps on n (16 cols each)
    int row0 = blockIdx.x * 128;
    int z = blockIdx.y;
    int b = z >> 4, n = z & 15;
    const __half* Qb = q + ((size_t)b*Tt + row0) * Dd + n*HDh;
    const __half* Kb = k + (size_t)b*Tt*Dd + n*HDh;
    const __half* Vb = v + (size_t)b*Tt*Dd + n*HDh;

    // load Q tile (128 x 64 halfs, 8 x 16B chunks per row)
    #pragma unroll
    for (int i = 0; i < 4; i++) {
        int f = tid + i*256;
        int rr = f >> 3, cq = f & 7;
        CP16(s2u(sQ + rr*36 + cq*4), Qb + (size_t)rr * Dd + cq*8);
    }
    CP_COMMIT();

    float l[8] = {0,0,0,0,0,0,0,0};
    float accO[4][2][4] = {};

    for (int s0 = 0; s0 < Tt; s0 += 64) {
        // K tile via cp.async (64 x 64 halfs)
        #pragma unroll
        for (int i = 0; i < 2; i++) {
            int f = tid + i*256;
            int rr = f >> 3, cq = f & 7;
            CP16(s2u(sK + rr*36 + cq*4), Kb + (size_t)(s0 + rr) * Dd + cq*8);
        }
        CP_COMMIT();
        // V tile: load + transpose-pack into s-pair half2s
        #pragma unroll
        for (int i = 0; i < 2; i++) {
            int u = tid + i*256;
            int r = u >> 4, hq = u & 15;     // r: s-pair 0..31, hq: 4-col group
            uint2 a = *(const uint2*)(Vb + (size_t)(s0 + 2*r    ) * Dd + hq*4);
            uint2 bb= *(const uint2*)(Vb + (size_t)(s0 + 2*r + 1) * Dd + hq*4);
            uint4 o;
            o.x = (a.x & 0xFFFFu) | (bb.x << 16);
            o.y = (a.x >> 16)     | (bb.x & 0xFFFF0000u);
            o.z = (a.y & 0xFFFFu) | (bb.y << 16);
            o.w = (a.y >> 16)     | (bb.y & 0xFFFF0000u);
            *(uint4*)(sV + r*72 + hq*4) = o;
        }
        CP_WAIT0();
        __syncthreads();

        // S = Q @ K^T  (128 x 64)
        float accS[4][2][4] = {};
        #pragma unroll
        for (int kk = 0; kk < 64; kk += 16) {
            int kc = kk >> 1;
            uint32_t af[4][4], bf[2][2];
            #pragma unroll
            for (int i = 0; i < 4; i++) {
                int m = wm0 + i*16 + g;
                af[i][0] = sQ[m*36 + kc + tig];
                af[i][1] = sQ[(m+8)*36 + kc + tig];
                af[i][2] = sQ[m*36 + kc + tig + 4];
                af[i][3] = sQ[(m+8)*36 + kc + tig + 4];
            }
            #pragma unroll
            for (int j = 0; j < 2; j++) {
                int nn = wn0 + j*8 + g;
                bf[j][0] = sK[nn*36 + kc + tig];
                bf[j][1] = sK[nn*36 + kc + tig + 4];
            }
            #pragma unroll
            for (int i = 0; i < 4; i++)
                #pragma unroll
                for (int j = 0; j < 2; j++)
                    MMA_F16(accS[i][j], af[i], bf[j]);
        }

        // softcap + exp (fixed ref 2) + partial row-sum + store P (fp16 pairs)
        #pragma unroll
        for (int i = 0; i < 4; i++) {
            #pragma unroll
            for (int h = 0; h < 2; h++) {
                int m = wm0 + i*16 + g + h*8;
                float ps = 0.0f;
                #pragma unroll
                for (int j = 0; j < 2; j++) {
                    float s0v = accS[i][j][h*2 + 0];
                    float s1v = accS[i][j][h*2 + 1];
                    float u0 = __expf(s0v * 0.04f);
                    float u1 = __expf(s1v * 0.04f);
                    float w0 = fminf(48.0f - __fdividef(100.0f, u0 + 1.0f), 8.0f);
                    float w1 = fminf(48.0f - __fdividef(100.0f, u1 + 1.0f), 8.0f);
                    float p0 = __expf(w0);
                    float p1 = __expf(w1);
                    ps += p0 + p1;
                    sP[m*36 + (wid&3)*8 + j*4 + tig] = h2u(__floats2half2_rn(p0, p1));
                }
                ps += __shfl_xor_sync(0xffffffffu, ps, 1);
                ps += __shfl_xor_sync(0xffffffffu, ps, 2);
                l[i*2 + h] += ps;     // this warp's 16-column share
            }
        }
        __syncthreads();

        // O += P @ V  (128 x 64, k = 64)
        #pragma unroll
        for (int kk = 0; kk < 64; kk += 16) {
            int kc = kk >> 1;
            uint32_t af[4][4], bf[2][2];
            #pragma unroll
            for (int i = 0; i < 4; i++) {
                int m = wm0 + i*16 + g;
                af[i][0] = sP[m*36 + kc + tig];
                af[i][1] = sP[(m+8)*36 + kc + tig];
                af[i][2] = sP[m*36 + kc + tig + 4];
                af[i][3] = sP[(m+8)*36 + kc + tig + 4];
            }
            #pragma unroll
            for (int j = 0; j < 2; j++) {
                int nn = wn0 + j*8 + g;
                bf[j][0] = sV[(kc + tig)*72 + nn];
                bf[j][1] = sV[(kc + tig + 4)*72 + nn];
            }
            #pragma unroll
            for (int i = 0; i < 4; i++)
                #pragma unroll
                for (int j = 0; j < 2; j++)
                    MMA_F16(accO[i][j], af[i], bf[j]);
        }
        __syncthreads();
    }

    // combine per-warp l partials across the 4 n-warps
    #pragma unroll
    for (int i = 0; i < 4; i++)
        #pragma unroll
        for (int h = 0; h < 2; h++)
            if (tig == 0)
                sL[(wid & 3)*128 + wm0 + i*16 + h*8 + g] = l[i*2 + h];
    __syncthreads();

    // normalize by total l and store ctx (fp16; feeds out-proj GEMM)
    __half* Cb = ctx + ((size_t)b*Tt + row0) * Dd + n*HDh;
    #pragma unroll
    for (int i = 0; i < 4; i++) {
        #pragma unroll
        for (int h = 0; h < 2; h++) {
            int m = wm0 + i*16 + g + h*8;
            float ltot = sL[m] + sL[128 + m] + sL[256 + m] + sL[384 + m];
            float linv = __fdividef(1.0f, ltot);
            #pragma unroll
            for (int j = 0; j < 2; j++) {
                int col = wn0 + j*8 + tig*2;
                float v0 = accO[i][j][h*2 + 0] * linv;
                float v1 = accO[i][j][h*2 + 1] * linv;
                *(uint32_t*)(Cb + (size_t)m * Dd + col) =
                    h2u(__floats2half2_rn(v0, v1));
            }
        }
    }
}

// -------- launch --------
extern "C" void kernel_launch(void* const* d_in, const int* in_sizes, int n_in,
                              void* d_out, int out_size)
{
    const float* inputs = (const float*)d_in[0];
    const float* ln1_g  = (const float*)d_in[1];
    const float* ln1_b  = (const float*)d_in[2];
    const float* wq     = (const float*)d_in[3];
    const float* bq     = (const float*)d_in[4];
    const float* wk     = (const float*)d_in[5];
    const float* bk     = (const float*)d_in[6];
    const float* wv     = (const float*)d_in[7];
    const float* bv     = (const float*)d_in[8];
    const float* wo     = (const float*)d_in[9];
    const float* bo     = (const float*)d_in[10];
    const float* ln2_g  = (const float*)d_in[11];
    const float* ln2_b  = (const float*)d_in[12];
    const float* w1     = (const float*)d_in[13];
    const float* b1     = (const float*)d_in[14];
    const float* w2     = (const float*)d_in[15];
    const float* b2     = (const float*)d_in[16];
    float* out = (float*)d_out;

    __half *xln, *q, *k, *v, *ctx, *yln, *h1;
    float *xres;
    uint32_t *wq_p, *wk_p, *wv_p, *wo_p, *w1_p, *w2_p;
    cudaGetSymbolAddress((void**)&xln,  g_xln);
    cudaGetSymbolAddress((void**)&q,    g_q);
    cudaGetSymbolAddress((void**)&k,    g_k);
    cudaGetSymbolAddress((void**)&v,    g_v);
    cudaGetSymbolAddress((void**)&ctx,  g_ctx);
    cudaGetSymbolAddress((void**)&xres, g_xres);
    cudaGetSymbolAddress((void**)&yln,  g_yln);
    cudaGetSymbolAddress((void**)&h1,   g_h1);
    cudaGetSymbolAddress((void**)&wq_p, g_wq_p);
    cudaGetSymbolAddress((void**)&wk_p, g_wk_p);
    cudaGetSymbolAddress((void**)&wv_p, g_wv_p);
    cudaGetSymbolAddress((void**)&wo_p, g_wo_p);
    cudaGetSymbolAddress((void**)&w1_p, g_w1_p);
    cudaGetSymbolAddress((void**)&w2_p, g_w2_p);

    // opt-in dynamic smem
    cudaFuncSetAttribute((const void*)gemm2<0,true,false,true>,  cudaFuncAttributeMaxDynamicSharedMemorySize, G2_SMEM);
    cudaFuncSetAttribute((const void*)gemm2<0,true,true,false>,  cudaFuncAttributeMaxDynamicSharedMemorySize, G2_SMEM);
    cudaFuncSetAttribute((const void*)gemm2<1,true,false,true>,  cudaFuncAttributeMaxDynamicSharedMemorySize, G2_SMEM);
    cudaFuncSetAttribute((const void*)flash_attn, cudaFuncAttributeMaxDynamicSharedMemorySize, FA_SMEM);

    // 0) pack weights to fp16 k-pair-interleaved
    {
        int tot = Dd/2*Dd;
        pack_w_kernel<<<(tot+255)/256, 256>>>(wq, wq_p, Dd, tot);
        pack_w_kernel<<<(tot+255)/256, 256>>>(wk, wk_p, Dd, tot);
        pack_w_kernel<<<(tot+255)/256, 256>>>(wv, wv_p, Dd, tot);
        pack_w_kernel<<<(tot+255)/256, 256>>>(wo, wo_p, Dd, tot);
        int tot1 = Dd/2*FFd;
        pack_w_kernel<<<(tot1+255)/256, 256>>>(w1, w1_p, FFd, tot1);
        int tot2 = FFd/2*Dd;
        pack_w_kernel<<<(tot2+255)/256, 256>>>(w2, w2_p, Dd, tot2);
    }

    // 1) LN1 (fp16 out)
    ln_kernel<<<MM, 256>>>(inputs, ln1_g, ln1_b, xln);

    // 2) QKV projections (q scaled by 0.125)
    dim3 gD(Dd/128, MM/128);
    gemm2<0,true,false,true><<<gD, 256, G2_SMEM>>>(xln, wq_p, bq, nullptr, q, MM, Dd, Dd, 0.125f);
    gemm2<0,true,false,true><<<gD, 256, G2_SMEM>>>(xln, wk_p, bk, nullptr, k, MM, Dd, Dd, 1.0f);
    gemm2<0,true,false,true><<<gD, 256, G2_SMEM>>>(xln, wv_p, bv, nullptr, v, MM, Dd, Dd, 1.0f);

    // 3) fused attention -> ctx
    dim3 gA(Tt/128, Bb*NHh);
    flash_attn<<<gA, 256, FA_SMEM>>>(q, k, v, ctx);

    // 4) out-proj + residual(inputs) -> xres (fp32)
    gemm2<0,true,true,false><<<gD, 256, G2_SMEM>>>(ctx, wo_p, bo, inputs, xres, MM, Dd, Dd, 1.0f);

    // 5) LN2
    ln_kernel<<<MM, 256>>>(xres, ln2_g, ln2_b, yln);

    // 6) MLP up + exact GELU -> h1 (fp16)
    dim3 gF(FFd/128, MM/128);
    gemm2<1,true,false,true><<<gF, 256, G2_SMEM>>>(yln, w1_p, b1, nullptr, h1, MM, FFd, Dd, 1.0f);

    // 7) MLP down + bias + residual(xres) -> out (fp32)
    gemm2<0,true,true,false><<<gD, 256, G2_SMEM>>>(h1, w2_p, b2, xres, out, MM, Dd, FFd, 1.0f);
}

// round 8
// speedup vs baseline: 6.4030x; 1.1017x over previous
#include <cuda_runtime.h>
#include <cuda_fp16.h>
#include <math.h>
#include <stdint.h>

// Problem dims
#define Bb 4
#define Tt 2048
#define Dd 1024
#define NHh 16
#define HDh 64
#define FFd 4096
#define MM (Bb*Tt)          // 8192 rows
#define QKVS 3072           // fused qkv row stride

// -------- scratch (device globals; no allocs allowed) --------
__device__ __half g_xln[(size_t)MM*Dd];
__device__ __half g_qkv[(size_t)MM*QKVS];
__device__ __half g_ctx[(size_t)MM*Dd];
__device__ float  g_xres[(size_t)MM*Dd];
__device__ __half g_yln[(size_t)MM*Dd];
__device__ __half g_h1 [(size_t)MM*FFd];
// packed fp16 weights: u32 [K/2][N], u32 = half2(w[2r][n], w[2r+1][n])
__device__ uint32_t g_wqkv_p[(size_t)Dd/2*QKVS];
__device__ float    g_bqkv  [QKVS];
__device__ uint32_t g_wo_p[(size_t)Dd/2*Dd];
__device__ uint32_t g_w1_p[(size_t)Dd/2*FFd];
__device__ uint32_t g_w2_p[(size_t)FFd/2*Dd];

// -------- helpers --------
#define MMA_F16(c, a, b) \
    asm volatile("mma.sync.aligned.m16n8k16.row.col.f32.f16.f16.f32 " \
                 "{%0,%1,%2,%3},{%4,%5,%6,%7},{%8,%9},{%0,%1,%2,%3};" \
                 : "+f"((c)[0]), "+f"((c)[1]), "+f"((c)[2]), "+f"((c)[3]) \
                 : "r"((a)[0]), "r"((a)[1]), "r"((a)[2]), "r"((a)[3]), \
                   "r"((b)[0]), "r"((b)[1]))

#define LDSM4(r0, r1, r2, r3, addr) \
    asm volatile("ldmatrix.sync.aligned.m8n8.x4.shared.b16 {%0,%1,%2,%3}, [%4];" \
                 : "=r"(r0), "=r"(r1), "=r"(r2), "=r"(r3) : "r"(addr))

#define CP16(dst_u32, src_ptr) \
    asm volatile("cp.async.cg.shared.global [%0], [%1], 16;" :: "r"(dst_u32), "l"(src_ptr))
#define CP_COMMIT() asm volatile("cp.async.commit_group;")
#define CP_WAIT0()  asm volatile("cp.async.wait_group 0;")
#define CP_WAIT1()  asm volatile("cp.async.wait_group 1;")

__device__ __forceinline__ uint32_t s2u(const void* p) {
    return (uint32_t)__cvta_generic_to_shared(p);
}
__device__ __forceinline__ uint32_t h2u(__half2 h) { return *(uint32_t*)&h; }

__device__ __forceinline__ float block_reduce_sum(float v, float* sh) {
    int t = threadIdx.x;
    #pragma unroll
    for (int o = 16; o > 0; o >>= 1) v += __shfl_down_sync(0xffffffffu, v, o);
    if ((t & 31) == 0) sh[t >> 5] = v;
    __syncthreads();
    if (t < 32) {
        float w = (t < 8) ? sh[t] : 0.0f;
        #pragma unroll
        for (int o = 4; o > 0; o >>= 1) w += __shfl_down_sync(0xffffffffu, w, o);
        if (t == 0) sh[0] = w;
    }
    __syncthreads();
    float r = sh[0];
    __syncthreads();
    return r;
}

// -------- weight pack: fp32 [K][N] -> u32 [K/2][N] (half2 along k) --------
__global__ void pack_w_kernel(const float* __restrict__ in, uint32_t* __restrict__ out,
                              int N, int total)   // total = K/2*N
{
    int idx = blockIdx.x * 256 + threadIdx.x;
    if (idx < total) {
        int r = idx / N, n = idx - r * N;
        float a = in[(size_t)(2*r) * N + n];
        float b = in[(size_t)(2*r+1) * N + n];
        out[idx] = h2u(__floats2half2_rn(a, b));
    }
}

// -------- fused qkv weight pack (wq pre-scaled 0.125) --------
__global__ void pack_qkv_w_kernel(const float* __restrict__ wq, const float* __restrict__ wk,
                                  const float* __restrict__ wv, uint32_t* __restrict__ out)
{
    int idx = blockIdx.x * 256 + threadIdx.x;   // total Dd/2*QKVS
    if (idx < Dd/2*QKVS) {
        int r = idx / QKVS, n = idx - r * QKVS;
        const float* src; float sc; int nn;
        if (n < Dd)        { src = wq; sc = 0.125f; nn = n; }
        else if (n < 2*Dd) { src = wk; sc = 1.0f;   nn = n - Dd; }
        else               { src = wv; sc = 1.0f;   nn = n - 2*Dd; }
        float a = src[(size_t)(2*r) * Dd + nn] * sc;
        float b = src[(size_t)(2*r+1) * Dd + nn] * sc;
        out[idx] = h2u(__floats2half2_rn(a, b));
    }
}

__global__ void pack_qkv_b_kernel(const float* __restrict__ bq, const float* __restrict__ bk,
                                  const float* __restrict__ bv, float* __restrict__ out)
{
    int n = blockIdx.x * 256 + threadIdx.x;
    if (n < QKVS) {
        if (n < Dd)        out[n] = bq[n] * 0.125f;
        else if (n < 2*Dd) out[n] = bk[n - Dd];
        else               out[n] = bv[n - 2*Dd];
    }
}

// -------- LayerNorm: one block (256 thr) per row of 1024; fp16 out --------
__global__ void ln_kernel(const float* __restrict__ x, const float* __restrict__ gamma,
                          const float* __restrict__ beta, __half* __restrict__ out)
{
    __shared__ float sh[32];
    size_t row = blockIdx.x;
    const float4* xr = (const float4*)(x + row * Dd);
    int t = threadIdx.x;
    float4 xv = xr[t];
    float s  = xv.x + xv.y + xv.z + xv.w;
    float s2 = xv.x*xv.x + xv.y*xv.y + xv.z*xv.z + xv.w*xv.w;
    float S  = block_reduce_sum(s,  sh);
    float S2 = block_reduce_sum(s2, sh);
    float mean = S * (1.0f / Dd);
    float var  = S2 * (1.0f / Dd) - mean * mean;
    float rs   = rsqrtf(var + 1e-6f);
    float4 gv = ((const float4*)gamma)[t];
    float4 bv = ((const float4*)beta)[t];
    __half2 h0 = __floats2half2_rn((xv.x - mean) * rs * gv.x + bv.x,
                                   (xv.y - mean) * rs * gv.y + bv.y);
    __half2 h1 = __floats2half2_rn((xv.z - mean) * rs * gv.z + bv.z,
                                   (xv.w - mean) * rs * gv.w + bv.w);
    uint2 pkd; pkd.x = h2u(h0); pkd.y = h2u(h1);
    *(uint2*)(out + row * Dd + t*4) = pkd;
}

// ============================================================================
// cp.async double-buffered FP16 GEMM: C = act(A@B + bias) (+res)
// A [M,K] fp16 row-major; B packed u32 [K/2][N]. BM=128 BN=128 BK=32, 256 thr.
// 2-stage pipeline; warps 2m x 4n; mma m16n8k16; ldmatrix.x4 for A fragments.
// smem: sA u32 [128][20], sB u32 [16][136].
// ============================================================================
#define G2_SMEM ((2*128*20 + 2*16*136)*4)
template<int ACT, bool HAS_RES, bool OUT_HALF>
__global__ __launch_bounds__(256, 2) void gemm2(
    const __half* __restrict__ A, const uint32_t* __restrict__ Bm,
    const float* __restrict__ bias, const float* __restrict__ res,
    void* __restrict__ Cv, int M, int N, int K)
{
    extern __shared__ uint32_t smem_[];
    uint32_t* sA = smem_;               // [2][128*20]
    uint32_t* sB = smem_ + 2*128*20;    // [2][16*136]
    int tid = threadIdx.x;
    int lane = tid & 31, wid = tid >> 5;
    int g = lane >> 2, tig = lane & 3;
    int wm0 = (wid >> 2) * 64;
    int wn0 = (wid & 3) * 32;
    int row0 = blockIdx.y * 128;
    int col0 = blockIdx.x * 128;
    const __half* Ab = A + (size_t)row0 * K;
    const uint32_t* Bp = Bm + col0;

    // ldmatrix lane address components
    int lr = lane & 7, sel = lane >> 3;
    int a_row_off = ((sel & 1) << 3) + lr;   // row within 16-row tile
    int a_col_off = (sel >> 1) << 2;         // u32 col (0 or 4)

    float acc[4][4][4] = {};

    int nk = K >> 5;
    #define COPY_STAGE(buf, k0) do { \
        uint32_t* dA = sA + (buf)*128*20; \
        uint32_t* dB = sB + (buf)*16*136; \
        _Pragma("unroll") \
        for (int i_ = 0; i_ < 2; i_++) { \
            int f = tid + i_*256; \
            int rr = f >> 2, cq = f & 3; \
            CP16(s2u(dA + rr*20 + cq*4), Ab + (size_t)rr * K + (k0) + cq*8); \
        } \
        _Pragma("unroll") \
        for (int i_ = 0; i_ < 2; i_++) { \
            int f = tid + i_*256; \
            int rr = f >> 5, cq = f & 31; \
            CP16(s2u(dB + rr*136 + cq*4), Bp + (size_t)(((k0)>>1) + rr) * N + cq*4); \
        } \
    } while (0)

    COPY_STAGE(0, 0);
    CP_COMMIT();
    for (int it = 0; it < nk; it++) {
        if (it + 1 < nk) {
            COPY_STAGE((it+1)&1, (it+1)<<5);
            CP_COMMIT();
            CP_WAIT1();
        } else {
            CP_WAIT0();
        }
        __syncthreads();
        uint32_t* cA = sA + (it&1)*128*20;
        uint32_t* cB = sB + (it&1)*16*136;
        #pragma unroll
        for (int kk = 0; kk < 32; kk += 16) {
            int kc = kk >> 1;
            uint32_t af[4][4], bf[4][2];
            #pragma unroll
            for (int i = 0; i < 4; i++) {
                uint32_t addr = s2u(cA + (wm0 + i*16 + a_row_off)*20 + kc + a_col_off);
                LDSM4(af[i][0], af[i][1], af[i][2], af[i][3], addr);
            }
            #pragma unroll
            for (int j = 0; j < 4; j++) {
                int nn = wn0 + j*8 + g;
                bf[j][0] = cB[(kc + tig)*136 + nn];
                bf[j][1] = cB[(kc + tig + 4)*136 + nn];
            }
            #pragma unroll
            for (int i = 0; i < 4; i++)
                #pragma unroll
                for (int j = 0; j < 4; j++)
                    MMA_F16(acc[i][j], af[i], bf[j]);
        }
        __syncthreads();
    }
    #undef COPY_STAGE

    // epilogue
    #pragma unroll
    for (int i = 0; i < 4; i++) {
        #pragma unroll
        for (int j = 0; j < 4; j++) {
            int col = col0 + wn0 + j*8 + tig*2;
            #pragma unroll
            for (int h = 0; h < 2; h++) {
                int row = row0 + wm0 + i*16 + g + h*8;
                float v0 = acc[i][j][h*2 + 0] + bias[col];
                float v1 = acc[i][j][h*2 + 1] + bias[col + 1];
                if (ACT == 1) {
                    v0 = 0.5f * v0 * (1.0f + erff(v0 * 0.70710678118654752f));
                    v1 = 0.5f * v1 * (1.0f + erff(v1 * 0.70710678118654752f));
                }
                if (HAS_RES) {
                    float2 rr = *(const float2*)(res + (size_t)row * N + col);
                    v0 += rr.x; v1 += rr.y;
                }
                if (OUT_HALF) {
                    *(uint32_t*)((__half*)Cv + (size_t)row * N + col) =
                        h2u(__floats2half2_rn(v0, v1));
                } else {
                    *(float2*)((float*)Cv + (size_t)row * N + col) = make_float2(v0, v1);
                }
            }
        }
    }
}

// ============================================================================
// Fused flash attention, fp16 operands, soft-cap with fixed reference 2:
//   p = 2^(min(tanh(s/50)*50*log2e - 2*log2e, 11.5)); ref cancels in l-norm.
// q/k/v live in fused qkv tensor with row stride QKVS.
// BM=128, BS=64. 256 thr, warps 2m x 4n. ldmatrix for Q/P fragments.
// smem u32: sQ [128][36], sK [64][36], sV packed [32][72], sP packed [128][36].
// ============================================================================
#define FA_SMEM ((128*36 + 64*36 + 32*72 + 128*36 + 4*128)*4)
__global__ __launch_bounds__(256, 2) void flash_attn(
    const __half* __restrict__ qkv, __half* __restrict__ ctx)
{
    extern __shared__ uint32_t smem_[];
    uint32_t* sQ = smem_;                 // [128][36]
    uint32_t* sK = smem_ + 128*36;        // [64][36]
    uint32_t* sV = sK + 64*36;            // [32][72] packed s-pairs
    uint32_t* sP = sV + 32*72;            // [128][36] packed s-pairs
    float*    sL = (float*)(sP + 128*36); // [4][128]
    int tid = threadIdx.x;
    int lane = tid & 31, wid = tid >> 5;
    int g = lane >> 2, tig = lane & 3;
    int wm0 = (wid >> 2) * 64;            // 2 warps on m
    int wn0 = (wid & 3) * 16;             // 4 warps on n (16 cols each)
    int row0 = blockIdx.x * 128;
    int z = blockIdx.y;
    int b = z >> 4, n = z & 15;
    const __half* Qb = qkv + ((size_t)b*Tt + row0) * QKVS + n*HDh;
    const __half* Kb = qkv + (size_t)b*Tt*QKVS + Dd   + n*HDh;
    const __half* Vb = qkv + (size_t)b*Tt*QKVS + 2*Dd + n*HDh;

    int lr = lane & 7, sel = lane >> 3;
    int a_row_off = ((sel & 1) << 3) + lr;
    int a_col_off = (sel >> 1) << 2;

    // load Q tile (128 x 64 halfs, 8 x 16B chunks per row)
    #pragma unroll
    for (int i = 0; i < 4; i++) {
        int f = tid + i*256;
        int rr = f >> 3, cq = f & 7;
        CP16(s2u(sQ + rr*36 + cq*4), Qb + (size_t)rr * QKVS + cq*8);
    }
    CP_COMMIT();

    const __half2 c_scale = __floats2half2_rn(72.134752f, 72.134752f);   // 50*log2e
    const __half2 c_off   = __floats2half2_rn(-2.8853901f, -2.8853901f); // -2*log2e
    const __half2 c_clamp = __floats2half2_rn(11.5f, 11.5f);

    float l[8] = {0,0,0,0,0,0,0,0};
    float accO[4][2][4] = {};

    for (int s0 = 0; s0 < Tt; s0 += 64) {
        // K tile via cp.async (64 x 64 halfs)
        #pragma unroll
        for (int i = 0; i < 2; i++) {
            int f = tid + i*256;
            int rr = f >> 3, cq = f & 7;
            CP16(s2u(sK + rr*36 + cq*4), Kb + (size_t)(s0 + rr) * QKVS + cq*8);
        }
        CP_COMMIT();
        // V tile: load + transpose-pack into s-pair half2s
        #pragma unroll
        for (int i = 0; i < 2; i++) {
            int u = tid + i*256;
            int r = u >> 4, hq = u & 15;
            uint2 a = *(const uint2*)(Vb + (size_t)(s0 + 2*r    ) * QKVS + hq*4);
            uint2 bb= *(const uint2*)(Vb + (size_t)(s0 + 2*r + 1) * QKVS + hq*4);
            uint4 o;
            o.x = (a.x & 0xFFFFu) | (bb.x << 16);
            o.y = (a.x >> 16)     | (bb.x & 0xFFFF0000u);
            o.z = (a.y & 0xFFFFu) | (bb.y << 16);
            o.w = (a.y >> 16)     | (bb.y & 0xFFFF0000u);
            *(uint4*)(sV + r*72 + hq*4) = o;
        }
        CP_WAIT0();
        __syncthreads();

        // S = Q @ K^T  (128 x 64)
        float accS[4][2][4] = {};
        #pragma unroll
        for (int kk = 0; kk < 64; kk += 16) {
            int kc = kk >> 1;
            uint32_t af[4][4], bf[2][2];
            #pragma unroll
            for (int i = 0; i < 4; i++) {
                uint32_t addr = s2u(sQ + (wm0 + i*16 + a_row_off)*36 + kc + a_col_off);
                LDSM4(af[i][0], af[i][1], af[i][2], af[i][3], addr);
            }
            #pragma unroll
            for (int j = 0; j < 2; j++) {
                int nn = wn0 + j*8 + g;
                bf[j][0] = sK[nn*36 + kc + tig];
                bf[j][1] = sK[nn*36 + kc + tig + 4];
            }
            #pragma unroll
            for (int i = 0; i < 4; i++)
                #pragma unroll
                for (int j = 0; j < 2; j++)
                    MMA_F16(accS[i][j], af[i], bf[j]);
        }

        // softcap + exp2 (fixed ref 2) in f16x2 + partial row-sum + store P
        #pragma unroll
        for (int i = 0; i < 4; i++) {
            #pragma unroll
            for (int h = 0; h < 2; h++) {
                int m = wm0 + i*16 + g + h*8;
                float ps = 0.0f;
                #pragma unroll
                for (int j = 0; j < 2; j++) {
                    __half2 x = __floats2half2_rn(accS[i][j][h*2 + 0] * 0.02f,
                                                  accS[i][j][h*2 + 1] * 0.02f);
                    uint32_t tu;
                    asm("tanh.approx.f16x2 %0, %1;" : "=r"(tu) : "r"(h2u(x)));
                    __half2 w = __hfma2(*(__half2*)&tu, c_scale, c_off);
                    w = __hmin2(w, c_clamp);
                    uint32_t pu;
                    asm("ex2.approx.f16x2 %0, %1;" : "=r"(pu) : "r"(h2u(w)));
                    sP[m*36 + (wid&3)*8 + j*4 + tig] = pu;
                    float2 pf = __half22float2(*(__half2*)&pu);
                    ps += pf.x + pf.y;
                }
                ps += __shfl_xor_sync(0xffffffffu, ps, 1);
                ps += __shfl_xor_sync(0xffffffffu, ps, 2);
                l[i*2 + h] += ps;     // this warp's 16-column share
            }
        }
        __syncthreads();

        // O += P @ V  (128 x 64, k = 64)
        #pragma unroll
        for (int kk = 0; kk < 64; kk += 16) {
            int kc = kk >> 1;
            uint32_t af[4][4], bf[2][2];
            #pragma unroll
            for (int i = 0; i < 4; i++) {
                uint32_t addr = s2u(sP + (wm0 + i*16 + a_row_off)*36 + kc + a_col_off);
                LDSM4(af[i][0], af[i][1], af[i][2], af[i][3], addr);
            }
            #pragma unroll
            for (int j = 0; j < 2; j++) {
                int nn = wn0 + j*8 + g;
                bf[j][0] = sV[(kc + tig)*72 + nn];
                bf[j][1] = sV[(kc + tig + 4)*72 + nn];
            }
            #pragma unroll
            for (int i = 0; i < 4; i++)
                #pragma unroll
                for (int j = 0; j < 2; j++)
                    MMA_F16(accO[i][j], af[i], bf[j]);
        }
        __syncthreads();
    }

    // combine per-warp l partials across the 4 n-warps
    #pragma unroll
    for (int i = 0; i < 4; i++)
        #pragma unroll
        for (int h = 0; h < 2; h++)
            if (tig == 0)
                sL[(wid & 3)*128 + wm0 + i*16 + h*8 + g] = l[i*2 + h];
    __syncthreads();

    // normalize by total l and store ctx (fp16; feeds out-proj GEMM)
    __half* Cb = ctx + ((size_t)b*Tt + row0) * Dd + n*HDh;
    #pragma unroll
    for (int i = 0; i < 4; i++) {
        #pragma unroll
        for (int h = 0; h < 2; h++) {
            int m = wm0 + i*16 + g + h*8;
            float ltot = sL[m] + sL[128 + m] + sL[256 + m] + sL[384 + m];
            float linv = __fdividef(1.0f, ltot);
            #pragma unroll
            for (int j = 0; j < 2; j++) {
                int col = wn0 + j*8 + tig*2;
                float v0 = accO[i][j][h*2 + 0] * linv;
                float v1 = accO[i][j][h*2 + 1] * linv;
                *(uint32_t*)(Cb + (size_t)m * Dd + col) =
                    h2u(__floats2half2_rn(v0, v1));
            }
        }
    }
}

// -------- launch --------
extern "C" void kernel_launch(void* const* d_in, const int* in_sizes, int n_in,
                              void* d_out, int out_size)
{
    const float* inputs = (const float*)d_in[0];
    const float* ln1_g  = (const float*)d_in[1];
    const float* ln1_b  = (const float*)d_in[2];
    const float* wq     = (const float*)d_in[3];
    const float* bq     = (const float*)d_in[4];
    const float* wk     = (const float*)d_in[5];
    const float* bk     = (const float*)d_in[6];
    const float* wv     = (const float*)d_in[7];
    const float* bv     = (const float*)d_in[8];
    const float* wo     = (const float*)d_in[9];
    const float* bo     = (const float*)d_in[10];
    const float* ln2_g  = (const float*)d_in[11];
    const float* ln2_b  = (const float*)d_in[12];
    const float* w1     = (const float*)d_in[13];
    const float* b1     = (const float*)d_in[14];
    const float* w2     = (const float*)d_in[15];
    const float* b2     = (const float*)d_in[16];
    float* out = (float*)d_out;

    __half *xln, *qkv, *ctx, *yln, *h1;
    float *xres, *bqkv;
    uint32_t *wqkv_p, *wo_p, *w1_p, *w2_p;
    cudaGetSymbolAddress((void**)&xln,    g_xln);
    cudaGetSymbolAddress((void**)&qkv,    g_qkv);
    cudaGetSymbolAddress((void**)&ctx,    g_ctx);
    cudaGetSymbolAddress((void**)&xres,   g_xres);
    cudaGetSymbolAddress((void**)&yln,    g_yln);
    cudaGetSymbolAddress((void**)&h1,     g_h1);
    cudaGetSymbolAddress((void**)&wqkv_p, g_wqkv_p);
    cudaGetSymbolAddress((void**)&bqkv,   g_bqkv);
    cudaGetSymbolAddress((void**)&wo_p,   g_wo_p);
    cudaGetSymbolAddress((void**)&w1_p,   g_w1_p);
    cudaGetSymbolAddress((void**)&w2_p,   g_w2_p);

    // opt-in dynamic smem
    cudaFuncSetAttribute((const void*)gemm2<0,false,true>, cudaFuncAttributeMaxDynamicSharedMemorySize, G2_SMEM);
    cudaFuncSetAttribute((const void*)gemm2<0,true,false>, cudaFuncAttributeMaxDynamicSharedMemorySize, G2_SMEM);
    cudaFuncSetAttribute((const void*)gemm2<1,false,true>, cudaFuncAttributeMaxDynamicSharedMemorySize, G2_SMEM);
    cudaFuncSetAttribute((const void*)flash_attn, cudaFuncAttributeMaxDynamicSharedMemorySize, FA_SMEM);

    // 0) pack weights
    pack_qkv_w_kernel<<<(Dd/2*QKVS + 255)/256, 256>>>(wq, wk, wv, wqkv_p);
    pack_qkv_b_kernel<<<(QKVS + 255)/256, 256>>>(bq, bk, bv, bqkv);
    {
        int tot = Dd/2*Dd;
        pack_w_kernel<<<(tot+255)/256, 256>>>(wo, wo_p, Dd, tot);
        int tot1 = Dd/2*FFd;
        pack_w_kernel<<<(tot1+255)/256, 256>>>(w1, w1_p, FFd, tot1);
        int tot2 = FFd/2*Dd;
        pack_w_kernel<<<(tot2+255)/256, 256>>>(w2, w2_p, Dd, tot2);
    }

    // 1) LN1 (fp16 out)
    ln_kernel<<<MM, 256>>>(inputs, ln1_g, ln1_b, xln);

    // 2) fused QKV projection -> qkv [M][3072]
    dim3 gQKV(QKVS/128, MM/128);
    gemm2<0,false,true><<<gQKV, 256, G2_SMEM>>>(xln, wqkv_p, bqkv, nullptr, qkv, MM, QKVS, Dd);

    // 3) fused attention -> ctx
    dim3 gA(Tt/128, Bb*NHh);
    flash_attn<<<gA, 256, FA_SMEM>>>(qkv, ctx);

    // 4) out-proj + residual(inputs) -> xres (fp32)
    dim3 gD(Dd/128, MM/128);
    gemm2<0,true,false><<<gD, 256, G2_SMEM>>>(ctx, wo_p, bo, inputs, xres, MM, Dd, Dd);

    // 5) LN2
    ln_kernel<<<MM, 256>>>(xres, ln2_g, ln2_b, yln);

    // 6) MLP up + exact GELU -> h1 (fp16)
    dim3 gF(FFd/128, MM/128);
    gemm2<1,false,true><<<gF, 256, G2_SMEM>>>(yln, w1_p, b1, nullptr, h1, MM, FFd, Dd);

    // 7) MLP down + bias + residual(xres) -> out (fp32)
    gemm2<0,true,false><<<gD, 256, G2_SMEM>>>(h1, w2_p, b2, xres, out, MM, Dd, FFd);
}

// round 9
// speedup vs baseline: 6.6090x; 1.0322x over previous
#include <cuda_runtime.h>
#include <cuda_fp16.h>
#include <math.h>
#include <stdint.h>

// Problem dims
#define Bb 4
#define Tt 2048
#define Dd 1024
#define NHh 16
#define HDh 64
#define FFd 4096
#define MM (Bb*Tt)          // 8192 rows
#define QKVS 3072           // fused qkv row stride

// -------- scratch (device globals; no allocs allowed) --------
__device__ __half g_xln[(size_t)MM*Dd];
__device__ __half g_qkv[(size_t)MM*QKVS];
__device__ uint32_t g_vp[(size_t)MM*Dd/2];   // V packed: [b][n][spair][64] u32
__device__ __half g_ctx[(size_t)MM*Dd];
__device__ float  g_xres[(size_t)MM*Dd];
__device__ __half g_yln[(size_t)MM*Dd];
__device__ __half g_h1 [(size_t)MM*FFd];
// packed fp16 weights: u32 [K/2][N], u32 = half2(w[2r][n], w[2r+1][n])
__device__ uint32_t g_wqkv_p[(size_t)Dd/2*QKVS];
__device__ float    g_bqkv  [QKVS];
__device__ uint32_t g_wo_p[(size_t)Dd/2*Dd];
__device__ uint32_t g_w1_p[(size_t)Dd/2*FFd];
__device__ uint32_t g_w2_p[(size_t)FFd/2*Dd];

// -------- helpers --------
#define MMA_F16(c, a, b) \
    asm volatile("mma.sync.aligned.m16n8k16.row.col.f32.f16.f16.f32 " \
                 "{%0,%1,%2,%3},{%4,%5,%6,%7},{%8,%9},{%0,%1,%2,%3};" \
                 : "+f"((c)[0]), "+f"((c)[1]), "+f"((c)[2]), "+f"((c)[3]) \
                 : "r"((a)[0]), "r"((a)[1]), "r"((a)[2]), "r"((a)[3]), \
                   "r"((b)[0]), "r"((b)[1]))

#define LDSM4(r0, r1, r2, r3, addr) \
    asm volatile("ldmatrix.sync.aligned.m8n8.x4.shared.b16 {%0,%1,%2,%3}, [%4];" \
                 : "=r"(r0), "=r"(r1), "=r"(r2), "=r"(r3) : "r"(addr))

#define CP16(dst_u32, src_ptr) \
    asm volatile("cp.async.cg.shared.global [%0], [%1], 16;" :: "r"(dst_u32), "l"(src_ptr))
#define CP_COMMIT() asm volatile("cp.async.commit_group;")
#define CP_WAIT0()  asm volatile("cp.async.wait_group 0;")
#define CP_WAIT1()  asm volatile("cp.async.wait_group 1;")

__device__ __forceinline__ uint32_t s2u(const void* p) {
    return (uint32_t)__cvta_generic_to_shared(p);
}
__device__ __forceinline__ uint32_t h2u(__half2 h) { return *(uint32_t*)&h; }

__device__ __forceinline__ float block_reduce_sum(float v, float* sh) {
    int t = threadIdx.x;
    #pragma unroll
    for (int o = 16; o > 0; o >>= 1) v += __shfl_down_sync(0xffffffffu, v, o);
    if ((t & 31) == 0) sh[t >> 5] = v;
    __syncthreads();
    if (t < 32) {
        float w = (t < 8) ? sh[t] : 0.0f;
        #pragma unroll
        for (int o = 4; o > 0; o >>= 1) w += __shfl_down_sync(0xffffffffu, w, o);
        if (t == 0) sh[0] = w;
    }
    __syncthreads();
    float r = sh[0];
    __syncthreads();
    return r;
}

// -------- weight pack: fp32 [K][N] -> u32 [K/2][N] (half2 along k) --------
__global__ void pack_w_kernel(const float* __restrict__ in, uint32_t* __restrict__ out,
                              int N, int total)
{
    int idx = blockIdx.x * 256 + threadIdx.x;
    if (idx < total) {
        int r = idx / N, n = idx - r * N;
        float a = in[(size_t)(2*r) * N + n];
        float b = in[(size_t)(2*r+1) * N + n];
        out[idx] = h2u(__floats2half2_rn(a, b));
    }
}

// -------- fused qkv weight pack (wq pre-scaled 0.125) --------
__global__ void pack_qkv_w_kernel(const float* __restrict__ wq, const float* __restrict__ wk,
                                  const float* __restrict__ wv, uint32_t* __restrict__ out)
{
    int idx = blockIdx.x * 256 + threadIdx.x;
    if (idx < Dd/2*QKVS) {
        int r = idx / QKVS, n = idx - r * QKVS;
        const float* src; float sc; int nn;
        if (n < Dd)        { src = wq; sc = 0.125f; nn = n; }
        else if (n < 2*Dd) { src = wk; sc = 1.0f;   nn = n - Dd; }
        else               { src = wv; sc = 1.0f;   nn = n - 2*Dd; }
        float a = src[(size_t)(2*r) * Dd + nn] * sc;
        float b = src[(size_t)(2*r+1) * Dd + nn] * sc;
        out[idx] = h2u(__floats2half2_rn(a, b));
    }
}

__global__ void pack_qkv_b_kernel(const float* __restrict__ bq, const float* __restrict__ bk,
                                  const float* __restrict__ bv, float* __restrict__ out)
{
    int n = blockIdx.x * 256 + threadIdx.x;
    if (n < QKVS) {
        if (n < Dd)        out[n] = bq[n] * 0.125f;
        else if (n < 2*Dd) out[n] = bk[n - Dd];
        else               out[n] = bv[n - 2*Dd];
    }
}

// -------- V repack: qkv V-part -> u32 [b][n][spair][64] (s-pair half2) --------
__global__ void repack_v_kernel(const __half* __restrict__ qkv, uint32_t* __restrict__ vp)
{
    size_t idx = (size_t)blockIdx.x * 256 + threadIdx.x;   // MM*Dd/2 total
    int h = idx & 63;
    size_t r1 = idx >> 6;
    int spair = (int)(r1 & (Tt/2 - 1));
    size_t r2 = r1 >> 10;
    int n = (int)(r2 & (NHh - 1));
    int b = (int)(r2 >> 4);
    const __half* src = qkv + ((size_t)b*Tt + 2*spair) * QKVS + 2*Dd + n*HDh + h;
    vp[idx] = h2u(__halves2half2(src[0], src[QKVS]));
}

// -------- LayerNorm: one block (256 thr) per row of 1024; fp16 out --------
__global__ void ln_kernel(const float* __restrict__ x, const float* __restrict__ gamma,
                          const float* __restrict__ beta, __half* __restrict__ out)
{
    __shared__ float sh[32];
    size_t row = blockIdx.x;
    const float4* xr = (const float4*)(x + row * Dd);
    int t = threadIdx.x;
    float4 xv = xr[t];
    float s  = xv.x + xv.y + xv.z + xv.w;
    float s2 = xv.x*xv.x + xv.y*xv.y + xv.z*xv.z + xv.w*xv.w;
    float S  = block_reduce_sum(s,  sh);
    float S2 = block_reduce_sum(s2, sh);
    float mean = S * (1.0f / Dd);
    float var  = S2 * (1.0f / Dd) - mean * mean;
    float rs   = rsqrtf(var + 1e-6f);
    float4 gv = ((const float4*)gamma)[t];
    float4 bv = ((const float4*)beta)[t];
    __half2 h0 = __floats2half2_rn((xv.x - mean) * rs * gv.x + bv.x,
                                   (xv.y - mean) * rs * gv.y + bv.y);
    __half2 h1 = __floats2half2_rn((xv.z - mean) * rs * gv.z + bv.z,
                                   (xv.w - mean) * rs * gv.w + bv.w);
    uint2 pkd; pkd.x = h2u(h0); pkd.y = h2u(h1);
    *(uint2*)(out + row * Dd + t*4) = pkd;
}

// ============================================================================
// cp.async double-buffered FP16 GEMM: C = act(A@B + bias) (+res)
// A [M,K] fp16 row-major; B packed u32 [K/2][N]. BM=128 BN=128 BK=64, 256 thr.
// 2-stage pipeline; warps 2m x 4n; mma m16n8k16; ldmatrix.x4 for A fragments.
// smem: sA u32 [128][36], sB u32 [32][136] (x2 stages).
// ============================================================================
#define G2_SMEM ((2*128*36 + 2*32*136)*4)
template<int ACT, bool HAS_RES, bool OUT_HALF>
__global__ __launch_bounds__(256, 2) void gemm2(
    const __half* __restrict__ A, const uint32_t* __restrict__ Bm,
    const float* __restrict__ bias, const float* __restrict__ res,
    void* __restrict__ Cv, int M, int N, int K)
{
    extern __shared__ uint32_t smem_[];
    uint32_t* sA = smem_;               // [2][128*36]
    uint32_t* sB = smem_ + 2*128*36;    // [2][32*136]
    int tid = threadIdx.x;
    int lane = tid & 31, wid = tid >> 5;
    int g = lane >> 2, tig = lane & 3;
    int wm0 = (wid >> 2) * 64;
    int wn0 = (wid & 3) * 32;
    int row0 = blockIdx.y * 128;
    int col0 = blockIdx.x * 128;
    const __half* Ab = A + (size_t)row0 * K;
    const uint32_t* Bp = Bm + col0;

    int lr = lane & 7, sel = lane >> 3;
    int a_row_off = ((sel & 1) << 3) + lr;
    int a_col_off = (sel >> 1) << 2;

    float acc[4][4][4] = {};

    int nk = K >> 6;
    #define COPY_STAGE(buf, k0) do { \
        uint32_t* dA = sA + (buf)*128*36; \
        uint32_t* dB = sB + (buf)*32*136; \
        _Pragma("unroll") \
        for (int i_ = 0; i_ < 4; i_++) { \
            int f = tid + i_*256; \
            int rr = f >> 3, cq = f & 7; \
            CP16(s2u(dA + rr*36 + cq*4), Ab + (size_t)rr * K + (k0) + cq*8); \
        } \
        _Pragma("unroll") \
        for (int i_ = 0; i_ < 4; i_++) { \
            int f = tid + i_*256; \
            int rr = f >> 5, cq = f & 31; \
            CP16(s2u(dB + rr*136 + cq*4), Bp + (size_t)(((k0)>>1) + rr) * N + cq*4); \
        } \
    } while (0)

    COPY_STAGE(0, 0);
    CP_COMMIT();
    for (int it = 0; it < nk; it++) {
        if (it + 1 < nk) {
            COPY_STAGE((it+1)&1, (it+1)<<6);
            CP_COMMIT();
            CP_WAIT1();
        } else {
            CP_WAIT0();
        }
        __syncthreads();
        uint32_t* cA = sA + (it&1)*128*36;
        uint32_t* cB = sB + (it&1)*32*136;
        #pragma unroll
        for (int ks = 0; ks < 4; ks++) {
            int kc = ks * 8;
            uint32_t af[4][4], bf[4][2];
            #pragma unroll
            for (int i = 0; i < 4; i++) {
                uint32_t addr = s2u(cA + (wm0 + i*16 + a_row_off)*36 + kc + a_col_off);
                LDSM4(af[i][0], af[i][1], af[i][2], af[i][3], addr);
            }
            #pragma unroll
            for (int j = 0; j < 4; j++) {
                int nn = wn0 + j*8 + g;
                bf[j][0] = cB[(kc + tig)*136 + nn];
                bf[j][1] = cB[(kc + tig + 4)*136 + nn];
            }
            #pragma unroll
            for (int i = 0; i < 4; i++)
                #pragma unroll
                for (int j = 0; j < 4; j++)
                    MMA_F16(acc[i][j], af[i], bf[j]);
        }
        __syncthreads();
    }
    #undef COPY_STAGE

    // epilogue
    #pragma unroll
    for (int i = 0; i < 4; i++) {
        #pragma unroll
        for (int j = 0; j < 4; j++) {
            int col = col0 + wn0 + j*8 + tig*2;
            #pragma unroll
            for (int h = 0; h < 2; h++) {
                int row = row0 + wm0 + i*16 + g + h*8;
                float v0 = acc[i][j][h*2 + 0] + bias[col];
                float v1 = acc[i][j][h*2 + 1] + bias[col + 1];
                if (ACT == 1) {
                    v0 = 0.5f * v0 * (1.0f + erff(v0 * 0.70710678118654752f));
                    v1 = 0.5f * v1 * (1.0f + erff(v1 * 0.70710678118654752f));
                }
                if (HAS_RES) {
                    float2 rr = *(const float2*)(res + (size_t)row * N + col);
                    v0 += rr.x; v1 += rr.y;
                }
                if (OUT_HALF) {
                    *(uint32_t*)((__half*)Cv + (size_t)row * N + col) =
                        h2u(__floats2half2_rn(v0, v1));
                } else {
                    *(float2*)((float*)Cv + (size_t)row * N + col) = make_float2(v0, v1);
                }
            }
        }
    }
}

// ============================================================================
// Fused flash attention, fp16, soft-cap fixed reference 2:
//   p = 2^(min(tanh(s/50)*50*log2e - 2*log2e, 11.5)); ref cancels in l-norm.
// Q/K from fused qkv (stride QKVS); V pre-packed s-pairs from g_vp.
// BM=128, BS=64. 256 thr, warps 2m x 4n. Double-buffered K/V via cp.async.
// smem u32: sQ [128][36], sK [2][64][36], sV [2][32][72], sP [128][36].
// ============================================================================
#define FA_SMEM ((128*36 + 2*64*36 + 2*32*72 + 128*36 + 4*128)*4)
__global__ __launch_bounds__(256, 2) void flash_attn(
    const __half* __restrict__ qkv, const uint32_t* __restrict__ vp,
    __half* __restrict__ ctx)
{
    extern __shared__ uint32_t smem_[];
    uint32_t* sQ = smem_;                  // [128][36]
    uint32_t* sK = smem_ + 128*36;         // [2][64][36]
    uint32_t* sV = sK + 2*64*36;           // [2][32][72]
    uint32_t* sP = sV + 2*32*72;           // [128][36]
    float*    sL = (float*)(sP + 128*36);  // [4][128]
    int tid = threadIdx.x;
    int lane = tid & 31, wid = tid >> 5;
    int g = lane >> 2, tig = lane & 3;
    int wm0 = (wid >> 2) * 64;
    int wn0 = (wid & 3) * 16;
    int row0 = blockIdx.x * 128;
    int z = blockIdx.y;
    int b = z >> 4, n = z & 15;
    const __half* Qb = qkv + ((size_t)b*Tt + row0) * QKVS + n*HDh;
    const __half* Kb = qkv + (size_t)b*Tt*QKVS + Dd + n*HDh;
    const uint32_t* Vp = vp + (size_t)(b*NHh + n) * (Tt/2) * HDh;

    int lr = lane & 7, sel = lane >> 3;
    int a_row_off = ((sel & 1) << 3) + lr;
    int a_col_off = (sel >> 1) << 2;

    #define LOAD_KV(buf, s0) do { \
        uint32_t* dK = sK + (buf)*64*36; \
        uint32_t* dV = sV + (buf)*32*72; \
        _Pragma("unroll") \
        for (int i_ = 0; i_ < 2; i_++) { \
            int f = tid + i_*256; \
            int rr = f >> 3, cq = f & 7; \
            CP16(s2u(dK + rr*36 + cq*4), Kb + (size_t)((s0) + rr) * QKVS + cq*8); \
        } \
        _Pragma("unroll") \
        for (int i_ = 0; i_ < 2; i_++) { \
            int f = tid + i_*256; \
            int rr = f >> 4, hq = f & 15; \
            CP16(s2u(dV + rr*72 + hq*4), Vp + ((size_t)((s0)>>1) + rr) * HDh + hq*4); \
        } \
    } while (0)

    // load Q tile (group), then KV stage 0 (group)
    #pragma unroll
    for (int i = 0; i < 4; i++) {
        int f = tid + i*256;
        int rr = f >> 3, cq = f & 7;
        CP16(s2u(sQ + rr*36 + cq*4), Qb + (size_t)rr * QKVS + cq*8);
    }
    CP_COMMIT();
    LOAD_KV(0, 0);
    CP_COMMIT();

    const __half2 c_scale = __floats2half2_rn(72.134752f, 72.134752f);
    const __half2 c_off   = __floats2half2_rn(-2.8853901f, -2.8853901f);
    const __half2 c_clamp = __floats2half2_rn(11.5f, 11.5f);

    float l[8] = {0,0,0,0,0,0,0,0};
    float accO[4][2][4] = {};

    const int NT = Tt / 64;
    for (int t = 0; t < NT; t++) {
        CP_WAIT0();          // current K/V group complete (prefetch not yet issued)
        __syncthreads();     // K/V visible; all warps past prev P@V (sP/buffers reusable)
        if (t + 1 < NT) {
            LOAD_KV((t+1)&1, (t+1)*64);   // overlaps with this tile's compute
            CP_COMMIT();
        }
        uint32_t* cK = sK + (t&1)*64*36;
        uint32_t* cV = sV + (t&1)*32*72;

        // S = Q @ K^T  (128 x 64)
        float accS[4][2][4] = {};
        #pragma unroll
        for (int kk = 0; kk < 64; kk += 16) {
            int kc = kk >> 1;
            uint32_t af[4][4], bf[2][2];
            #pragma unroll
            for (int i = 0; i < 4; i++) {
                uint32_t addr = s2u(sQ + (wm0 + i*16 + a_row_off)*36 + kc + a_col_off);
                LDSM4(af[i][0], af[i][1], af[i][2], af[i][3], addr);
            }
            #pragma unroll
            for (int j = 0; j < 2; j++) {
                int nn = wn0 + j*8 + g;
                bf[j][0] = cK[nn*36 + kc + tig];
                bf[j][1] = cK[nn*36 + kc + tig + 4];
            }
            #pragma unroll
            for (int i = 0; i < 4; i++)
                #pragma unroll
                for (int j = 0; j < 2; j++)
                    MMA_F16(accS[i][j], af[i], bf[j]);
        }

        // softcap + exp2 (fixed ref 2) in f16x2 + partial row-sum + store P
        #pragma unroll
        for (int i = 0; i < 4; i++) {
            #pragma unroll
            for (int h = 0; h < 2; h++) {
                int m = wm0 + i*16 + g + h*8;
                float ps = 0.0f;
                #pragma unroll
                for (int j = 0; j < 2; j++) {
                    __half2 x = __floats2half2_rn(accS[i][j][h*2 + 0] * 0.02f,
                                                  accS[i][j][h*2 + 1] * 0.02f);
                    uint32_t tu;
                    asm("tanh.approx.f16x2 %0, %1;" : "=r"(tu) : "r"(h2u(x)));
                    __half2 w = __hfma2(*(__half2*)&tu, c_scale, c_off);
                    w = __hmin2(w, c_clamp);
                    uint32_t pu;
                    asm("ex2.approx.f16x2 %0, %1;" : "=r"(pu) : "r"(h2u(w)));
                    sP[m*36 + (wid&3)*8 + j*4 + tig] = pu;
                    float2 pf = __half22float2(*(__half2*)&pu);
                    ps += pf.x + pf.y;
                }
                ps += __shfl_xor_sync(0xffffffffu, ps, 1);
                ps += __shfl_xor_sync(0xffffffffu, ps, 2);
                l[i*2 + h] += ps;
            }
        }
        __syncthreads();

        // O += P @ V  (128 x 64, k = 64)
        #pragma unroll
        for (int kk = 0; kk < 64; kk += 16) {
            int kc = kk >> 1;
            uint32_t af[4][4], bf[2][2];
            #pragma unroll
            for (int i = 0; i < 4; i++) {
                uint32_t addr = s2u(sP + (wm0 + i*16 + a_row_off)*36 + kc + a_col_off);
                LDSM4(af[i][0], af[i][1], af[i][2], af[i][3], addr);
            }
            #pragma unroll
            for (int j = 0; j < 2; j++) {
                int nn = wn0 + j*8 + g;
                bf[j][0] = cV[(kc + tig)*72 + nn];
                bf[j][1] = cV[(kc + tig + 4)*72 + nn];
            }
            #pragma unroll
            for (int i = 0; i < 4; i++)
                #pragma unroll
                for (int j = 0; j < 2; j++)
                    MMA_F16(accO[i][j], af[i], bf[j]);
        }
    }
    #undef LOAD_KV

    __syncthreads();
    // combine per-warp l partials across the 4 n-warps
    #pragma unroll
    for (int i = 0; i < 4; i++)
        #pragma unroll
        for (int h = 0; h < 2; h++)
            if (tig == 0)
                sL[(wid & 3)*128 + wm0 + i*16 + h*8 + g] = l[i*2 + h];
    __syncthreads();

    // normalize by total l and store ctx (fp16; feeds out-proj GEMM)
    __half* Cb = ctx + ((size_t)b*Tt + row0) * Dd + n*HDh;
    #pragma unroll
    for (int i = 0; i < 4; i++) {
        #pragma unroll
        for (int h = 0; h < 2; h++) {
            int m = wm0 + i*16 + g + h*8;
            float ltot = sL[m] + sL[128 + m] + sL[256 + m] + sL[384 + m];
            float linv = __fdividef(1.0f, ltot);
            #pragma unroll
            for (int j = 0; j < 2; j++) {
                int col = wn0 + j*8 + tig*2;
                float v0 = accO[i][j][h*2 + 0] * linv;
                float v1 = accO[i][j][h*2 + 1] * linv;
                *(uint32_t*)(Cb + (size_t)m * Dd + col) =
                    h2u(__floats2half2_rn(v0, v1));
            }
        }
    }
}

// -------- launch --------
extern "C" void kernel_launch(void* const* d_in, const int* in_sizes, int n_in,
                              void* d_out, int out_size)
{
    const float* inputs = (const float*)d_in[0];
    const float* ln1_g  = (const float*)d_in[1];
    const float* ln1_b  = (const float*)d_in[2];
    const float* wq     = (const float*)d_in[3];
    const float* bq     = (const float*)d_in[4];
    const float* wk     = (const float*)d_in[5];
    const float* bk     = (const float*)d_in[6];
    const float* wv     = (const float*)d_in[7];
    const float* bv     = (const float*)d_in[8];
    const float* wo     = (const float*)d_in[9];
    const float* bo     = (const float*)d_in[10];
    const float* ln2_g  = (const float*)d_in[11];
    const float* ln2_b  = (const float*)d_in[12];
    const float* w1     = (const float*)d_in[13];
    const float* b1     = (const float*)d_in[14];
    const float* w2     = (const float*)d_in[15];
    const float* b2     = (const float*)d_in[16];
    float* out = (float*)d_out;

    __half *xln, *qkv, *ctx, *yln, *h1;
    float *xres, *bqkv;
    uint32_t *vp, *wqkv_p, *wo_p, *w1_p, *w2_p;
    cudaGetSymbolAddress((void**)&xln,    g_xln);
    cudaGetSymbolAddress((void**)&qkv,    g_qkv);
    cudaGetSymbolAddress((void**)&vp,     g_vp);
    cudaGetSymbolAddress((void**)&ctx,    g_ctx);
    cudaGetSymbolAddress((void**)&xres,   g_xres);
    cudaGetSymbolAddress((void**)&yln,    g_yln);
    cudaGetSymbolAddress((void**)&h1,     g_h1);
    cudaGetSymbolAddress((void**)&wqkv_p, g_wqkv_p);
    cudaGetSymbolAddress((void**)&bqkv,   g_bqkv);
    cudaGetSymbolAddress((void**)&wo_p,   g_wo_p);
    cudaGetSymbolAddress((void**)&w1_p,   g_w1_p);
    cudaGetSymbolAddress((void**)&w2_p,   g_w2_p);

    // opt-in dynamic smem
    cudaFuncSetAttribute((const void*)gemm2<0,false,true>, cudaFuncAttributeMaxDynamicSharedMemorySize, G2_SMEM);
    cudaFuncSetAttribute((const void*)gemm2<0,true,false>, cudaFuncAttributeMaxDynamicSharedMemorySize, G2_SMEM);
    cudaFuncSetAttribute((const void*)gemm2<1,false,true>, cudaFuncAttributeMaxDynamicSharedMemorySize, G2_SMEM);
    cudaFuncSetAttribute((const void*)flash_attn, cudaFuncAttributeMaxDynamicSharedMemorySize, FA_SMEM);

    // 0) pack weights
    pack_qkv_w_kernel<<<(Dd/2*QKVS + 255)/256, 256>>>(wq, wk, wv, wqkv_p);
    pack_qkv_b_kernel<<<(QKVS + 255)/256, 256>>>(bq, bk, bv, bqkv);
    {
        int tot = Dd/2*Dd;
        pack_w_kernel<<<(tot+255)/256, 256>>>(wo, wo_p, Dd, tot);
        int tot1 = Dd/2*FFd;
        pack_w_kernel<<<(tot1+255)/256, 256>>>(w1, w1_p, FFd, tot1);
        int tot2 = FFd/2*Dd;
        pack_w_kernel<<<(tot2+255)/256, 256>>>(w2, w2_p, Dd, tot2);
    }

    // 1) LN1 (fp16 out)
    ln_kernel<<<MM, 256>>>(inputs, ln1_g, ln1_b, xln);

    // 2) fused QKV projection -> qkv [M][3072]
    dim3 gQKV(QKVS/128, MM/128);
    gemm2<0,false,true><<<gQKV, 256, G2_SMEM>>>(xln, wqkv_p, bqkv, nullptr, qkv, MM, QKVS, Dd);

    // 2b) repack V into s-pair layout
    repack_v_kernel<<<(int)((size_t)MM*Dd/2/256), 256>>>(qkv, vp);

    // 3) fused attention -> ctx
    dim3 gA(Tt/128, Bb*NHh);
    flash_attn<<<gA, 256, FA_SMEM>>>(qkv, vp, ctx);

    // 4) out-proj + residual(inputs) -> xres (fp32)
    dim3 gD(Dd/128, MM/128);
    gemm2<0,true,false><<<gD, 256, G2_SMEM>>>(ctx, wo_p, bo, inputs, xres, MM, Dd, Dd);

    // 5) LN2
    ln_kernel<<<MM, 256>>>(xres, ln2_g, ln2_b, yln);

    // 6) MLP up + exact GELU -> h1 (fp16)
    dim3 gF(FFd/128, MM/128);
    gemm2<1,false,true><<<gF, 256, G2_SMEM>>>(yln, w1_p, b1, nullptr, h1, MM, FFd, Dd);

    // 7) MLP down + bias + residual(xres) -> out (fp32)
    gemm2<0,true,false><<<gD, 256, G2_SMEM>>>(h1, w2_p, b2, xres, out, MM, Dd, FFd);
}

// round 12
// speedup vs baseline: 6.8089x; 1.0302x over previous
#include <cuda_runtime.h>
#include <cuda_fp16.h>
#include <math.h>
#include <stdint.h>

// Problem dims
#define Bb 4
#define Tt 2048
#define Dd 1024
#define NHh 16
#define HDh 64
#define FFd 4096
#define MM (Bb*Tt)          // 8192 rows
#define QKVS 3072           // fused qkv row stride

// -------- scratch (device globals; no allocs allowed) --------
__device__ __half g_xln[(size_t)MM*Dd];
__device__ __half g_qkv[(size_t)MM*QKVS];
__device__ uint32_t g_vp[(size_t)MM*Dd/2];   // V packed: [b][n][spair][64] u32
__device__ __half g_ctx[(size_t)MM*Dd];
__device__ float  g_xres[(size_t)MM*Dd];
__device__ __half g_yln[(size_t)MM*Dd];
__device__ __half g_h1 [(size_t)MM*FFd];
// packed fp16 weights: u32 [K/2][N], u32 = half2(w[2r][n], w[2r+1][n])
__device__ uint32_t g_wqkv_p[(size_t)Dd/2*QKVS];
__device__ float    g_bqkv  [QKVS];
__device__ uint32_t g_wo_p[(size_t)Dd/2*Dd];
__device__ uint32_t g_w1_p[(size_t)Dd/2*FFd];
__device__ uint32_t g_w2_p[(size_t)FFd/2*Dd];

// -------- helpers --------
#define MMA_F16(c, a, b) \
    asm volatile("mma.sync.aligned.m16n8k16.row.col.f32.f16.f16.f32 " \
                 "{%0,%1,%2,%3},{%4,%5,%6,%7},{%8,%9},{%0,%1,%2,%3};" \
                 : "+f"((c)[0]), "+f"((c)[1]), "+f"((c)[2]), "+f"((c)[3]) \
                 : "r"((a)[0]), "r"((a)[1]), "r"((a)[2]), "r"((a)[3]), \
                   "r"((b)[0]), "r"((b)[1]))

#define LDSM4(r0, r1, r2, r3, addr) \
    asm volatile("ldmatrix.sync.aligned.m8n8.x4.shared.b16 {%0,%1,%2,%3}, [%4];" \
                 : "=r"(r0), "=r"(r1), "=r"(r2), "=r"(r3) : "r"(addr))

#define CP16(dst_u32, src_ptr) \
    asm volatile("cp.async.cg.shared.global [%0], [%1], 16;" :: "r"(dst_u32), "l"(src_ptr))
#define CP_COMMIT() asm volatile("cp.async.commit_group;")
#define CP_WAIT0()  asm volatile("cp.async.wait_group 0;")
#define CP_WAIT1()  asm volatile("cp.async.wait_group 1;")

__device__ __forceinline__ uint32_t s2u(const void* p) {
    return (uint32_t)__cvta_generic_to_shared(p);
}
__device__ __forceinline__ uint32_t h2u(__half2 h) { return *(uint32_t*)&h; }

__device__ __forceinline__ float block_reduce_sum(float v, float* sh) {
    int t = threadIdx.x;
    #pragma unroll
    for (int o = 16; o > 0; o >>= 1) v += __shfl_down_sync(0xffffffffu, v, o);
    if ((t & 31) == 0) sh[t >> 5] = v;
    __syncthreads();
    if (t < 32) {
        float w = (t < 8) ? sh[t] : 0.0f;
        #pragma unroll
        for (int o = 4; o > 0; o >>= 1) w += __shfl_down_sync(0xffffffffu, w, o);
        if (t == 0) sh[0] = w;
    }
    __syncthreads();
    float r = sh[0];
    __syncthreads();
    return r;
}

// -------- weight pack: fp32 [K][N] -> u32 [K/2][N] (half2 along k) --------
__global__ void pack_w_kernel(const float* __restrict__ in, uint32_t* __restrict__ out,
                              int N, int total)
{
    int idx = blockIdx.x * 256 + threadIdx.x;
    if (idx < total) {
        int r = idx / N, n = idx - r * N;
        float a = in[(size_t)(2*r) * N + n];
        float b = in[(size_t)(2*r+1) * N + n];
        out[idx] = h2u(__floats2half2_rn(a, b));
    }
}

// -------- fused qkv weight pack (wq pre-scaled 0.125) --------
__global__ void pack_qkv_w_kernel(const float* __restrict__ wq, const float* __restrict__ wk,
                                  const float* __restrict__ wv, uint32_t* __restrict__ out)
{
    int idx = blockIdx.x * 256 + threadIdx.x;
    if (idx < Dd/2*QKVS) {
        int r = idx / QKVS, n = idx - r * QKVS;
        const float* src; float sc; int nn;
        if (n < Dd)        { src = wq; sc = 0.125f; nn = n; }
        else if (n < 2*Dd) { src = wk; sc = 1.0f;   nn = n - Dd; }
        else               { src = wv; sc = 1.0f;   nn = n - 2*Dd; }
        float a = src[(size_t)(2*r) * Dd + nn] * sc;
        float b = src[(size_t)(2*r+1) * Dd + nn] * sc;
        out[idx] = h2u(__floats2half2_rn(a, b));
    }
}

__global__ void pack_qkv_b_kernel(const float* __restrict__ bq, const float* __restrict__ bk,
                                  const float* __restrict__ bv, float* __restrict__ out)
{
    int n = blockIdx.x * 256 + threadIdx.x;
    if (n < QKVS) {
        if (n < Dd)        out[n] = bq[n] * 0.125f;
        else if (n < 2*Dd) out[n] = bk[n - Dd];
        else               out[n] = bv[n - 2*Dd];
    }
}

// -------- V repack: qkv V-part -> u32 [b][n][spair][64] (s-pair half2) --------
__global__ void repack_v_kernel(const __half* __restrict__ qkv, uint32_t* __restrict__ vp)
{
    size_t idx = (size_t)blockIdx.x * 256 + threadIdx.x;   // MM*Dd/2 total
    int h = idx & 63;
    size_t r1 = idx >> 6;
    int spair = (int)(r1 & (Tt/2 - 1));
    size_t r2 = r1 >> 10;
    int n = (int)(r2 & (NHh - 1));
    int b = (int)(r2 >> 4);
    const __half* src = qkv + ((size_t)b*Tt + 2*spair) * QKVS + 2*Dd + n*HDh + h;
    vp[idx] = h2u(__halves2half2(src[0], src[QKVS]));
}

// -------- LayerNorm: one block (256 thr) per row of 1024; fp16 out --------
__global__ void ln_kernel(const float* __restrict__ x, const float* __restrict__ gamma,
                          const float* __restrict__ beta, __half* __restrict__ out)
{
    __shared__ float sh[32];
    size_t row = blockIdx.x;
    const float4* xr = (const float4*)(x + row * Dd);
    int t = threadIdx.x;
    float4 xv = xr[t];
    float s  = xv.x + xv.y + xv.z + xv.w;
    float s2 = xv.x*xv.x + xv.y*xv.y + xv.z*xv.z + xv.w*xv.w;
    float S  = block_reduce_sum(s,  sh);
    float S2 = block_reduce_sum(s2, sh);
    float mean = S * (1.0f / Dd);
    float var  = S2 * (1.0f / Dd) - mean * mean;
    float rs   = rsqrtf(var + 1e-6f);
    float4 gv = ((const float4*)gamma)[t];
    float4 bv = ((const float4*)beta)[t];
    __half2 h0 = __floats2half2_rn((xv.x - mean) * rs * gv.x + bv.x,
                                   (xv.y - mean) * rs * gv.y + bv.y);
    __half2 h1 = __floats2half2_rn((xv.z - mean) * rs * gv.z + bv.z,
                                   (xv.w - mean) * rs * gv.w + bv.w);
    uint2 pkd; pkd.x = h2u(h0); pkd.y = h2u(h1);
    *(uint2*)(out + row * Dd + t*4) = pkd;
}

// ============================================================================
// cp.async 3-stage pipelined FP16 GEMM: C = act(A@B + bias) (+res)
// A [M,K] fp16 row-major; B packed u32 [K/2][N]. BM=128 BN=128 BK=64, 256 thr.
// warps 2m x 4n; mma m16n8k16; ldmatrix.x4 for A fragments.
// smem: sA u32 [3][128][36], sB u32 [3][32][136]; ONE barrier per K-iter
// (mod-3 rotation: prefetch target == compute buffer of iter t-1, drained by
//  the top-of-iter barrier).
// ============================================================================
#define G2_SMEM (3*(128*36 + 32*136)*4)
template<int ACT, bool HAS_RES, bool OUT_HALF>
__global__ __launch_bounds__(256, 2) void gemm2(
    const __half* __restrict__ A, const uint32_t* __restrict__ Bm,
    const float* __restrict__ bias, const float* __restrict__ res,
    void* __restrict__ Cv, int M, int N, int K)
{
    extern __shared__ uint32_t smem_[];
    uint32_t* sA = smem_;               // [3][128*36]
    uint32_t* sB = smem_ + 3*128*36;    // [3][32*136]
    int tid = threadIdx.x;
    int lane = tid & 31, wid = tid >> 5;
    int g = lane >> 2, tig = lane & 3;
    int wm0 = (wid >> 2) * 64;
    int wn0 = (wid & 3) * 32;
    int row0 = blockIdx.y * 128;
    int col0 = blockIdx.x * 128;
    const __half* Ab = A + (size_t)row0 * K;
    const uint32_t* Bp = Bm + col0;

    int lr = lane & 7, sel = lane >> 3;
    int a_row_off = ((sel & 1) << 3) + lr;
    int a_col_off = (sel >> 1) << 2;

    float acc[4][4][4] = {};

    int nk = K >> 6;
    #define COPY_STAGE(buf, k0) do { \
        uint32_t* dA = sA + (buf)*128*36; \
        uint32_t* dB = sB + (buf)*32*136; \
        _Pragma("unroll") \
        for (int i_ = 0; i_ < 4; i_++) { \
            int f = tid + i_*256; \
            int rr = f >> 3, cq = f & 7; \
            CP16(s2u(dA + rr*36 + cq*4), Ab + (size_t)rr * K + (k0) + cq*8); \
        } \
        _Pragma("unroll") \
        for (int i_ = 0; i_ < 4; i_++) { \
            int f = tid + i_*256; \
            int rr = f >> 5, cq = f & 31; \
            CP16(s2u(dB + rr*136 + cq*4), Bp + (size_t)(((k0)>>1) + rr) * N + cq*4); \
        } \
    } while (0)

    COPY_STAGE(0, 0);
    CP_COMMIT();
    if (nk > 1) { COPY_STAGE(1, 64); CP_COMMIT(); }

    for (int it = 0; it < nk; it++) {
        if (it + 1 < nk) { CP_WAIT1(); } else { CP_WAIT0(); }
        __syncthreads();                      // stage it ready; stage (it+2)%3 drained
        if (it + 2 < nk) {
            COPY_STAGE((it + 2) % 3, (it + 2) << 6);
            CP_COMMIT();
        }
        uint32_t* cA = sA + (it % 3)*128*36;
        uint32_t* cB = sB + (it % 3)*32*136;
        #pragma unroll
        for (int ks = 0; ks < 4; ks++) {
            int kc = ks * 8;
            uint32_t af[4][4], bf[4][2];
            #pragma unroll
            for (int i = 0; i < 4; i++) {
                uint32_t addr = s2u(cA + (wm0 + i*16 + a_row_off)*36 + kc + a_col_off);
                LDSM4(af[i][0], af[i][1], af[i][2], af[i][3], addr);
            }
            #pragma unroll
            for (int j = 0; j < 4; j++) {
                int nn = wn0 + j*8 + g;
                bf[j][0] = cB[(kc + tig)*136 + nn];
                bf[j][1] = cB[(kc + tig + 4)*136 + nn];
            }
            #pragma unroll
            for (int i = 0; i < 4; i++)
                #pragma unroll
                for (int j = 0; j < 4; j++)
                    MMA_F16(acc[i][j], af[i], bf[j]);
        }
    }
    #undef COPY_STAGE

    // epilogue
    #pragma unroll
    for (int i = 0; i < 4; i++) {
        #pragma unroll
        for (int j = 0; j < 4; j++) {
            int col = col0 + wn0 + j*8 + tig*2;
            #pragma unroll
            for (int h = 0; h < 2; h++) {
                int row = row0 + wm0 + i*16 + g + h*8;
                float v0 = acc[i][j][h*2 + 0] + bias[col];
                float v1 = acc[i][j][h*2 + 1] + bias[col + 1];
                if (ACT == 1) {
                    v0 = 0.5f * v0 * (1.0f + erff(v0 * 0.70710678118654752f));
                    v1 = 0.5f * v1 * (1.0f + erff(v1 * 0.70710678118654752f));
                }
                if (HAS_RES) {
                    float2 rr = *(const float2*)(res + (size_t)row * N + col);
                    v0 += rr.x; v1 += rr.y;
                }
                if (OUT_HALF) {
                    *(uint32_t*)((__half*)Cv + (size_t)row * N + col) =
                        h2u(__floats2half2_rn(v0, v1));
                } else {
                    *(float2*)((float*)Cv + (size_t)row * N + col) = make_float2(v0, v1);
                }
            }
        }
    }
}

// ============================================================================
// Fused flash attention, fp16, soft-cap fixed reference 2:
//   p = 2^(min(tanh(s/50)*50*log2e - 2*log2e, 11.5)); ref cancels in l-norm.
// Q/K from fused qkv (stride QKVS); V pre-packed s-pairs from g_vp.
// BM=128, BS=64. 256 thr, warps 2m x 4n. Double-buffered K/V via cp.async.
// Row-sum: per-thread partial accumulated in-loop; quad shfl deferred to end.
// smem u32: sQ [128][36], sK [2][64][36], sV [2][32][72], sP [128][36].
// ============================================================================
#define FA_SMEM ((128*36 + 2*64*36 + 2*32*72 + 128*36 + 4*128)*4)
__global__ __launch_bounds__(256, 2) void flash_attn(
    const __half* __restrict__ qkv, const uint32_t* __restrict__ vp,
    __half* __restrict__ ctx)
{
    extern __shared__ uint32_t smem_[];
    uint32_t* sQ = smem_;                  // [128][36]
    uint32_t* sK = smem_ + 128*36;         // [2][64][36]
    uint32_t* sV = sK + 2*64*36;           // [2][32][72]
    uint32_t* sP = sV + 2*32*72;           // [128][36]
    float*    sL = (float*)(sP + 128*36);  // [4][128]
    int tid = threadIdx.x;
    int lane = tid & 31, wid = tid >> 5;
    int g = lane >> 2, tig = lane & 3;
    int wm0 = (wid >> 2) * 64;
    int wn0 = (wid & 3) * 16;
    int row0 = blockIdx.x * 128;
    int z = blockIdx.y;
    int b = z >> 4, n = z & 15;
    const __half* Qb = qkv + ((size_t)b*Tt + row0) * QKVS + n*HDh;
    const __half* Kb = qkv + (size_t)b*Tt*QKVS + Dd + n*HDh;
    const uint32_t* Vp = vp + (size_t)(b*NHh + n) * (Tt/2) * HDh;

    int lr = lane & 7, sel = lane >> 3;
    int a_row_off = ((sel & 1) << 3) + lr;
    int a_col_off = (sel >> 1) << 2;

    #define LOAD_KV(buf, s0) do { \
        uint32_t* dK = sK + (buf)*64*36; \
        uint32_t* dV = sV + (buf)*32*72; \
        _Pragma("unroll") \
        for (int i_ = 0; i_ < 2; i_++) { \
            int f = tid + i_*256; \
            int rr = f >> 3, cq = f & 7; \
            CP16(s2u(dK + rr*36 + cq*4), Kb + (size_t)((s0) + rr) * QKVS + cq*8); \
        } \
        _Pragma("unroll") \
        for (int i_ = 0; i_ < 2; i_++) { \
            int f = tid + i_*256; \
            int rr = f >> 4, hq = f & 15; \
            CP16(s2u(dV + rr*72 + hq*4), Vp + ((size_t)((s0)>>1) + rr) * HDh + hq*4); \
        } \
    } while (0)

    #pragma unroll
    for (int i = 0; i < 4; i++) {
        int f = tid + i*256;
        int rr = f >> 3, cq = f & 7;
        CP16(s2u(sQ + rr*36 + cq*4), Qb + (size_t)rr * QKVS + cq*8);
    }
    CP_COMMIT();
    LOAD_KV(0, 0);
    CP_COMMIT();

    const __half2 c_scale = __floats2half2_rn(72.134752f, 72.134752f);
    const __half2 c_off   = __floats2half2_rn(-2.8853901f, -2.8853901f);
    const __half2 c_clamp = __floats2half2_rn(11.5f, 11.5f);

    float l[8] = {0,0,0,0,0,0,0,0};        // per-thread partials (quad-reduced at end)
    float accO[4][2][4] = {};

    const int NT = Tt / 64;
    for (int t = 0; t < NT; t++) {
        CP_WAIT0();
        __syncthreads();
        if (t + 1 < NT) {
            LOAD_KV((t+1)&1, (t+1)*64);
            CP_COMMIT();
        }
        uint32_t* cK = sK + (t&1)*64*36;
        uint32_t* cV = sV + (t&1)*32*72;

        float accS[4][2][4] = {};
        #pragma unroll
        for (int kk = 0; kk < 64; kk += 16) {
            int kc = kk >> 1;
            uint32_t af[4][4], bf[2][2];
            #pragma unroll
            for (int i = 0; i < 4; i++) {
                uint32_t addr = s2u(sQ + (wm0 + i*16 + a_row_off)*36 + kc + a_col_off);
                LDSM4(af[i][0], af[i][1], af[i][2], af[i][3], addr);
            }
            #pragma unroll
            for (int j = 0; j < 2; j++) {
                int nn = wn0 + j*8 + g;
                bf[j][0] = cK[nn*36 + kc + tig];
                bf[j][1] = cK[nn*36 + kc + tig + 4];
            }
            #pragma unroll
            for (int i = 0; i < 4; i++)
                #pragma unroll
                for (int j = 0; j < 2; j++)
                    MMA_F16(accS[i][j], af[i], bf[j]);
        }

        // softcap + exp2 (fixed ref 2) in f16x2 + per-thread partial sum + store P
        #pragma unroll
        for (int i = 0; i < 4; i++) {
            #pragma unroll
            for (int h = 0; h < 2; h++) {
                int m = wm0 + i*16 + g + h*8;
                float ps = 0.0f;
                #pragma unroll
                for (int j = 0; j < 2; j++) {
                    __half2 x = __floats2half2_rn(accS[i][j][h*2 + 0] * 0.02f,
                                                  accS[i][j][h*2 + 1] * 0.02f);
                    uint32_t tu;
                    asm("tanh.approx.f16x2 %0, %1;" : "=r"(tu) : "r"(h2u(x)));
                    __half2 w = __hfma2(*(__half2*)&tu, c_scale, c_off);
                    w = __hmin2(w, c_clamp);
                    uint32_t pu;
                    asm("ex2.approx.f16x2 %0, %1;" : "=r"(pu) : "r"(h2u(w)));
                    sP[m*36 + (wid&3)*8 + j*4 + tig] = pu;
                    float2 pf = __half22float2(*(__half2*)&pu);
                    ps += pf.x + pf.y;
                }
                l[i*2 + h] += ps;      // defer quad shfl to after the loop
            }
        }
        __syncthreads();

        #pragma unroll
        for (int kk = 0; kk < 64; kk += 16) {
            int kc = kk >> 1;
            uint32_t af[4][4], bf[2][2];
            #pragma unroll
            for (int i = 0; i < 4; i++) {
                uint32_t addr = s2u(sP + (wm0 + i*16 + a_row_off)*36 + kc + a_col_off);
                LDSM4(af[i][0], af[i][1], af[i][2], af[i][3], addr);
            }
            #pragma unroll
            for (int j = 0; j < 2; j++) {
                int nn = wn0 + j*8 + g;
                bf[j][0] = cV[(kc + tig)*72 + nn];
                bf[j][1] = cV[(kc + tig + 4)*72 + nn];
            }
            #pragma unroll
            for (int i = 0; i < 4; i++)
                #pragma unroll
                for (int j = 0; j < 2; j++)
                    MMA_F16(accO[i][j], af[i], bf[j]);
        }
    }
    #undef LOAD_KV

    // quad-reduce the deferred partials, then combine across the 4 n-warps
    #pragma unroll
    for (int q = 0; q < 8; q++) {
        l[q] += __shfl_xor_sync(0xffffffffu, l[q], 1);
        l[q] += __shfl_xor_sync(0xffffffffu, l[q], 2);
    }
    __syncthreads();
    #pragma unroll
    for (int i = 0; i < 4; i++)
        #pragma unroll
        for (int h = 0; h < 2; h++)
            if (tig == 0)
                sL[(wid & 3)*128 + wm0 + i*16 + h*8 + g] = l[i*2 + h];
    __syncthreads();

    __half* Cb = ctx + ((size_t)b*Tt + row0) * Dd + n*HDh;
    #pragma unroll
    for (int i = 0; i < 4; i++) {
        #pragma unroll
        for (int h = 0; h < 2; h++) {
            int m = wm0 + i*16 + g + h*8;
            float ltot = sL[m] + sL[128 + m] + sL[256 + m] + sL[384 + m];
            float linv = __fdividef(1.0f, ltot);
            #pragma unroll
            for (int j = 0; j < 2; j++) {
                int col = wn0 + j*8 + tig*2;
                float v0 = accO[i][j][h*2 + 0] * linv;
                float v1 = accO[i][j][h*2 + 1] * linv;
                *(uint32_t*)(Cb + (size_t)m * Dd + col) =
                    h2u(__floats2half2_rn(v0, v1));
            }
        }
    }
}

// -------- launch --------
extern "C" void kernel_launch(void* const* d_in, const int* in_sizes, int n_in,
                              void* d_out, int out_size)
{
    const float* inputs = (const float*)d_in[0];
    const float* ln1_g  = (const float*)d_in[1];
    const float* ln1_b  = (const float*)d_in[2];
    const float* wq     = (const float*)d_in[3];
    const float* bq     = (const float*)d_in[4];
    const float* wk     = (const float*)d_in[5];
    const float* bk     = (const float*)d_in[6];
    const float* wv     = (const float*)d_in[7];
    const float* bv     = (const float*)d_in[8];
    const float* wo     = (const float*)d_in[9];
    const float* bo     = (const float*)d_in[10];
    const float* ln2_g  = (const float*)d_in[11];
    const float* ln2_b  = (const float*)d_in[12];
    const float* w1     = (const float*)d_in[13];
    const float* b1     = (const float*)d_in[14];
    const float* w2     = (const float*)d_in[15];
    const float* b2     = (const float*)d_in[16];
    float* out = (float*)d_out;

    __half *xln, *qkv, *ctx, *yln, *h1;
    float *xres, *bqkv;
    uint32_t *vp, *wqkv_p, *wo_p, *w1_p, *w2_p;
    cudaGetSymbolAddress((void**)&xln,    g_xln);
    cudaGetSymbolAddress((void**)&qkv,    g_qkv);
    cudaGetSymbolAddress((void**)&vp,     g_vp);
    cudaGetSymbolAddress((void**)&ctx,    g_ctx);
    cudaGetSymbolAddress((void**)&xres,   g_xres);
    cudaGetSymbolAddress((void**)&yln,    g_yln);
    cudaGetSymbolAddress((void**)&h1,     g_h1);
    cudaGetSymbolAddress((void**)&wqkv_p, g_wqkv_p);
    cudaGetSymbolAddress((void**)&bqkv,   g_bqkv);
    cudaGetSymbolAddress((void**)&wo_p,   g_wo_p);
    cudaGetSymbolAddress((void**)&w1_p,   g_w1_p);
    cudaGetSymbolAddress((void**)&w2_p,   g_w2_p);

    // opt-in dynamic smem
    cudaFuncSetAttribute((const void*)gemm2<0,false,true>, cudaFuncAttributeMaxDynamicSharedMemorySize, G2_SMEM);
    cudaFuncSetAttribute((const void*)gemm2<0,true,false>, cudaFuncAttributeMaxDynamicSharedMemorySize, G2_SMEM);
    cudaFuncSetAttribute((const void*)gemm2<1,false,true>, cudaFuncAttributeMaxDynamicSharedMemorySize, G2_SMEM);
    cudaFuncSetAttribute((const void*)flash_attn, cudaFuncAttributeMaxDynamicSharedMemorySize, FA_SMEM);

    // 0) pack weights
    pack_qkv_w_kernel<<<(Dd/2*QKVS + 255)/256, 256>>>(wq, wk, wv, wqkv_p);
    pack_qkv_b_kernel<<<(QKVS + 255)/256, 256>>>(bq, bk, bv, bqkv);
    {
        int tot = Dd/2*Dd;
        pack_w_kernel<<<(tot+255)/256, 256>>>(wo, wo_p, Dd, tot);
        int tot1 = Dd/2*FFd;
        pack_w_kernel<<<(tot1+255)/256, 256>>>(w1, w1_p, FFd, tot1);
        int tot2 = FFd/2*Dd;
        pack_w_kernel<<<(tot2+255)/256, 256>>>(w2, w2_p, Dd, tot2);
    }

    // 1) LN1 (fp16 out)
    ln_kernel<<<MM, 256>>>(inputs, ln1_g, ln1_b, xln);

    // 2) fused QKV projection -> qkv [M][3072]
    dim3 gQKV(QKVS/128, MM/128);
    gemm2<0,false,true><<<gQKV, 256, G2_SMEM>>>(xln, wqkv_p, bqkv, nullptr, qkv, MM, QKVS, Dd);

    // 2b) repack V into s-pair layout
    repack_v_kernel<<<(int)((size_t)MM*Dd/2/256), 256>>>(qkv, vp);

    // 3) fused attention -> ctx
    dim3 gA(Tt/128, Bb*NHh);
    flash_attn<<<gA, 256, FA_SMEM>>>(qkv, vp, ctx);

    // 4) out-proj + residual(inputs) -> xres (fp32)
    dim3 gD(Dd/128, MM/128);
    gemm2<0,true,false><<<gD, 256, G2_SMEM>>>(ctx, wo_p, bo, inputs, xres, MM, Dd, Dd);

    // 5) LN2
    ln_kernel<<<MM, 256>>>(xres, ln2_g, ln2_b, yln);

    // 6) MLP up + exact GELU -> h1 (fp16)
    dim3 gF(FFd/128, MM/128);
    gemm2<1,false,true><<<gF, 256, G2_SMEM>>>(yln, w1_p, b1, nullptr, h1, MM, FFd, Dd);

    // 7) MLP down + bias + residual(xres) -> out (fp32)
    gemm2<0,true,false><<<gD, 256, G2_SMEM>>>(h1, w2_p, b2, xres, out, MM, Dd, FFd);
}

// round 13
// speedup vs baseline: 7.1755x; 1.0538x over previous
#include <cuda_runtime.h>
#include <cuda_fp16.h>
#include <math.h>
#include <stdint.h>

// Problem dims
#define Bb 4
#define Tt 2048
#define Dd 1024
#define NHh 16
#define HDh 64
#define FFd 4096
#define MM (Bb*Tt)          // 8192 rows
#define QKVS 3072           // fused qkv row stride

// -------- scratch (device globals; no allocs allowed) --------
__device__ __half g_xln[(size_t)MM*Dd];
__device__ __half g_qkv[(size_t)MM*QKVS];
__device__ uint32_t g_vp[(size_t)MM*Dd/2];   // V packed: [b][n][spair][64] u32
__device__ __half g_ctx[(size_t)MM*Dd];
__device__ float  g_xres[(size_t)MM*Dd];
__device__ __half g_yln[(size_t)MM*Dd];
__device__ __half g_h1 [(size_t)MM*FFd];
// packed fp16 weights: u32 [K/2][N], u32 = half2(w[2r][n], w[2r+1][n])
__device__ uint32_t g_wqkv_p[(size_t)Dd/2*QKVS];
__device__ float    g_bqkv  [QKVS];
__device__ uint32_t g_wo_p[(size_t)Dd/2*Dd];
__device__ uint32_t g_w1_p[(size_t)Dd/2*FFd];
__device__ uint32_t g_w2_p[(size_t)FFd/2*Dd];

// -------- helpers --------
#define MMA_F16(c, a, b) \
    asm volatile("mma.sync.aligned.m16n8k16.row.col.f32.f16.f16.f32 " \
                 "{%0,%1,%2,%3},{%4,%5,%6,%7},{%8,%9},{%0,%1,%2,%3};" \
                 : "+f"((c)[0]), "+f"((c)[1]), "+f"((c)[2]), "+f"((c)[3]) \
                 : "r"((a)[0]), "r"((a)[1]), "r"((a)[2]), "r"((a)[3]), \
                   "r"((b)[0]), "r"((b)[1]))

#define LDSM4(r0, r1, r2, r3, addr) \
    asm volatile("ldmatrix.sync.aligned.m8n8.x4.shared.b16 {%0,%1,%2,%3}, [%4];" \
                 : "=r"(r0), "=r"(r1), "=r"(r2), "=r"(r3) : "r"(addr))

#define CP16(dst_u32, src_ptr) \
    asm volatile("cp.async.cg.shared.global [%0], [%1], 16;" :: "r"(dst_u32), "l"(src_ptr))
#define CP_COMMIT() asm volatile("cp.async.commit_group;")
#define CP_WAIT0()  asm volatile("cp.async.wait_group 0;")
#define CP_WAIT1()  asm volatile("cp.async.wait_group 1;")

__device__ __forceinline__ uint32_t s2u(const void* p) {
    return (uint32_t)__cvta_generic_to_shared(p);
}
__device__ __forceinline__ uint32_t h2u(__half2 h) { return *(uint32_t*)&h; }

__device__ __forceinline__ float block_reduce_sum(float v, float* sh) {
    int t = threadIdx.x;
    #pragma unroll
    for (int o = 16; o > 0; o >>= 1) v += __shfl_down_sync(0xffffffffu, v, o);
    if ((t & 31) == 0) sh[t >> 5] = v;
    __syncthreads();
    if (t < 32) {
        float w = (t < 8) ? sh[t] : 0.0f;
        #pragma unroll
        for (int o = 4; o > 0; o >>= 1) w += __shfl_down_sync(0xffffffffu, w, o);
        if (t == 0) sh[0] = w;
    }
    __syncthreads();
    float r = sh[0];
    __syncthreads();
    return r;
}

// -------- vectorized weight pack (N = 1<<SHIFT): fp32 [K][N] -> u32 [K/2][N] --------
template<int SHIFT>
__global__ void pack_w4_kernel(const float* __restrict__ in, uint32_t* __restrict__ out,
                               int total4)   // total4 = (K/2*N)/4
{
    int idx = blockIdx.x * 256 + threadIdx.x;
    if (idx < total4) {
        int r  = idx >> (SHIFT - 2);
        int n  = (idx & ((1 << (SHIFT - 2)) - 1)) * 4;
        float4 a = *(const float4*)(in + (((size_t)(2*r))   << SHIFT) + n);
        float4 b = *(const float4*)(in + (((size_t)(2*r+1)) << SHIFT) + n);
        uint4 o;
        o.x = h2u(__floats2half2_rn(a.x, b.x));
        o.y = h2u(__floats2half2_rn(a.y, b.y));
        o.z = h2u(__floats2half2_rn(a.z, b.z));
        o.w = h2u(__floats2half2_rn(a.w, b.w));
        *(uint4*)(out + (((size_t)r) << SHIFT) + n) = o;
    }
}

// -------- fused qkv weight pack, 4-wide (wq pre-scaled 0.125) --------
__global__ void pack_qkv_w_kernel(const float* __restrict__ wq, const float* __restrict__ wk,
                                  const float* __restrict__ wv, uint32_t* __restrict__ out)
{
    int idx = blockIdx.x * 256 + threadIdx.x;   // groups of 4; total Dd/2*QKVS/4
    if (idx < Dd/2*QKVS/4) {
        int r = idx / (QKVS/4);                 // compile-time const divide -> mul/shift
        int n = (idx - r * (QKVS/4)) * 4;
        const float* src; float sc; int nn;
        if (n < Dd)        { src = wq; sc = 0.125f; nn = n; }
        else if (n < 2*Dd) { src = wk; sc = 1.0f;   nn = n - Dd; }
        else               { src = wv; sc = 1.0f;   nn = n - 2*Dd; }
        float4 a = *(const float4*)(src + (size_t)(2*r) * Dd + nn);
        float4 b = *(const float4*)(src + (size_t)(2*r+1) * Dd + nn);
        uint4 o;
        o.x = h2u(__floats2half2_rn(a.x * sc, b.x * sc));
        o.y = h2u(__floats2half2_rn(a.y * sc, b.y * sc));
        o.z = h2u(__floats2half2_rn(a.z * sc, b.z * sc));
        o.w = h2u(__floats2half2_rn(a.w * sc, b.w * sc));
        *(uint4*)(out + (size_t)r * QKVS + n) = o;
    }
}

__global__ void pack_qkv_b_kernel(const float* __restrict__ bq, const float* __restrict__ bk,
                                  const float* __restrict__ bv, float* __restrict__ out)
{
    int n = blockIdx.x * 256 + threadIdx.x;
    if (n < QKVS) {
        if (n < Dd)        out[n] = bq[n] * 0.125f;
        else if (n < 2*Dd) out[n] = bk[n - Dd];
        else               out[n] = bv[n - 2*Dd];
    }
}

// -------- V repack: qkv V-part -> u32 [b][n][spair][64] (s-pair half2) --------
__global__ void repack_v_kernel(const __half* __restrict__ qkv, uint32_t* __restrict__ vp)
{
    size_t idx = (size_t)blockIdx.x * 256 + threadIdx.x;   // MM*Dd/2 total
    int h = idx & 63;
    size_t r1 = idx >> 6;
    int spair = (int)(r1 & (Tt/2 - 1));
    size_t r2 = r1 >> 10;
    int n = (int)(r2 & (NHh - 1));
    int b = (int)(r2 >> 4);
    const __half* src = qkv + ((size_t)b*Tt + 2*spair) * QKVS + 2*Dd + n*HDh + h;
    vp[idx] = h2u(__halves2half2(src[0], src[QKVS]));
}

// -------- LayerNorm: one block (256 thr) per row of 1024; fp16 out --------
__global__ void ln_kernel(const float* __restrict__ x, const float* __restrict__ gamma,
                          const float* __restrict__ beta, __half* __restrict__ out)
{
    __shared__ float sh[32];
    size_t row = blockIdx.x;
    const float4* xr = (const float4*)(x + row * Dd);
    int t = threadIdx.x;
    float4 xv = xr[t];
    float s  = xv.x + xv.y + xv.z + xv.w;
    float s2 = xv.x*xv.x + xv.y*xv.y + xv.z*xv.z + xv.w*xv.w;
    float S  = block_reduce_sum(s,  sh);
    float S2 = block_reduce_sum(s2, sh);
    float mean = S * (1.0f / Dd);
    float var  = S2 * (1.0f / Dd) - mean * mean;
    float rs   = rsqrtf(var + 1e-6f);
    float4 gv = ((const float4*)gamma)[t];
    float4 bv = ((const float4*)beta)[t];
    __half2 h0 = __floats2half2_rn((xv.x - mean) * rs * gv.x + bv.x,
                                   (xv.y - mean) * rs * gv.y + bv.y);
    __half2 h1 = __floats2half2_rn((xv.z - mean) * rs * gv.z + bv.z,
                                   (xv.w - mean) * rs * gv.w + bv.w);
    uint2 pkd; pkd.x = h2u(h0); pkd.y = h2u(h1);
    *(uint2*)(out + row * Dd + t*4) = pkd;
}

// ============================================================================
// cp.async 3-stage pipelined FP16 GEMM: C = act(A@B + bias) (+res)
// (unchanged from round 12 — passing)
// ============================================================================
#define G2_SMEM (3*(128*36 + 32*136)*4)
template<int ACT, bool HAS_RES, bool OUT_HALF>
__global__ __launch_bounds__(256, 2) void gemm2(
    const __half* __restrict__ A, const uint32_t* __restrict__ Bm,
    const float* __restrict__ bias, const float* __restrict__ res,
    void* __restrict__ Cv, int M, int N, int K)
{
    extern __shared__ uint32_t smem_[];
    uint32_t* sA = smem_;               // [3][128*36]
    uint32_t* sB = smem_ + 3*128*36;    // [3][32*136]
    int tid = threadIdx.x;
    int lane = tid & 31, wid = tid >> 5;
    int g = lane >> 2, tig = lane & 3;
    int wm0 = (wid >> 2) * 64;
    int wn0 = (wid & 3) * 32;
    int row0 = blockIdx.y * 128;
    int col0 = blockIdx.x * 128;
    const __half* Ab = A + (size_t)row0 * K;
    const uint32_t* Bp = Bm + col0;

    int lr = lane & 7, sel = lane >> 3;
    int a_row_off = ((sel & 1) << 3) + lr;
    int a_col_off = (sel >> 1) << 2;

    float acc[4][4][4] = {};

    int nk = K >> 6;
    #define COPY_STAGE(buf, k0) do { \
        uint32_t* dA = sA + (buf)*128*36; \
        uint32_t* dB = sB + (buf)*32*136; \
        _Pragma("unroll") \
        for (int i_ = 0; i_ < 4; i_++) { \
            int f = tid + i_*256; \
            int rr = f >> 3, cq = f & 7; \
            CP16(s2u(dA + rr*36 + cq*4), Ab + (size_t)rr * K + (k0) + cq*8); \
        } \
        _Pragma("unroll") \
        for (int i_ = 0; i_ < 4; i_++) { \
            int f = tid + i_*256; \
            int rr = f >> 5, cq = f & 31; \
            CP16(s2u(dB + rr*136 + cq*4), Bp + (size_t)(((k0)>>1) + rr) * N + cq*4); \
        } \
    } while (0)

    COPY_STAGE(0, 0);
    CP_COMMIT();
    if (nk > 1) { COPY_STAGE(1, 64); CP_COMMIT(); }

    for (int it = 0; it < nk; it++) {
        if (it + 1 < nk) { CP_WAIT1(); } else { CP_WAIT0(); }
        __syncthreads();
        if (it + 2 < nk) {
            COPY_STAGE((it + 2) % 3, (it + 2) << 6);
            CP_COMMIT();
        }
        uint32_t* cA = sA + (it % 3)*128*36;
        uint32_t* cB = sB + (it % 3)*32*136;
        #pragma unroll
        for (int ks = 0; ks < 4; ks++) {
            int kc = ks * 8;
            uint32_t af[4][4], bf[4][2];
            #pragma unroll
            for (int i = 0; i < 4; i++) {
                uint32_t addr = s2u(cA + (wm0 + i*16 + a_row_off)*36 + kc + a_col_off);
                LDSM4(af[i][0], af[i][1], af[i][2], af[i][3], addr);
            }
            #pragma unroll
            for (int j = 0; j < 4; j++) {
                int nn = wn0 + j*8 + g;
                bf[j][0] = cB[(kc + tig)*136 + nn];
                bf[j][1] = cB[(kc + tig + 4)*136 + nn];
            }
            #pragma unroll
            for (int i = 0; i < 4; i++)
                #pragma unroll
                for (int j = 0; j < 4; j++)
                    MMA_F16(acc[i][j], af[i], bf[j]);
        }
    }
    #undef COPY_STAGE

    // epilogue
    #pragma unroll
    for (int i = 0; i < 4; i++) {
        #pragma unroll
        for (int j = 0; j < 4; j++) {
            int col = col0 + wn0 + j*8 + tig*2;
            #pragma unroll
            for (int h = 0; h < 2; h++) {
                int row = row0 + wm0 + i*16 + g + h*8;
                float v0 = acc[i][j][h*2 + 0] + bias[col];
                float v1 = acc[i][j][h*2 + 1] + bias[col + 1];
                if (ACT == 1) {
                    v0 = 0.5f * v0 * (1.0f + erff(v0 * 0.70710678118654752f));
                    v1 = 0.5f * v1 * (1.0f + erff(v1 * 0.70710678118654752f));
                }
                if (HAS_RES) {
                    float2 rr = *(const float2*)(res + (size_t)row * N + col);
                    v0 += rr.x; v1 += rr.y;
                }
                if (OUT_HALF) {
                    *(uint32_t*)((__half*)Cv + (size_t)row * N + col) =
                        h2u(__floats2half2_rn(v0, v1));
                } else {
                    *(float2*)((float*)Cv + (size_t)row * N + col) = make_float2(v0, v1);
                }
            }
        }
    }
}

// ============================================================================
// Fused flash attention, fp16, soft-cap fixed reference 2.
// NEW: warps 8m x 1n — each warp owns 16 rows x ALL 64 S-cols, so the S
// accumulator converts IN REGISTERS to the P A-fragment for P@V (no sP smem,
// no second barrier, fully warp-local row sums).
//   a0=pack(c0,c1)[j=2c], a1=pack(c2,c3)[j=2c], a2/a3 same for j=2c+1.
// K B-fragments via ldmatrix.x4 (one LDSM4 = b0/b1 for two n-tiles).
// smem u32: sQ [128][36], sK [2][64][36], sV [2][32][72].
// ============================================================================
#define FA_SMEM ((128*36 + 2*64*36 + 2*32*72)*4)
__global__ __launch_bounds__(256, 2) void flash_attn(
    const __half* __restrict__ qkv, const uint32_t* __restrict__ vp,
    __half* __restrict__ ctx)
{
    extern __shared__ uint32_t smem_[];
    uint32_t* sQ = smem_;                  // [128][36]
    uint32_t* sK = smem_ + 128*36;         // [2][64][36]
    uint32_t* sV = sK + 2*64*36;           // [2][32][72]
    int tid = threadIdx.x;
    int lane = tid & 31, wid = tid >> 5;
    int g = lane >> 2, tig = lane & 3;
    int wm0 = wid * 16;                    // 8 warps on m, 16 rows each
    int row0 = blockIdx.x * 128;
    int z = blockIdx.y;
    int b = z >> 4, n = z & 15;
    const __half* Qb = qkv + ((size_t)b*Tt + row0) * QKVS + n*HDh;
    const __half* Kb = qkv + (size_t)b*Tt*QKVS + Dd + n*HDh;
    const uint32_t* Vp = vp + (size_t)(b*NHh + n) * (Tt/2) * HDh;

    int lr = lane & 7, sel = lane >> 3;
    int a_row_off = ((sel & 1) << 3) + lr;
    int a_col_off = (sel >> 1) << 2;

    #define LOAD_KV(buf, s0) do { \
        uint32_t* dK = sK + (buf)*64*36; \
        uint32_t* dV = sV + (buf)*32*72; \
        _Pragma("unroll") \
        for (int i_ = 0; i_ < 2; i_++) { \
            int f = tid + i_*256; \
            int rr = f >> 3, cq = f & 7; \
            CP16(s2u(dK + rr*36 + cq*4), Kb + (size_t)((s0) + rr) * QKVS + cq*8); \
        } \
        _Pragma("unroll") \
        for (int i_ = 0; i_ < 2; i_++) { \
            int f = tid + i_*256; \
            int rr = f >> 4, hq = f & 15; \
            CP16(s2u(dV + rr*72 + hq*4), Vp + ((size_t)((s0)>>1) + rr) * HDh + hq*4); \
        } \
    } while (0)

    #pragma unroll
    for (int i = 0; i < 4; i++) {
        int f = tid + i*256;
        int rr = f >> 3, cq = f & 7;
        CP16(s2u(sQ + rr*36 + cq*4), Qb + (size_t)rr * QKVS + cq*8);
    }
    CP_COMMIT();
    LOAD_KV(0, 0);
    CP_COMMIT();

    const __half2 c_scale = __floats2half2_rn(72.134752f, 72.134752f);
    const __half2 c_off   = __floats2half2_rn(-2.8853901f, -2.8853901f);
    const __half2 c_clamp = __floats2half2_rn(11.5f, 11.5f);

    float l0 = 0.0f, l1 = 0.0f;            // rows g / g+8 partials (quad-reduced at end)
    float accO[8][4] = {};

    const int NT = Tt / 64;
    for (int t = 0; t < NT; t++) {
        CP_WAIT0();
        __syncthreads();
        if (t + 1 < NT) {
            LOAD_KV((t+1)&1, (t+1)*64);
            CP_COMMIT();
        }
        uint32_t* cK = sK + (t&1)*64*36;
        uint32_t* cV = sV + (t&1)*32*72;

        // ---- S = Q @ K^T  (16 x 64 per warp) ----
        float accS[8][4] = {};
        uint32_t aq[4][4];
        #pragma unroll
        for (int c = 0; c < 4; c++) {
            uint32_t addr = s2u(sQ + (wm0 + a_row_off)*36 + 8*c + a_col_off);
            LDSM4(aq[c][0], aq[c][1], aq[c][2], aq[c][3], addr);
        }
        #pragma unroll
        for (int c = 0; c < 4; c++) {
            #pragma unroll
            for (int jq = 0; jq < 4; jq++) {
                uint32_t t0, t1, t2, t3;
                uint32_t addr = s2u(cK + (16*jq + a_row_off)*36 + 8*c + a_col_off);
                LDSM4(t0, t1, t2, t3, addr);
                uint32_t b0[2] = {t0, t2};
                uint32_t b1[2] = {t1, t3};
                MMA_F16(accS[2*jq],     aq[c], b0);
                MMA_F16(accS[2*jq + 1], aq[c], b1);
            }
        }

        // ---- softcap + exp2 (fixed ref 2), pack P fragments in registers ----
        uint32_t ph0[8], ph1[8];
        #pragma unroll
        for (int j = 0; j < 8; j++) {
            __half2 x01 = __floats2half2_rn(accS[j][0] * 0.02f, accS[j][1] * 0.02f);
            __half2 x23 = __floats2half2_rn(accS[j][2] * 0.02f, accS[j][3] * 0.02f);
            uint32_t tu0, tu1;
            asm("tanh.approx.f16x2 %0, %1;" : "=r"(tu0) : "r"(h2u(x01)));
            asm("tanh.approx.f16x2 %0, %1;" : "=r"(tu1) : "r"(h2u(x23)));
            __half2 w0 = __hmin2(__hfma2(*(__half2*)&tu0, c_scale, c_off), c_clamp);
            __half2 w1 = __hmin2(__hfma2(*(__half2*)&tu1, c_scale, c_off), c_clamp);
            asm("ex2.approx.f16x2 %0, %1;" : "=r"(ph0[j]) : "r"(h2u(w0)));
            asm("ex2.approx.f16x2 %0, %1;" : "=r"(ph1[j]) : "r"(h2u(w1)));
            float2 p0 = __half22float2(*(__half2*)&ph0[j]);
            float2 p1 = __half22float2(*(__half2*)&ph1[j]);
            l0 += p0.x + p0.y;
            l1 += p1.x + p1.y;
        }

        // ---- O += P @ V  (16 x 64, k = 64; P fragments straight from regs) ----
        #pragma unroll
        for (int c = 0; c < 4; c++) {
            uint32_t af[4] = { ph0[2*c], ph1[2*c], ph0[2*c + 1], ph1[2*c + 1] };
            #pragma unroll
            for (int jo = 0; jo < 8; jo++) {
                uint32_t bf[2];
                bf[0] = cV[(8*c + tig    )*72 + 8*jo + g];
                bf[1] = cV[(8*c + tig + 4)*72 + 8*jo + g];
                MMA_F16(accO[jo], af, bf);
            }
        }
    }
    #undef LOAD_KV

    // complete row sums within the quad (rows are warp-exclusive)
    l0 += __shfl_xor_sync(0xffffffffu, l0, 1);
    l0 += __shfl_xor_sync(0xffffffffu, l0, 2);
    l1 += __shfl_xor_sync(0xffffffffu, l1, 1);
    l1 += __shfl_xor_sync(0xffffffffu, l1, 2);
    float linv0 = __fdividef(1.0f, l0);
    float linv1 = __fdividef(1.0f, l1);

    // store ctx (fp16)
    __half* Cb = ctx + ((size_t)b*Tt + row0) * Dd + n*HDh;
    int m0 = wm0 + g, m1 = wm0 + g + 8;
    #pragma unroll
    for (int jo = 0; jo < 8; jo++) {
        int col = 8*jo + 2*tig;
        *(uint32_t*)(Cb + (size_t)m0 * Dd + col) =
            h2u(__floats2half2_rn(accO[jo][0] * linv0, accO[jo][1] * linv0));
        *(uint32_t*)(Cb + (size_t)m1 * Dd + col) =
            h2u(__floats2half2_rn(accO[jo][2] * linv1, accO[jo][3] * linv1));
    }
}

// -------- launch --------
extern "C" void kernel_launch(void* const* d_in, const int* in_sizes, int n_in,
                              void* d_out, int out_size)
{
    const float* inputs = (const float*)d_in[0];
    const float* ln1_g  = (const float*)d_in[1];
    const float* ln1_b  = (const float*)d_in[2];
    const float* wq     = (const float*)d_in[3];
    const float* bq     = (const float*)d_in[4];
    const float* wk     = (const float*)d_in[5];
    const float* bk     = (const float*)d_in[6];
    const float* wv     = (const float*)d_in[7];
    const float* bv     = (const float*)d_in[8];
    const float* wo     = (const float*)d_in[9];
    const float* bo     = (const float*)d_in[10];
    const float* ln2_g  = (const float*)d_in[11];
    const float* ln2_b  = (const float*)d_in[12];
    const float* w1     = (const float*)d_in[13];
    const float* b1     = (const float*)d_in[14];
    const float* w2     = (const float*)d_in[15];
    const float* b2     = (const float*)d_in[16];
    float* out = (float*)d_out;

    __half *xln, *qkv, *ctx, *yln, *h1;
    float *xres, *bqkv;
    uint32_t *vp, *wqkv_p, *wo_p, *w1_p, *w2_p;
    cudaGetSymbolAddress((void**)&xln,    g_xln);
    cudaGetSymbolAddress((void**)&qkv,    g_qkv);
    cudaGetSymbolAddress((void**)&vp,     g_vp);
    cudaGetSymbolAddress((void**)&ctx,    g_ctx);
    cudaGetSymbolAddress((void**)&xres,   g_xres);
    cudaGetSymbolAddress((void**)&yln,    g_yln);
    cudaGetSymbolAddress((void**)&h1,     g_h1);
    cudaGetSymbolAddress((void**)&wqkv_p, g_wqkv_p);
    cudaGetSymbolAddress((void**)&bqkv,   g_bqkv);
    cudaGetSymbolAddress((void**)&wo_p,   g_wo_p);
    cudaGetSymbolAddress((void**)&w1_p,   g_w1_p);
    cudaGetSymbolAddress((void**)&w2_p,   g_w2_p);

    // opt-in dynamic smem
    cudaFuncSetAttribute((const void*)gemm2<0,false,true>, cudaFuncAttributeMaxDynamicSharedMemorySize, G2_SMEM);
    cudaFuncSetAttribute((const void*)gemm2<0,true,false>, cudaFuncAttributeMaxDynamicSharedMemorySize, G2_SMEM);
    cudaFuncSetAttribute((const void*)gemm2<1,false,true>, cudaFuncAttributeMaxDynamicSharedMemorySize, G2_SMEM);
    cudaFuncSetAttribute((const void*)flash_attn, cudaFuncAttributeMaxDynamicSharedMemorySize, FA_SMEM);

    // 0) pack weights (vectorized, compile-time shifts for power-of-two N)
    pack_qkv_w_kernel<<<(Dd/2*QKVS/4 + 255)/256, 256>>>(wq, wk, wv, wqkv_p);
    pack_qkv_b_kernel<<<(QKVS + 255)/256, 256>>>(bq, bk, bv, bqkv);
    {
        int t_wo = Dd/2*Dd/4;
        pack_w4_kernel<10><<<(t_wo + 255)/256, 256>>>(wo, wo_p, t_wo);
        int t_w1 = Dd/2*FFd/4;
        pack_w4_kernel<12><<<(t_w1 + 255)/256, 256>>>(w1, w1_p, t_w1);
        int t_w2 = FFd/2*Dd/4;
        pack_w4_kernel<10><<<(t_w2 + 255)/256, 256>>>(w2, w2_p, t_w2);
    }

    // 1) LN1 (fp16 out)
    ln_kernel<<<MM, 256>>>(inputs, ln1_g, ln1_b, xln);

    // 2) fused QKV projection -> qkv [M][3072]
    dim3 gQKV(QKVS/128, MM/128);
    gemm2<0,false,true><<<gQKV, 256, G2_SMEM>>>(xln, wqkv_p, bqkv, nullptr, qkv, MM, QKVS, Dd);

    // 2b) repack V into s-pair layout
    repack_v_kernel<<<(int)((size_t)MM*Dd/2/256), 256>>>(qkv, vp);

    // 3) fused attention -> ctx
    dim3 gA(Tt/128, Bb*NHh);
    flash_attn<<<gA, 256, FA_SMEM>>>(qkv, vp, ctx);

    // 4) out-proj + residual(inputs) -> xres (fp32)
    dim3 gD(Dd/128, MM/128);
    gemm2<0,true,false><<<gD, 256, G2_SMEM>>>(ctx, wo_p, bo, inputs, xres, MM, Dd, Dd);

    // 5) LN2
    ln_kernel<<<MM, 256>>>(xres, ln2_g, ln2_b, yln);

    // 6) MLP up + exact GELU -> h1 (fp16)
    dim3 gF(FFd/128, MM/128);
    gemm2<1,false,true><<<gF, 256, G2_SMEM>>>(yln, w1_p, b1, nullptr, h1, MM, FFd, Dd);

    // 7) MLP down + bias + residual(xres) -> out (fp32)
    gemm2<0,true,false><<<gD, 256, G2_SMEM>>>(h1, w2_p, b2, xres, out, MM, Dd, FFd);
}

// round 17
// speedup vs baseline: 7.2616x; 1.0120x over previous
#include <cuda_runtime.h>
#include <cuda_fp16.h>
#include <math.h>
#include <stdint.h>

// Problem dims
#define Bb 4
#define Tt 2048
#define Dd 1024
#define NHh 16
#define HDh 64
#define FFd 4096
#define MM (Bb*Tt)          // 8192 rows
#define QKVS 3072           // fused qkv row stride

// -------- scratch (device globals; no allocs allowed) --------
__device__ __half g_xln[(size_t)MM*Dd];
__device__ __half g_qkv[(size_t)MM*QKVS];
__device__ uint2  g_vp[(size_t)MM*Dd/4];     // V paired: [b][n][chunk][16 rows][64] uint2
__device__ __half g_ctx[(size_t)MM*Dd];
__device__ float  g_xres[(size_t)MM*Dd];
__device__ __half g_yln[(size_t)MM*Dd];
__device__ __half g_h1 [(size_t)MM*FFd];
// paired fp16 weights: uint2 [K/64][16][N], row r'=ks*4+tig holds kpairs
// (32c+ks*8+tig) in .x and (+4) in .y — so one LDS.64 = full mma B fragment.
__device__ uint2 g_wqkv_p[(size_t)Dd/4*QKVS];
__device__ float g_bqkv  [QKVS];
__device__ uint2 g_wo_p[(size_t)Dd/4*Dd];
__device__ uint2 g_w1_p[(size_t)Dd/4*FFd];
__device__ uint2 g_w2_p[(size_t)FFd/4*Dd];

// -------- helpers --------
#define MMA_F16(c, a, b) \
    asm volatile("mma.sync.aligned.m16n8k16.row.col.f32.f16.f16.f32 " \
                 "{%0,%1,%2,%3},{%4,%5,%6,%7},{%8,%9},{%0,%1,%2,%3};" \
                 : "+f"((c)[0]), "+f"((c)[1]), "+f"((c)[2]), "+f"((c)[3]) \
                 : "r"((a)[0]), "r"((a)[1]), "r"((a)[2]), "r"((a)[3]), \
                   "r"((b)[0]), "r"((b)[1]))

#define LDSM4(r0, r1, r2, r3, addr) \
    asm volatile("ldmatrix.sync.aligned.m8n8.x4.shared.b16 {%0,%1,%2,%3}, [%4];" \
                 : "=r"(r0), "=r"(r1), "=r"(r2), "=r"(r3) : "r"(addr))

#define CP16(dst_u32, src_ptr) \
    asm volatile("cp.async.cg.shared.global [%0], [%1], 16;" :: "r"(dst_u32), "l"(src_ptr))
#define CP_COMMIT() asm volatile("cp.async.commit_group;")
#define CP_WAIT0()  asm volatile("cp.async.wait_group 0;")
#define CP_WAIT1()  asm volatile("cp.async.wait_group 1;")

__device__ __forceinline__ uint32_t s2u(const void* p) {
    return (uint32_t)__cvta_generic_to_shared(p);
}
__device__ __forceinline__ uint32_t h2u(__half2 h) { return *(uint32_t*)&h; }

__device__ __forceinline__ float block_reduce_sum(float v, float* sh) {
    int t = threadIdx.x;
    #pragma unroll
    for (int o = 16; o > 0; o >>= 1) v += __shfl_down_sync(0xffffffffu, v, o);
    if ((t & 31) == 0) sh[t >> 5] = v;
    __syncthreads();
    if (t < 32) {
        float w = (t < 8) ? sh[t] : 0.0f;
        #pragma unroll
        for (int o = 4; o > 0; o >>= 1) w += __shfl_down_sync(0xffffffffu, w, o);
        if (t == 0) sh[0] = w;
    }
    __syncthreads();
    float r = sh[0];
    __syncthreads();
    return r;
}

// -------- paired weight pack (N = 1<<SHIFT): fp32 [K][N] -> uint2 [K/64][16][N] --------
template<int SHIFT>
__global__ void pack_w4_kernel(const float* __restrict__ in, uint2* __restrict__ out,
                               int total4)   // total4 = (K/4*N)/4
{
    int idx = blockIdx.x * 256 + threadIdx.x;
    if (idx < total4) {
        int n  = (idx & ((1 << (SHIFT - 2)) - 1)) * 4;
        int r  = idx >> (SHIFT - 2);      // c*16 + rp
        int c  = r >> 4, rp = r & 15;
        int ks = rp >> 2, tig = rp & 3;
        int kp0 = c*32 + ks*8 + tig, kp1 = kp0 + 4;
        float4 a0 = *(const float4*)(in + (((size_t)(2*kp0))   << SHIFT) + n);
        float4 a1 = *(const float4*)(in + (((size_t)(2*kp0+1)) << SHIFT) + n);
        float4 c0 = *(const float4*)(in + (((size_t)(2*kp1))   << SHIFT) + n);
        float4 c1 = *(const float4*)(in + (((size_t)(2*kp1+1)) << SHIFT) + n);
        uint2* o = out + (((size_t)r) << SHIFT) + n;
        o[0] = make_uint2(h2u(__floats2half2_rn(a0.x, a1.x)), h2u(__floats2half2_rn(c0.x, c1.x)));
        o[1] = make_uint2(h2u(__floats2half2_rn(a0.y, a1.y)), h2u(__floats2half2_rn(c0.y, c1.y)));
        o[2] = make_uint2(h2u(__floats2half2_rn(a0.z, a1.z)), h2u(__floats2half2_rn(c0.z, c1.z)));
        o[3] = make_uint2(h2u(__floats2half2_rn(a0.w, a1.w)), h2u(__floats2half2_rn(c0.w, c1.w)));
    }
}

// -------- fused qkv paired pack (wq pre-scaled 0.125) --------
__global__ void pack_qkv_w_kernel(const float* __restrict__ wq, const float* __restrict__ wk,
                                  const float* __restrict__ wv, uint2* __restrict__ out)
{
    int idx = blockIdx.x * 256 + threadIdx.x;   // total4 = (Dd/64)*16*(QKVS/4)
    if (idx < (Dd/64)*16*(QKVS/4)) {
        int n  = (idx % (QKVS/4)) * 4;
        int r  = idx / (QKVS/4);
        int c  = r >> 4, rp = r & 15;
        int ks = rp >> 2, tig = rp & 3;
        int kp0 = c*32 + ks*8 + tig, kp1 = kp0 + 4;
        const float* src; float sc; int nn;
        if (n < Dd)        { src = wq; sc = 0.125f; nn = n; }
        else if (n < 2*Dd) { src = wk; sc = 1.0f;   nn = n - Dd; }
        else               { src = wv; sc = 1.0f;   nn = n - 2*Dd; }
        float4 a0 = *(const float4*)(src + (size_t)(2*kp0)   * Dd + nn);
        float4 a1 = *(const float4*)(src + (size_t)(2*kp0+1) * Dd + nn);
        float4 c0 = *(const float4*)(src + (size_t)(2*kp1)   * Dd + nn);
        float4 c1 = *(const float4*)(src + (size_t)(2*kp1+1) * Dd + nn);
        uint2* o = out + (size_t)r * QKVS + n;
        o[0] = make_uint2(h2u(__floats2half2_rn(a0.x*sc, a1.x*sc)), h2u(__floats2half2_rn(c0.x*sc, c1.x*sc)));
        o[1] = make_uint2(h2u(__floats2half2_rn(a0.y*sc, a1.y*sc)), h2u(__floats2half2_rn(c0.y*sc, c1.y*sc)));
        o[2] = make_uint2(h2u(__floats2half2_rn(a0.z*sc, a1.z*sc)), h2u(__floats2half2_rn(c0.z*sc, c1.z*sc)));
        o[3] = make_uint2(h2u(__floats2half2_rn(a0.w*sc, a1.w*sc)), h2u(__floats2half2_rn(c0.w*sc, c1.w*sc)));
    }
}

__global__ void pack_qkv_b_kernel(const float* __restrict__ bq, const float* __restrict__ bk,
                                  const float* __restrict__ bv, float* __restrict__ out)
{
    int n = blockIdx.x * 256 + threadIdx.x;
    if (n < QKVS) {
        if (n < Dd)        out[n] = bq[n] * 0.125f;
        else if (n < 2*Dd) out[n] = bk[n - Dd];
        else               out[n] = bv[n - 2*Dd];
    }
}

// -------- V repack: qkv V-part -> uint2 [b][n][chunk][16 rows: c*4+tig][64] --------
// uint2 = ( half2(V[2sp0],V[2sp0+1]), half2(V[2sp1],V[2sp1+1]) ), sp1 = sp0+4
__global__ void repack_v_kernel(const __half* __restrict__ qkv, uint2* __restrict__ vp)
{
    size_t idx = (size_t)blockIdx.x * 256 + threadIdx.x;   // MM*Dd/4 total
    int h = idx & 63;
    size_t r1 = idx >> 6;
    int rp = (int)(r1 & 15);
    size_t r2 = r1 >> 4;
    int c64 = (int)(r2 & 31);          // Tt/64 = 32 chunks
    size_t r3 = r2 >> 5;
    int n = (int)(r3 & (NHh - 1));
    int b = (int)(r3 >> 4);
    int ci = rp >> 2, tig = rp & 3;
    int sp0 = c64*32 + ci*8 + tig, sp1 = sp0 + 4;
    const __half* base = qkv + (size_t)b*Tt*QKVS + 2*Dd + n*HDh + h;
    uint2 o;
    o.x = h2u(__halves2half2(base[(size_t)(2*sp0)*QKVS], base[(size_t)(2*sp0+1)*QKVS]));
    o.y = h2u(__halves2half2(base[(size_t)(2*sp1)*QKVS], base[(size_t)(2*sp1+1)*QKVS]));
    vp[idx] = o;
}

// -------- LayerNorm: one block (256 thr) per row of 1024; fp16 out --------
__global__ void ln_kernel(const float* __restrict__ x, const float* __restrict__ gamma,
                          const float* __restrict__ beta, __half* __restrict__ out)
{
    __shared__ float sh[32];
    size_t row = blockIdx.x;
    const float4* xr = (const float4*)(x + row * Dd);
    int t = threadIdx.x;
    float4 xv = xr[t];
    float s  = xv.x + xv.y + xv.z + xv.w;
    float s2 = xv.x*xv.x + xv.y*xv.y + xv.z*xv.z + xv.w*xv.w;
    float S  = block_reduce_sum(s,  sh);
    float S2 = block_reduce_sum(s2, sh);
    float mean = S * (1.0f / Dd);
    float var  = S2 * (1.0f / Dd) - mean * mean;
    float rs   = rsqrtf(var + 1e-6f);
    float4 gv = ((const float4*)gamma)[t];
    float4 bv = ((const float4*)beta)[t];
    __half2 h0 = __floats2half2_rn((xv.x - mean) * rs * gv.x + bv.x,
                                   (xv.y - mean) * rs * gv.y + bv.y);
    __half2 h1 = __floats2half2_rn((xv.z - mean) * rs * gv.z + bv.z,
                                   (xv.w - mean) * rs * gv.w + bv.w);
    uint2 pkd; pkd.x = h2u(h0); pkd.y = h2u(h1);
    *(uint2*)(out + row * Dd + t*4) = pkd;
}

// ============================================================================
// cp.async 3-stage pipelined FP16 GEMM: C = act(A@B + bias) (+res)
// A [M,K] fp16 row-major; B paired uint2 [K/64][16][N]. BM=128 BN=128 BK=64.
// 256 thr; warps 2m x 4n; mma m16n8k16; ldmatrix.x4 A; one LDS.64 = B fragment.
// smem: sA u32 [3][128][36], sB u32 [3][16 rows][264] (128 uint2 + 4 pad / row).
// Stride 264 == 8 mod 32 -> LDS.64 banks 8*tig+2g, conflict-free.
// ============================================================================
#define G2_SMEM (3*(128*36 + 16*264)*4)
template<int ACT, bool HAS_RES, bool OUT_HALF>
__global__ __launch_bounds__(256, 2) void gemm2(
    const __half* __restrict__ A, const uint2* __restrict__ Bm,
    const float* __restrict__ bias, const float* __restrict__ res,
    void* __restrict__ Cv, int M, int N, int K)
{
    extern __shared__ uint32_t smem_[];
    uint32_t* sA = smem_;               // [3][128*36]
    uint32_t* sB = smem_ + 3*128*36;    // [3][16*264]
    int tid = threadIdx.x;
    int lane = tid & 31, wid = tid >> 5;
    int g = lane >> 2, tig = lane & 3;
    int wm0 = (wid >> 2) * 64;
    int wn0 = (wid & 3) * 32;
    int row0 = blockIdx.y * 128;
    int col0 = blockIdx.x * 128;
    const __half* Ab = A + (size_t)row0 * K;
    const uint2* Bp = Bm + col0;

    int lr = lane & 7, sel = lane >> 3;
    int a_row_off = ((sel & 1) << 3) + lr;
    int a_col_off = (sel >> 1) << 2;

    float acc[4][4][4] = {};

    int nk = K >> 6;
    #define COPY_STAGE(buf, k0) do { \
        uint32_t* dA = sA + (buf)*128*36; \
        uint32_t* dB = sB + (buf)*16*264; \
        _Pragma("unroll") \
        for (int i_ = 0; i_ < 4; i_++) { \
            int f = tid + i_*256; \
            int rr = f >> 3, cq = f & 7; \
            CP16(s2u(dA + rr*36 + cq*4), Ab + (size_t)rr * K + (k0) + cq*8); \
        } \
        _Pragma("unroll") \
        for (int i_ = 0; i_ < 4; i_++) { \
            int f = tid + i_*256; \
            int rr = f >> 6, cq = f & 63; \
            CP16(s2u(dB + rr*264 + cq*4), \
                 Bp + ((size_t)(((k0) >> 6)*16 + rr)) * N + cq*2); \
        } \
    } while (0)

    COPY_STAGE(0, 0);
    CP_COMMIT();
    if (nk > 1) { COPY_STAGE(1, 64); CP_COMMIT(); }

    for (int it = 0; it < nk; it++) {
        if (it + 1 < nk) { CP_WAIT1(); } else { CP_WAIT0(); }
        __syncthreads();
        if (it + 2 < nk) {
            COPY_STAGE((it + 2) % 3, (it + 2) << 6);
            CP_COMMIT();
        }
        uint32_t* cA = sA + (it % 3)*128*36;
        uint32_t* cB = sB + (it % 3)*16*264;
        #pragma unroll
        for (int ks = 0; ks < 4; ks++) {
            int kc = ks * 8;
            uint32_t af[4][4], bf[4][2];
            #pragma unroll
            for (int i = 0; i < 4; i++) {
                uint32_t addr = s2u(cA + (wm0 + i*16 + a_row_off)*36 + kc + a_col_off);
                LDSM4(af[i][0], af[i][1], af[i][2], af[i][3], addr);
            }
            #pragma unroll
            for (int j = 0; j < 4; j++) {
                uint2 bv = *(const uint2*)(cB + (ks*4 + tig)*264 + (wn0 + j*8 + g)*2);
                bf[j][0] = bv.x;
                bf[j][1] = bv.y;
            }
            #pragma unroll
            for (int i = 0; i < 4; i++)
                #pragma unroll
                for (int j = 0; j < 4; j++)
                    MMA_F16(acc[i][j], af[i], bf[j]);
        }
    }
    #undef COPY_STAGE

    // epilogue
    #pragma unroll
    for (int i = 0; i < 4; i++) {
        #pragma unroll
        for (int j = 0; j < 4; j++) {
            int col = col0 + wn0 + j*8 + tig*2;
            #pragma unroll
            for (int h = 0; h < 2; h++) {
                int row = row0 + wm0 + i*16 + g + h*8;
                float v0 = acc[i][j][h*2 + 0] + bias[col];
                float v1 = acc[i][j][h*2 + 1] + bias[col + 1];
                if (ACT == 1) {
                    v0 = 0.5f * v0 * (1.0f + erff(v0 * 0.70710678118654752f));
                    v1 = 0.5f * v1 * (1.0f + erff(v1 * 0.70710678118654752f));
                }
                if (HAS_RES) {
                    float2 rr = *(const float2*)(res + (size_t)row * N + col);
                    v0 += rr.x; v1 += rr.y;
                }
                if (OUT_HALF) {
                    *(uint32_t*)((__half*)Cv + (size_t)row * N + col) =
                        h2u(__floats2half2_rn(v0, v1));
                } else {
                    *(float2*)((float*)Cv + (size_t)row * N + col) = make_float2(v0, v1);
                }
            }
        }
    }
}

// ============================================================================
// Fused flash attention, fp16, soft-cap fixed reference 2.
// Warps 8m x 1n; S accumulator -> P A-fragment in registers (no sP smem).
// Q fragments hoisted out of the tile loop. V paired (one LDS.64 = fragment).
// smem u32: sQ [128][36], sK [2][64][36], sV [2][16 rows][136] (64 uint2 + pad).
// ============================================================================
#define FA_SMEM ((128*36 + 2*64*36 + 2*16*136)*4)
__global__ __launch_bounds__(256, 2) void flash_attn(
    const __half* __restrict__ qkv, const uint2* __restrict__ vp,
    __half* __restrict__ ctx)
{
    extern __shared__ uint32_t smem_[];
    uint32_t* sQ = smem_;                  // [128][36]
    uint32_t* sK = smem_ + 128*36;         // [2][64][36]
    uint32_t* sV = sK + 2*64*36;           // [2][16*136]
    int tid = threadIdx.x;
    int lane = tid & 31, wid = tid >> 5;
    int g = lane >> 2, tig = lane & 3;
    int wm0 = wid * 16;                    // 8 warps on m, 16 rows each
    int row0 = blockIdx.x * 128;
    int z = blockIdx.y;
    int b = z >> 4, n = z & 15;
    const __half* Qb = qkv + ((size_t)b*Tt + row0) * QKVS + n*HDh;
    const __half* Kb = qkv + (size_t)b*Tt*QKVS + Dd + n*HDh;
    const uint2* Vp = vp + (size_t)(b*NHh + n) * 32768;   // 32 chunks * 16 * 64

    int lr = lane & 7, sel = lane >> 3;
    int a_row_off = ((sel & 1) << 3) + lr;
    int a_col_off = (sel >> 1) << 2;

    #define LOAD_KV(buf, s0) do { \
        uint32_t* dK = sK + (buf)*64*36; \
        uint32_t* dV = sV + (buf)*16*136; \
        _Pragma("unroll") \
        for (int i_ = 0; i_ < 2; i_++) { \
            int f = tid + i_*256; \
            int rr = f >> 3, cq = f & 7; \
            CP16(s2u(dK + rr*36 + cq*4), Kb + (size_t)((s0) + rr) * QKVS + cq*8); \
        } \
        _Pragma("unroll") \
        for (int i_ = 0; i_ < 2; i_++) { \
            int f = tid + i_*256; \
            int rr = f >> 5, cq = f & 31; \
            CP16(s2u(dV + rr*136 + cq*4), \
                 Vp + ((size_t)(((s0) >> 6)*16 + rr))*64 + cq*2); \
        } \
    } while (0)

    #pragma unroll
    for (int i = 0; i < 4; i++) {
        int f = tid + i*256;
        int rr = f >> 3, cq = f & 7;
        CP16(s2u(sQ + rr*36 + cq*4), Qb + (size_t)rr * QKVS + cq*8);
    }
    CP_COMMIT();
    LOAD_KV(0, 0);
    CP_COMMIT();
    CP_WAIT0();
    __syncthreads();

    // Q fragments are loop-invariant: load once
    uint32_t aq[4][4];
    #pragma unroll
    for (int c = 0; c < 4; c++) {
        uint32_t addr = s2u(sQ + (wm0 + a_row_off)*36 + 8*c + a_col_off);
        LDSM4(aq[c][0], aq[c][1], aq[c][2], aq[c][3], addr);
    }

    const __half2 c_scale = __floats2half2_rn(72.134752f, 72.134752f);
    const __half2 c_off   = __floats2half2_rn(-2.8853901f, -2.8853901f);
    const __half2 c_clamp = __floats2half2_rn(11.5f, 11.5f);

    float l0 = 0.0f, l1 = 0.0f;
    float accO[8][4] = {};

    const int NT = Tt / 64;
    for (int t = 0; t < NT; t++) {
        if (t > 0) {
            CP_WAIT0();
            __syncthreads();
        }
        if (t + 1 < NT) {
            LOAD_KV((t+1)&1, (t+1)*64);
            CP_COMMIT();
        }
        uint32_t* cK = sK + (t&1)*64*36;
        uint32_t* cV = sV + (t&1)*16*136;

        // ---- S = Q @ K^T  (16 x 64 per warp) ----
        float accS[8][4] = {};
        #pragma unroll
        for (int c = 0; c < 4; c++) {
            #pragma unroll
            for (int jq = 0; jq < 4; jq++) {
                uint32_t t0, t1, t2, t3;
                uint32_t addr = s2u(cK + (16*jq + a_row_off)*36 + 8*c + a_col_off);
                LDSM4(t0, t1, t2, t3, addr);
                uint32_t b0[2] = {t0, t2};
                uint32_t b1[2] = {t1, t3};
                MMA_F16(accS[2*jq],     aq[c], b0);
                MMA_F16(accS[2*jq + 1], aq[c], b1);
            }
        }

        // ---- softcap + exp2 (fixed ref 2), pack P fragments in registers ----
        uint32_t ph0[8], ph1[8];
        #pragma unroll
        for (int j = 0; j < 8; j++) {
            __half2 x01 = __floats2half2_rn(accS[j][0] * 0.02f, accS[j][1] * 0.02f);
            __half2 x23 = __floats2half2_rn(accS[j][2] * 0.02f, accS[j][3] * 0.02f);
            uint32_t tu0, tu1;
            asm("tanh.approx.f16x2 %0, %1;" : "=r"(tu0) : "r"(h2u(x01)));
            asm("tanh.approx.f16x2 %0, %1;" : "=r"(tu1) : "r"(h2u(x23)));
            __half2 w0 = __hmin2(__hfma2(*(__half2*)&tu0, c_scale, c_off), c_clamp);
            __half2 w1 = __hmin2(__hfma2(*(__half2*)&tu1, c_scale, c_off), c_clamp);
            asm("ex2.approx.f16x2 %0, %1;" : "=r"(ph0[j]) : "r"(h2u(w0)));
            asm("ex2.approx.f16x2 %0, %1;" : "=r"(ph1[j]) : "r"(h2u(w1)));
            float2 p0 = __half22float2(*(__half2*)&ph0[j]);
            float2 p1 = __half22float2(*(__half2*)&ph1[j]);
            l0 += p0.x + p0.y;
            l1 += p1.x + p1.y;
        }

        // ---- O += P @ V  (16 x 64, k = 64; one LDS.64 per V fragment) ----
        #pragma unroll
        for (int c = 0; c < 4; c++) {
            uint32_t af[4] = { ph0[2*c], ph1[2*c], ph0[2*c + 1], ph1[2*c + 1] };
            #pragma unroll
            for (int jo = 0; jo < 8; jo++) {
                uint2 bv = *(const uint2*)(cV + (c*4 + tig)*136 + (8*jo + g)*2);
                uint32_t bf[2] = { bv.x, bv.y };
                MMA_F16(accO[jo], af, bf);
            }
        }
    }
    #undef LOAD_KV

    // complete row sums within the quad (rows are warp-exclusive)
    l0 += __shfl_xor_sync(0xffffffffu, l0, 1);
    l0 += __shfl_xor_sync(0xffffffffu, l0, 2);
    l1 += __shfl_xor_sync(0xffffffffu, l1, 1);
    l1 += __shfl_xor_sync(0xffffffffu, l1, 2);
    float linv0 = __fdividef(1.0f, l0);
    float linv1 = __fdividef(1.0f, l1);

    // store ctx (fp16)
    __half* Cb = ctx + ((size_t)b*Tt + row0) * Dd + n*HDh;
    int m0 = wm0 + g, m1 = wm0 + g + 8;
    #pragma unroll
    for (int jo = 0; jo < 8; jo++) {
        int col = 8*jo + 2*tig;
        *(uint32_t*)(Cb + (size_t)m0 * Dd + col) =
            h2u(__floats2half2_rn(accO[jo][0] * linv0, accO[jo][1] * linv0));
        *(uint32_t*)(Cb + (size_t)m1 * Dd + col) =
            h2u(__floats2half2_rn(accO[jo][2] * linv1, accO[jo][3] * linv1));
    }
}

// -------- launch --------
extern "C" void kernel_launch(void* const* d_in, const int* in_sizes, int n_in,
                              void* d_out, int out_size)
{
    const float* inputs = (const float*)d_in[0];
    const float* ln1_g  = (const float*)d_in[1];
    const float* ln1_b  = (const float*)d_in[2];
    const float* wq     = (const float*)d_in[3];
    const float* bq     = (const float*)d_in[4];
    const float* wk     = (const float*)d_in[5];
    const float* bk     = (const float*)d_in[6];
    const float* wv     = (const float*)d_in[7];
    const float* bv     = (const float*)d_in[8];
    const float* wo     = (const float*)d_in[9];
    const float* bo     = (const float*)d_in[10];
    const float* ln2_g  = (const float*)d_in[11];
    const float* ln2_b  = (const float*)d_in[12];
    const float* w1     = (const float*)d_in[13];
    const float* b1     = (const float*)d_in[14];
    const float* w2     = (const float*)d_in[15];
    const float* b2     = (const float*)d_in[16];
    float* out = (float*)d_out;

    __half *xln, *qkv, *ctx, *yln, *h1;
    float *xres, *bqkv;
    uint2 *vp, *wqkv_p, *wo_p, *w1_p, *w2_p;
    cudaGetSymbolAddress((void**)&xln,    g_xln);
    cudaGetSymbolAddress((void**)&qkv,    g_qkv);
    cudaGetSymbolAddress((void**)&vp,     g_vp);
    cudaGetSymbolAddress((void**)&ctx,    g_ctx);
    cudaGetSymbolAddress((void**)&xres,   g_xres);
    cudaGetSymbolAddress((void**)&yln,    g_yln);
    cudaGetSymbolAddress((void**)&h1,     g_h1);
    cudaGetSymbolAddress((void**)&wqkv_p, g_wqkv_p);
    cudaGetSymbolAddress((void**)&bqkv,   g_bqkv);
    cudaGetSymbolAddress((void**)&wo_p,   g_wo_p);
    cudaGetSymbolAddress((void**)&w1_p,   g_w1_p);
    cudaGetSymbolAddress((void**)&w2_p,   g_w2_p);

    // opt-in dynamic smem
    cudaFuncSetAttribute((const void*)gemm2<0,false,true>, cudaFuncAttributeMaxDynamicSharedMemorySize, G2_SMEM);
    cudaFuncSetAttribute((const void*)gemm2<0,true,false>, cudaFuncAttributeMaxDynamicSharedMemorySize, G2_SMEM);
    cudaFuncSetAttribute((const void*)gemm2<1,false,true>, cudaFuncAttributeMaxDynamicSharedMemorySize, G2_SMEM);
    cudaFuncSetAttribute((const void*)flash_attn, cudaFuncAttributeMaxDynamicSharedMemorySize, FA_SMEM);

    // 0) pack weights (paired layout)
    pack_qkv_w_kernel<<<((Dd/64)*16*(QKVS/4) + 255)/256, 256>>>(wq, wk, wv, wqkv_p);
    pack_qkv_b_kernel<<<(QKVS + 255)/256, 256>>>(bq, bk, bv, bqkv);
    {
        int t_wo = Dd/4*Dd/4;
        pack_w4_kernel<10><<<(t_wo + 255)/256, 256>>>(wo, wo_p, t_wo);
        int t_w1 = Dd/4*FFd/4;
        pack_w4_kernel<12><<<(t_w1 + 255)/256, 256>>>(w1, w1_p, t_w1);
        int t_w2 = FFd/4*Dd/4;
        pack_w4_kernel<10><<<(t_w2 + 255)/256, 256>>>(w2, w2_p, t_w2);
    }

    // 1) LN1 (fp16 out)
    ln_kernel<<<MM, 256>>>(inputs, ln1_g, ln1_b, xln);

    // 2) fused QKV projection -> qkv [M][3072]
    dim3 gQKV(QKVS/128, MM/128);
    gemm2<0,false,true><<<gQKV, 256, G2_SMEM>>>(xln, wqkv_p, bqkv, nullptr, qkv, MM, QKVS, Dd);

    // 2b) repack V into paired layout
    repack_v_kernel<<<(int)((size_t)MM*Dd/4/256), 256>>>(qkv, vp);

    // 3) fused attention -> ctx
    dim3 gA(Tt/128, Bb*NHh);
    flash_attn<<<gA, 256, FA_SMEM>>>(qkv, vp, ctx);

    // 4) out-proj + residual(inputs) -> xres (fp32)
    dim3 gD(Dd/128, MM/128);
    gemm2<0,true,false><<<gD, 256, G2_SMEM>>>(ctx, wo_p, bo, inputs, xres, MM, Dd, Dd);

    // 5) LN2
    ln_kernel<<<MM, 256>>>(xres, ln2_g, ln2_b, yln);

    // 6) MLP up + exact GELU -> h1 (fp16)
    dim3 gF(FFd/128, MM/128);
    gemm2<1,false,true><<<gF, 256, G2_SMEM>>>(yln, w1_p, b1, nullptr, h1, MM, FFd, Dd);

    // 7) MLP down + bias + residual(xres) -> out (fp32)
    gemm2<0,true,false><<<gD, 256, G2_SMEM>>>(h1, w2_p, b2, xres, out, MM, Dd, FFd);
}